// round 4
// baseline (speedup 1.0000x reference)
#include <cuda_runtime.h>
#include <cuda_bf16.h>
#include <math.h>

#define N_NODES 20000
#define N_EDGES 320000
#define N_GRAPHS 200
#define TOWERS 5
#define F 75
#define TF 375
#define EDGE_DIM 50
#define N_ATTR 100
#define FOUT 15
#define ROW 384

// ---------------- static scratch (zero-initialized; pads never written) ----
__device__ float g_x[N_NODES * F];
__device__ float g_y[N_NODES * F];
__device__ float g_xd[(size_t)N_NODES * ROW];
__device__ float g_xs[(size_t)N_NODES * ROW];
__device__ float g_aggr[(size_t)N_NODES * 1500];
__device__ float g_S[N_NODES * F];
__device__ float g_et[N_ATTR * ROW];
__device__ float g_Mfold[F * F];
__device__ float g_bfold[F];
__device__ int   g_deg[N_NODES];
__device__ int   g_rowptr[N_NODES + 1];
__device__ int   g_cursor[N_NODES];
__device__ int2  g_col[N_EDGES];           // (src, attr)
__device__ float g_amp[N_NODES], g_att[N_NODES], g_invdeg[N_NODES];
__device__ float g_logsum;
__device__ int   g_part[128];
__device__ int   g_partscan[128];
__device__ float g_bnsum[F], g_bnsq[F];
__device__ float g_pooled[N_GRAPHS * F];

// ---------------- f32x2 helpers ----------------
typedef unsigned long long u64;
__device__ __forceinline__ u64 f2bcast(float a) {
    u64 r;
    asm("mov.b64 %0, {%1, %1};" : "=l"(r) : "f"(a));
    return r;
}
__device__ __forceinline__ u64 f2pk(float lo, float hi) {
    u64 r;
    asm("mov.b64 %0, {%1, %2};" : "=l"(r) : "f"(lo), "f"(hi));
    return r;
}
__device__ __forceinline__ void f2up(u64 v, float& lo, float& hi) {
    asm("mov.b64 {%0, %1}, %2;" : "=f"(lo), "=f"(hi) : "l"(v));
}
__device__ __forceinline__ u64 ffma2(u64 a, u64 b, u64 c) {
    u64 d;
    asm("fma.rn.f32x2 %0, %1, %2, %3;" : "=l"(d) : "l"(a), "l"(b), "l"(c));
    return d;
}
__device__ __forceinline__ u64 fadd2(u64 a, u64 b) {
    u64 d;
    asm("add.rn.f32x2 %0, %1, %2;" : "=l"(d) : "l"(a), "l"(b));
    return d;
}

// ---------------- preprocessing ----------------
#define GATHER_BLKS ((N_NODES * F + 255) / 256)
#define COUNT_BLKS ((N_EDGES + 255) / 256)
#define SCAN_BLKS ((N_NODES + 255) / 256)

__global__ void k_gather_count(const int* __restrict__ x_idx, const float* __restrict__ emb,
                               const int* __restrict__ ei) {
    int b = blockIdx.x;
    if (b < GATHER_BLKS) {
        int i = b * 256 + threadIdx.x;
        if (i < N_NODES * F) {
            int n = i / F, f = i - n * F;
            g_x[i] = emb[x_idx[n] * F + f];
        }
    } else {
        int i = (b - GATHER_BLKS) * 256 + threadIdx.x;
        if (i < N_EDGES) atomicAdd(&g_deg[ei[N_EDGES + i]], 1);
    }
}

__global__ void k_scanA() {
    __shared__ int ss[256];
    __shared__ float ls[256];
    int b = blockIdx.x, tid = threadIdx.x;
    int n = b * 256 + tid;
    int d = (n < N_NODES) ? g_deg[n] : 0;
    ss[tid] = d;
    ls[tid] = (n < N_NODES) ? logf((float)d + 1.f) : 0.f;
    __syncthreads();
    for (int o = 128; o; o >>= 1) {
        if (tid < o) { ss[tid] += ss[tid + o]; ls[tid] += ls[tid + o]; }
        __syncthreads();
    }
    if (tid == 0) { g_part[b] = ss[0]; atomicAdd(&g_logsum, ls[0]); }
}

__global__ void k_scanB() {
    __shared__ int s[128];
    int t = threadIdx.x;
    int own = (t < SCAN_BLKS) ? g_part[t] : 0;
    s[t] = own;
    __syncthreads();
    for (int o = 1; o < 128; o <<= 1) {
        int v = (t >= o) ? s[t - o] : 0;
        __syncthreads();
        s[t] += v;
        __syncthreads();
    }
    if (t < SCAN_BLKS) g_partscan[t] = s[t] - own;
}

__global__ void k_scanC() {
    __shared__ int s[256];
    int b = blockIdx.x, tid = threadIdx.x;
    int n = b * 256 + tid;
    int d = (n < N_NODES) ? g_deg[n] : 0;
    int own = d;
    s[tid] = d;
    __syncthreads();
    for (int o = 1; o < 256; o <<= 1) {
        int v = (tid >= o) ? s[tid - o] : 0;
        __syncthreads();
        s[tid] += v;
        __syncthreads();
    }
    int excl = s[tid] - own + g_partscan[b];
    if (n < N_NODES) {
        g_rowptr[n] = excl;
        g_cursor[n] = excl;
        float avg = g_logsum * (1.f / (float)N_NODES);
        float dc = fmaxf((float)d, 1.f);
        float L = logf(dc + 1.f);
        g_amp[n] = L / avg;
        g_att[n] = avg / L;
        g_invdeg[n] = 1.f / dc;
        if (n == N_NODES - 1) g_rowptr[N_NODES] = excl + d;
    }
    if (n < N_GRAPHS * F) g_pooled[n] = 0.f;
}

__global__ void k_scatter(const int* __restrict__ ei, const int* __restrict__ ea) {
    int i = blockIdx.x * 256 + threadIdx.x;
    if (i < N_EDGES) {
        int dst = ei[N_EDGES + i];
        int pos = atomicAdd(&g_cursor[dst], 1);
        g_col[pos] = make_int2(ei[i], ea[i]);
    }
    if (i < N_NODES) g_deg[i] = 0;     // reset for next invocation
    if (i == 0) g_logsum = 0.f;
}

// ---------------- per-layer: et table + Mfold + bn zero ----------------
__global__ void k_et_fold(const float* __restrict__ edge_emb, const float* __restrict__ W_edge,
                          const float* __restrict__ b_edge, const float* __restrict__ W_pre,
                          const float* __restrict__ b_pre, const float* __restrict__ W_post,
                          const float* __restrict__ b_post, const float* __restrict__ W_lin,
                          const float* __restrict__ b_lin, int l) {
    int a = blockIdx.x, t = threadIdx.x;
    if (a < N_ATTR) {
        __shared__ float e75[F];
        if (t < F) {
            float acc = b_edge[l * F + t];
            for (int d = 0; d < EDGE_DIM; d++)
                acc += edge_emb[a * EDGE_DIM + d] * W_edge[(l * EDGE_DIM + d) * F + t];
            e75[t] = acc;
        }
        __syncthreads();
        if (t < TF) {
            int tw = t / F, f = t - tw * F;
            float acc = b_pre[(l * TOWERS + tw) * F + f];
            const float* Wp = W_pre + ((size_t)((l * TOWERS + tw) * 225 + 150)) * F + f;
            for (int c = 0; c < F; c++) acc += e75[c] * Wp[c * F];
            g_et[a * ROW + t] = acc;
        }
    } else {
        for (int i = t; i < F * F; i += 384) {
            int c = i / F, o = i - c * F;
            float acc = 0.f;
            for (int tf = 0; tf < F; tf++) {
                int tw = tf / FOUT, f = tf - tw * FOUT;
                acc += W_post[((size_t)((l * TOWERS + tw) * 975 + c)) * FOUT + f] *
                       W_lin[(l * F + tf) * F + o];
            }
            g_Mfold[i] = acc;
        }
        if (t < F) {
            float bf = b_lin[l * F + t];
            for (int tf = 0; tf < F; tf++) {
                int tw = tf / FOUT, f = tf - tw * FOUT;
                bf += b_post[(l * TOWERS + tw) * FOUT + f] * W_lin[(l * F + tf) * F + t];
            }
            g_bfold[t] = bf;
            g_bnsum[t] = 0.f;
            g_bnsq[t] = 0.f;
        }
    }
}

// ---------------- xd|xs GEMM: per (part,tower): [N,75]@[75,75] ----------------
// block: 256 nodes x 80 cols. 256 thr: ty=tid>>3 (32), tx=tid&7.
// thread tile: 8 nodes x 5 col-pairs.
__global__ __launch_bounds__(256) void k_xds(const float* __restrict__ W_pre, int l) {
    __shared__ __align__(16) float As[256][25];
    __shared__ __align__(16) float Bs[25][80];
    int c = blockIdx.x;
    int n0 = blockIdx.y * 256;
    int part = c / 5, tw = c - part * 5;
    int tid = threadIdx.x;
    int ty = tid >> 3, tx = tid & 7;
    u64 acc[8][5];
#pragma unroll
    for (int i = 0; i < 8; i++)
#pragma unroll
        for (int j = 0; j < 5; j++) acc[i][j] = 0ULL;
    const float* Wbase = W_pre + (size_t)((l * TOWERS + tw) * 225 + part * F) * F;
    for (int kc = 0; kc < F; kc += 25) {
#pragma unroll
        for (int idx = tid; idx < 256 * 25; idx += 256) {
            int r = idx / 25, kk = idx - r * 25;
            int n = n0 + r;
            As[r][kk] = (n < N_NODES) ? g_x[n * F + kc + kk] : 0.f;
        }
        for (int idx = tid; idx < 25 * 80; idx += 256) {
            int kk = idx / 80, j = idx - kk * 80;
            Bs[kk][j] = (j < F) ? Wbase[(kc + kk) * F + j] : 0.f;
        }
        __syncthreads();
#pragma unroll 5
        for (int kk = 0; kk < 25; kk++) {
            u64 b2[5];
#pragma unroll
            for (int j = 0; j < 5; j++)
                b2[j] = *(const u64*)&Bs[kk][2 * (tx * 5 + j)];
#pragma unroll
            for (int i = 0; i < 8; i++) {
                u64 a2 = f2bcast(As[ty + 32 * i][kk]);
#pragma unroll
                for (int j = 0; j < 5; j++) acc[i][j] = ffma2(a2, b2[j], acc[i][j]);
            }
        }
        __syncthreads();
    }
    float* dst = part ? g_xs : g_xd;
#pragma unroll
    for (int i = 0; i < 8; i++) {
        int n = n0 + ty + 32 * i;
        if (n >= N_NODES) continue;
        float* row = dst + (size_t)n * ROW + tw * F;
#pragma unroll
        for (int j = 0; j < 5; j++) {
            int jc = 2 * (tx * 5 + j);
            float lo, hi;
            f2up(acc[i][j], lo, hi);
            if (jc < F) row[jc] = lo;
            if (jc + 1 < F) row[jc + 1] = hi;
        }
    }
}

// ---------------- aggregation: one warp per dst node ----------------
// m = xd + w, w = xs[src]+et[attr]; mean/min/max/std shift-equivariant in xd,
// so accumulate over w only, add xd in the epilogue.
__global__ void k_aggr() {
    int warp = (blockIdx.x * blockDim.x + threadIdx.x) >> 5;
    int lane = threadIdx.x & 31;
    if (warp >= N_NODES) return;
    int n = warp;
    u64 sum2[6], sq2[6];
    float mn[12], mx[12];
#pragma unroll
    for (int q = 0; q < 6; q++) { sum2[q] = 0ULL; sq2[q] = 0ULL; }
#pragma unroll
    for (int j = 0; j < 12; j++) { mn[j] = INFINITY; mx[j] = -INFINITY; }
    int e0 = g_rowptr[n], e1 = g_rowptr[n + 1];
#pragma unroll 2
    for (int e = e0; e < e1; e++) {
        int2 sa = g_col[e];
        const float4* xs4 = (const float4*)(g_xs + (size_t)sa.x * ROW);
        const float4* et4 = (const float4*)(g_et + sa.y * ROW);
#pragma unroll
        for (int q = 0; q < 3; q++) {
            float4 xv = xs4[lane * 3 + q];
            float4 ev = et4[lane * 3 + q];
            u64 v0 = fadd2(f2pk(xv.x, xv.y), f2pk(ev.x, ev.y));
            u64 v1 = fadd2(f2pk(xv.z, xv.w), f2pk(ev.z, ev.w));
            sum2[2 * q] = fadd2(sum2[2 * q], v0);
            sum2[2 * q + 1] = fadd2(sum2[2 * q + 1], v1);
            sq2[2 * q] = ffma2(v0, v0, sq2[2 * q]);
            sq2[2 * q + 1] = ffma2(v1, v1, sq2[2 * q + 1]);
            float a0, a1, a2, a3;
            f2up(v0, a0, a1);
            f2up(v1, a2, a3);
            int j = q * 4;
            mn[j] = fminf(mn[j], a0); mx[j] = fmaxf(mx[j], a0);
            mn[j + 1] = fminf(mn[j + 1], a1); mx[j + 1] = fmaxf(mx[j + 1], a1);
            mn[j + 2] = fminf(mn[j + 2], a2); mx[j + 2] = fmaxf(mx[j + 2], a2);
            mn[j + 3] = fminf(mn[j + 3], a3); mx[j + 3] = fmaxf(mx[j + 3], a3);
        }
    }
    float inv = g_invdeg[n];
    bool has = e1 > e0;
    const float4* xdrow = (const float4*)(g_xd + (size_t)n * ROW);
#pragma unroll
    for (int q = 0; q < 3; q++) {
        float4 xv = xdrow[lane * 3 + q];
        float xd4[4] = {xv.x, xv.y, xv.z, xv.w};
#pragma unroll
        for (int h4 = 0; h4 < 4; h4++) {
            int j = q * 4 + h4;                      // 0..11
            int f = lane * 12 + j;
            if (f >= TF) continue;
            float sm, sqv;
            {
                float lo, hi;
                f2up(sum2[j >> 1], lo, hi);
                sm = (j & 1) ? hi : lo;
                f2up(sq2[j >> 1], lo, hi);
                sqv = (j & 1) ? hi : lo;
            }
            float xd = xd4[h4];
            float meanw = sm * inv;
            float var = sqv * inv - meanw * meanw;
            float sd = sqrtf(fmaxf(var, 0.f) + 1e-5f);
            float mean = has ? (meanw + xd) : 0.f;
            float mnv = has ? (mn[j] + xd) : 0.f;
            float mxv = has ? (mx[j] + xd) : 0.f;
            int tw = f / F, jj = f - tw * F;
            float* outp = g_aggr + (size_t)n * 1500 + tw * 300 + jj;
            outp[0] = mean;
            outp[75] = mnv;
            outp[150] = mxv;
            outp[225] = sd;
        }
    }
}

// ---------------- S GEMM + scaler combine ----------------
__global__ __launch_bounds__(256) void k_gemmS(const float* __restrict__ W_post, int l) {
    __shared__ __align__(16) float As[256][25];
    __shared__ __align__(16) float Bs[25][48];
    int t = blockIdx.y;
    int n0 = blockIdx.x * 256;
    int tid = threadIdx.x;
    int ty = tid >> 3, tx = tid & 7;
    u64 acc[8][3];
#pragma unroll
    for (int i = 0; i < 8; i++)
#pragma unroll
        for (int g = 0; g < 3; g++) acc[i][g] = 0ULL;
    for (int kc = 0; kc < 300; kc += 25) {
#pragma unroll
        for (int idx = tid; idx < 256 * 25; idx += 256) {
            int r = idx / 25, kk = idx - r * 25;
            int n = n0 + r;
            As[r][kk] = (n < N_NODES) ? g_aggr[(size_t)n * 1500 + t * 300 + kc + kk] : 0.f;
        }
        for (int idx = tid; idx < 25 * 48; idx += 256) {
            int kk = idx / 48, j = idx - kk * 48;
            int g = j >> 4, f = j & 15;
            Bs[kk][j] = (f < FOUT)
                ? W_post[((size_t)((l * TOWERS + t) * 975 + 75 + g * 300 + kc + kk)) * FOUT + f]
                : 0.f;
        }
        __syncthreads();
#pragma unroll 5
        for (int kk = 0; kk < 25; kk++) {
            u64 b0 = *(const u64*)&Bs[kk][2 * tx];
            u64 b1 = *(const u64*)&Bs[kk][16 + 2 * tx];
            u64 b2 = *(const u64*)&Bs[kk][32 + 2 * tx];
#pragma unroll
            for (int i = 0; i < 8; i++) {
                u64 a2 = f2bcast(As[ty + 32 * i][kk]);
                acc[i][0] = ffma2(a2, b0, acc[i][0]);
                acc[i][1] = ffma2(a2, b1, acc[i][1]);
                acc[i][2] = ffma2(a2, b2, acc[i][2]);
            }
        }
        __syncthreads();
    }
#pragma unroll
    for (int i = 0; i < 8; i++) {
        int n = n0 + ty + 32 * i;
        if (n >= N_NODES) continue;
        float amp = g_amp[n], att = g_att[n];
        float a0l, a0h, a1l, a1h, a2l, a2h;
        f2up(acc[i][0], a0l, a0h);
        f2up(acc[i][1], a1l, a1h);
        f2up(acc[i][2], a2l, a2h);
        float* row = g_S + n * F + t * FOUT;
        row[2 * tx] = a0l + amp * a1l + att * a2l;
        if (2 * tx + 1 < FOUT) row[2 * tx + 1] = a0h + amp * a1h + att * a2h;
    }
}

// ---------------- post+lin GEMM (K=150) + BN reduce ----------------
__global__ __launch_bounds__(256) void k_gemm2(const float* __restrict__ W_lin, int l) {
    __shared__ __align__(16) float As[256][25];
    __shared__ __align__(16) float Bs[25][80];
    __shared__ float red[32][80];
    int n0 = blockIdx.x * 256;
    int tid = threadIdx.x;
    int ty = tid >> 3, tx = tid & 7;
    u64 acc[8][5];
#pragma unroll
    for (int i = 0; i < 8; i++)
#pragma unroll
        for (int j = 0; j < 5; j++) acc[i][j] = 0ULL;
    for (int kc = 0; kc < 150; kc += 25) {
#pragma unroll
        for (int idx = tid; idx < 256 * 25; idx += 256) {
            int r = idx / 25, kk = idx - r * 25;
            int n = n0 + r;
            int k = kc + kk;
            float v = 0.f;
            if (n < N_NODES) v = (k < F) ? g_x[n * F + k] : g_S[n * F + (k - F)];
            As[r][kk] = v;
        }
        for (int idx = tid; idx < 25 * 80; idx += 256) {
            int kk = idx / 80, j = idx - kk * 80;
            int k = kc + kk;
            float v = 0.f;
            if (j < F) v = (k < F) ? g_Mfold[k * F + j] : W_lin[(l * F + (k - F)) * F + j];
            Bs[kk][j] = v;
        }
        __syncthreads();
#pragma unroll 5
        for (int kk = 0; kk < 25; kk++) {
            u64 b2[5];
#pragma unroll
            for (int j = 0; j < 5; j++)
                b2[j] = *(const u64*)&Bs[kk][2 * (tx * 5 + j)];
#pragma unroll
            for (int i = 0; i < 8; i++) {
                u64 a2 = f2bcast(As[ty + 32 * i][kk]);
#pragma unroll
                for (int j = 0; j < 5; j++) acc[i][j] = ffma2(a2, b2[j], acc[i][j]);
            }
        }
        __syncthreads();
    }
    float s[10], q[10];
#pragma unroll
    for (int j = 0; j < 10; j++) { s[j] = 0.f; q[j] = 0.f; }
#pragma unroll
    for (int i = 0; i < 8; i++) {
        int n = n0 + ty + 32 * i;
        if (n >= N_NODES) continue;
#pragma unroll
        for (int j = 0; j < 5; j++) {
            int jc = 2 * (tx * 5 + j);
            float lo, hi;
            f2up(acc[i][j], lo, hi);
            if (jc < F) {
                float v = lo + g_bfold[jc];
                g_y[n * F + jc] = v;
                s[2 * j] += v; q[2 * j] += v * v;
            }
            if (jc + 1 < F) {
                float v = hi + g_bfold[jc + 1];
                g_y[n * F + jc + 1] = v;
                s[2 * j + 1] += v; q[2 * j + 1] += v * v;
            }
        }
    }
#pragma unroll
    for (int j = 0; j < 10; j++) red[ty][tx * 10 + j] = s[j];
    __syncthreads();
    if (tid < F) {
        float tot = 0.f;
        for (int yy = 0; yy < 32; yy++) tot += red[yy][tid];
        atomicAdd(&g_bnsum[tid], tot);
    }
    __syncthreads();
#pragma unroll
    for (int j = 0; j < 10; j++) red[ty][tx * 10 + j] = q[j];
    __syncthreads();
    if (tid < F) {
        float tot = 0.f;
        for (int yy = 0; yy < 32; yy++) tot += red[yy][tid];
        atomicAdd(&g_bnsq[tid], tot);
    }
}

// ---------------- BN finalize + apply + ReLU (+ pool on last layer) ------
__global__ void k_bnapply(const float* __restrict__ gamma, const float* __restrict__ beta,
                          const int* __restrict__ batch, int l, int do_pool) {
    __shared__ float sc[F], sh[F];
    int tid = threadIdx.x;
    if (tid < F) {
        float mu = g_bnsum[tid] * (1.f / (float)N_NODES);
        float var = g_bnsq[tid] * (1.f / (float)N_NODES) - mu * mu;
        float r = rsqrtf(var + 1e-5f);
        float s = r * gamma[l * F + tid];
        sc[tid] = s;
        sh[tid] = beta[l * F + tid] - mu * s;
    }
    __syncthreads();
    int base = blockIdx.x * 2048;
#pragma unroll
    for (int o = 0; o < 2048; o += 256) {
        int i = base + o + tid;
        if (i < N_NODES * F) {
            int n = i / F, c = i - n * F;
            float v = fmaxf(g_y[i] * sc[c] + sh[c], 0.f);
            g_x[i] = v;
            if (do_pool) atomicAdd(&g_pooled[batch[n] * F + c], v);
        }
    }
}

// ---------------- final MLP ----------------
__global__ void k_mlp(const float* __restrict__ W1, const float* __restrict__ b1,
                      const float* __restrict__ W2, const float* __restrict__ b2,
                      const float* __restrict__ W3, const float* __restrict__ b3,
                      float* __restrict__ out) {
    __shared__ float w1[75 * 50], w2[50 * 25], w3[25];
    int t = threadIdx.x;
    for (int i = t; i < 75 * 50; i += 256) w1[i] = W1[i];
    for (int i = t; i < 50 * 25; i += 256) w2[i] = W2[i];
    if (t < 25) w3[t] = W3[t];
    __syncthreads();
    if (t >= N_GRAPHS) return;
    const float* p = g_pooled + t * F;
    float h1[50];
    for (int j = 0; j < 50; j++) {
        float a = b1[j];
        for (int c = 0; c < F; c++) a += p[c] * w1[c * 50 + j];
        h1[j] = fmaxf(a, 0.f);
    }
    float h2[25];
    for (int j = 0; j < 25; j++) {
        float a = b2[j];
        for (int c = 0; c < 50; c++) a += h1[c] * w2[c * 25 + j];
        h2[j] = fmaxf(a, 0.f);
    }
    float o = b3[0];
    for (int c = 0; c < 25; c++) o += h2[c] * w3[c];
    out[t] = o;
}

// ---------------- launch ----------------
extern "C" void kernel_launch(void* const* d_in, const int* in_sizes, int n_in,
                              void* d_out, int out_size) {
    const int* x_idx = (const int*)d_in[0];
    const int* edge_index = (const int*)d_in[1];
    const int* eattr = (const int*)d_in[2];
    const int* batch = (const int*)d_in[3];
    const float* node_emb = (const float*)d_in[4];
    const float* edge_emb = (const float*)d_in[5];
    const float* W_edge = (const float*)d_in[6];
    const float* b_edge = (const float*)d_in[7];
    const float* W_pre = (const float*)d_in[8];
    const float* b_pre = (const float*)d_in[9];
    const float* W_post = (const float*)d_in[10];
    const float* b_post = (const float*)d_in[11];
    const float* W_lin = (const float*)d_in[12];
    const float* b_lin = (const float*)d_in[13];
    const float* gamma = (const float*)d_in[14];
    const float* beta = (const float*)d_in[15];
    const float* W1 = (const float*)d_in[16];
    const float* b1 = (const float*)d_in[17];
    const float* W2 = (const float*)d_in[18];
    const float* b2 = (const float*)d_in[19];
    const float* W3 = (const float*)d_in[20];
    const float* b3 = (const float*)d_in[21];
    float* out = (float*)d_out;

    dim3 gx(10, (N_NODES + 255) / 256);

    k_gather_count<<<GATHER_BLKS + COUNT_BLKS, 256>>>(x_idx, node_emb, edge_index); // 1
    k_scanA<<<SCAN_BLKS, 256>>>();                                                  // 2
    k_scanB<<<1, 128>>>();                                                          // 3
    k_xds<<<gx, 256>>>(W_pre, 0);                                                   // 4  <- ncu target
    k_scanC<<<SCAN_BLKS, 256>>>();                                                  // 5
    k_scatter<<<COUNT_BLKS, 256>>>(edge_index, eattr);                              // 6
    k_et_fold<<<N_ATTR + 1, 384>>>(edge_emb, W_edge, b_edge, W_pre, b_pre,
                                   W_post, b_post, W_lin, b_lin, 0);                // 7

    for (int l = 0; l < 2; l++) {
        if (l == 1) {
            k_xds<<<gx, 256>>>(W_pre, 1);
            k_et_fold<<<N_ATTR + 1, 384>>>(edge_emb, W_edge, b_edge, W_pre, b_pre,
                                           W_post, b_post, W_lin, b_lin, 1);
        }
        k_aggr<<<(N_NODES * 32 + 255) / 256, 256>>>();
        {
            dim3 grid((N_NODES + 255) / 256, TOWERS);
            k_gemmS<<<grid, 256>>>(W_post, l);
        }
        k_gemm2<<<(N_NODES + 255) / 256, 256>>>(W_lin, l);
        k_bnapply<<<(N_NODES * F + 2047) / 2048, 256>>>(gamma, beta, batch, l, l == 1);
    }

    k_mlp<<<1, 256>>>(W1, b1, W2, b2, W3, b3, out);
}

// round 5
// speedup vs baseline: 1.0880x; 1.0880x over previous
#include <cuda_runtime.h>
#include <cuda_bf16.h>
#include <math.h>

#define N_NODES 20000
#define N_EDGES 320000
#define N_GRAPHS 200
#define TOWERS 5
#define F 75
#define TF 375
#define EDGE_DIM 50
#define N_ATTR 100
#define FOUT 15
#define ROW 384

// ---------------- static scratch (zero-initialized; pads never written) ----
__device__ float g_x[N_NODES * F];
__device__ float g_y[N_NODES * F];
__device__ float g_xd[(size_t)N_NODES * ROW];
__device__ float g_xs[(size_t)N_NODES * ROW];
__device__ float g_aggr[(size_t)N_NODES * 1500];
__device__ float g_S[N_NODES * F];
__device__ float g_et[N_ATTR * ROW];
__device__ float g_Mfold[F * F];
__device__ float g_bfold[F];
__device__ int   g_deg[N_NODES];
__device__ int   g_rowptr[N_NODES + 1];
__device__ int   g_cursor[N_NODES];
__device__ int2  g_col[N_EDGES];           // (src, attr)
__device__ float g_amp[N_NODES], g_att[N_NODES], g_invdeg[N_NODES];
__device__ float g_logsum;
__device__ int   g_part[128];
__device__ int   g_partscan[128];
__device__ float g_bnsum[F], g_bnsq[F];
__device__ float g_pooled[N_GRAPHS * F];

// ---------------- f32x2 helpers ----------------
typedef unsigned long long u64;
__device__ __forceinline__ u64 f2bcast(float a) {
    u64 r;
    asm("mov.b64 %0, {%1, %1};" : "=l"(r) : "f"(a));
    return r;
}
__device__ __forceinline__ u64 f2pk(float lo, float hi) {
    u64 r;
    asm("mov.b64 %0, {%1, %2};" : "=l"(r) : "f"(lo), "f"(hi));
    return r;
}
__device__ __forceinline__ void f2up(u64 v, float& lo, float& hi) {
    asm("mov.b64 {%0, %1}, %2;" : "=f"(lo), "=f"(hi) : "l"(v));
}
__device__ __forceinline__ u64 ffma2(u64 a, u64 b, u64 c) {
    u64 d;
    asm("fma.rn.f32x2 %0, %1, %2, %3;" : "=l"(d) : "l"(a), "l"(b), "l"(c));
    return d;
}
__device__ __forceinline__ u64 fadd2(u64 a, u64 b) {
    u64 d;
    asm("add.rn.f32x2 %0, %1, %2;" : "=l"(d) : "l"(a), "l"(b));
    return d;
}

// ---------------- preprocessing ----------------
#define GATHER_BLKS ((N_NODES * F + 255) / 256)
#define COUNT_BLKS ((N_EDGES + 255) / 256)
#define SCAN_BLKS ((N_NODES + 255) / 256)

__global__ void k_gather_count(const int* __restrict__ x_idx, const float* __restrict__ emb,
                               const int* __restrict__ ei) {
    int b = blockIdx.x;
    if (b < GATHER_BLKS) {
        int i = b * 256 + threadIdx.x;
        if (i < N_NODES * F) {
            int n = i / F, f = i - n * F;
            g_x[i] = emb[x_idx[n] * F + f];
        }
    } else {
        int i = (b - GATHER_BLKS) * 256 + threadIdx.x;
        if (i < N_EDGES) atomicAdd(&g_deg[ei[N_EDGES + i]], 1);
    }
}

__global__ void k_scanA() {
    __shared__ int ss[256];
    __shared__ float ls[256];
    int b = blockIdx.x, tid = threadIdx.x;
    int n = b * 256 + tid;
    int d = (n < N_NODES) ? g_deg[n] : 0;
    ss[tid] = d;
    ls[tid] = (n < N_NODES) ? logf((float)d + 1.f) : 0.f;
    __syncthreads();
    for (int o = 128; o; o >>= 1) {
        if (tid < o) { ss[tid] += ss[tid + o]; ls[tid] += ls[tid + o]; }
        __syncthreads();
    }
    if (tid == 0) { g_part[b] = ss[0]; atomicAdd(&g_logsum, ls[0]); }
}

__global__ void k_scanB() {
    __shared__ int s[128];
    int t = threadIdx.x;
    int own = (t < SCAN_BLKS) ? g_part[t] : 0;
    s[t] = own;
    __syncthreads();
    for (int o = 1; o < 128; o <<= 1) {
        int v = (t >= o) ? s[t - o] : 0;
        __syncthreads();
        s[t] += v;
        __syncthreads();
    }
    if (t < SCAN_BLKS) g_partscan[t] = s[t] - own;
}

__global__ void k_scanC() {
    __shared__ int s[256];
    int b = blockIdx.x, tid = threadIdx.x;
    int n = b * 256 + tid;
    int d = (n < N_NODES) ? g_deg[n] : 0;
    int own = d;
    s[tid] = d;
    __syncthreads();
    for (int o = 1; o < 256; o <<= 1) {
        int v = (tid >= o) ? s[tid - o] : 0;
        __syncthreads();
        s[tid] += v;
        __syncthreads();
    }
    int excl = s[tid] - own + g_partscan[b];
    if (n < N_NODES) {
        g_rowptr[n] = excl;
        g_cursor[n] = excl;
        float avg = g_logsum * (1.f / (float)N_NODES);
        float dc = fmaxf((float)d, 1.f);
        float L = logf(dc + 1.f);
        g_amp[n] = L / avg;
        g_att[n] = avg / L;
        g_invdeg[n] = 1.f / dc;
        if (n == N_NODES - 1) g_rowptr[N_NODES] = excl + d;
    }
    if (n < N_GRAPHS * F) g_pooled[n] = 0.f;
}

__global__ void k_scatter(const int* __restrict__ ei, const int* __restrict__ ea) {
    int i = blockIdx.x * 256 + threadIdx.x;
    if (i < N_EDGES) {
        int dst = ei[N_EDGES + i];
        int pos = atomicAdd(&g_cursor[dst], 1);
        g_col[pos] = make_int2(ei[i], ea[i]);
    }
    if (i < N_NODES) g_deg[i] = 0;     // reset for next invocation
    if (i == 0) g_logsum = 0.f;
}

// ---------------- per-layer: et table + Mfold + bn zero ----------------
__global__ void k_et_fold(const float* __restrict__ edge_emb, const float* __restrict__ W_edge,
                          const float* __restrict__ b_edge, const float* __restrict__ W_pre,
                          const float* __restrict__ b_pre, const float* __restrict__ W_post,
                          const float* __restrict__ b_post, const float* __restrict__ W_lin,
                          const float* __restrict__ b_lin, int l) {
    int a = blockIdx.x, t = threadIdx.x;
    if (a < N_ATTR) {
        __shared__ float e75[F];
        if (t < F) {
            float acc = b_edge[l * F + t];
            for (int d = 0; d < EDGE_DIM; d++)
                acc += edge_emb[a * EDGE_DIM + d] * W_edge[(l * EDGE_DIM + d) * F + t];
            e75[t] = acc;
        }
        __syncthreads();
        if (t < TF) {
            int tw = t / F, f = t - tw * F;
            float acc = b_pre[(l * TOWERS + tw) * F + f];
            const float* Wp = W_pre + ((size_t)((l * TOWERS + tw) * 225 + 150)) * F + f;
            for (int c = 0; c < F; c++) acc += e75[c] * Wp[c * F];
            g_et[a * ROW + t] = acc;
        }
    } else {
        for (int i = t; i < F * F; i += 384) {
            int c = i / F, o = i - c * F;
            float acc = 0.f;
            for (int tf = 0; tf < F; tf++) {
                int tw = tf / FOUT, f = tf - tw * FOUT;
                acc += W_post[((size_t)((l * TOWERS + tw) * 975 + c)) * FOUT + f] *
                       W_lin[(l * F + tf) * F + o];
            }
            g_Mfold[i] = acc;
        }
        if (t < F) {
            float bf = b_lin[l * F + t];
            for (int tf = 0; tf < F; tf++) {
                int tw = tf / FOUT, f = tf - tw * FOUT;
                bf += b_post[(l * TOWERS + tw) * FOUT + f] * W_lin[(l * F + tf) * F + t];
            }
            g_bfold[t] = bf;
            g_bnsum[t] = 0.f;
            g_bnsq[t] = 0.f;
        }
    }
}

// ---------------- xd|xs GEMM: per (part,tower): [N,75]@[75,75] ----------------
// block: 128 nodes, full K=75 in smem, one sync. 256 thr: ty=tid>>3 (32), tx=tid&7.
// thread tile: 4 nodes (ty+32i) x 5 col-pairs.
__global__ __launch_bounds__(256, 2) void k_xds(const float* __restrict__ W_pre, int l) {
    __shared__ __align__(16) float As[128][76];
    __shared__ __align__(16) float Bs[75][80];
    int c = blockIdx.x;
    int n0 = blockIdx.y * 128;
    int part = c / 5, tw = c - part * 5;
    int tid = threadIdx.x;
    int ty = tid >> 3, tx = tid & 7;
    const float* Wbase = W_pre + (size_t)((l * TOWERS + tw) * 225 + part * F) * F;
    for (int idx = tid; idx < 128 * 75; idx += 256) {
        int r = idx / 75, k = idx - r * 75;
        int n = n0 + r;
        As[r][k] = (n < N_NODES) ? g_x[n * F + k] : 0.f;
    }
    for (int idx = tid; idx < 75 * 80; idx += 256) {
        int k = idx / 80, j = idx - k * 80;
        Bs[k][j] = (j < F) ? Wbase[k * F + j] : 0.f;
    }
    __syncthreads();
    u64 acc[4][5];
#pragma unroll
    for (int i = 0; i < 4; i++)
#pragma unroll
        for (int j = 0; j < 5; j++) acc[i][j] = 0ULL;
#pragma unroll 5
    for (int k = 0; k < 75; k++) {
        u64 b2[5];
#pragma unroll
        for (int j = 0; j < 5; j++)
            b2[j] = *(const u64*)&Bs[k][2 * (tx * 5 + j)];
#pragma unroll
        for (int i = 0; i < 4; i++) {
            u64 a2 = f2bcast(As[ty + 32 * i][k]);
#pragma unroll
            for (int j = 0; j < 5; j++) acc[i][j] = ffma2(a2, b2[j], acc[i][j]);
        }
    }
    float* dst = part ? g_xs : g_xd;
#pragma unroll
    for (int i = 0; i < 4; i++) {
        int n = n0 + ty + 32 * i;
        if (n >= N_NODES) continue;
        float* row = dst + (size_t)n * ROW + tw * F;
#pragma unroll
        for (int j = 0; j < 5; j++) {
            int jc = 2 * (tx * 5 + j);
            float lo, hi;
            f2up(acc[i][j], lo, hi);
            if (jc < F) row[jc] = lo;
            if (jc + 1 < F) row[jc + 1] = hi;
        }
    }
}

// ---------------- aggregation: one warp per dst node ----------------
// m = xd + w, w = xs[src]+et[attr]; shift-equivariant stats: accumulate w, add xd at end.
__global__ void k_aggr() {
    int warp = (blockIdx.x * blockDim.x + threadIdx.x) >> 5;
    int lane = threadIdx.x & 31;
    if (warp >= N_NODES) return;
    int n = warp;
    u64 sum2[6], sq2[6];
    float mn[12], mx[12];
#pragma unroll
    for (int q = 0; q < 6; q++) { sum2[q] = 0ULL; sq2[q] = 0ULL; }
#pragma unroll
    for (int j = 0; j < 12; j++) { mn[j] = INFINITY; mx[j] = -INFINITY; }
    int e0 = g_rowptr[n], e1 = g_rowptr[n + 1];
#pragma unroll 2
    for (int e = e0; e < e1; e++) {
        int2 sa = g_col[e];
        const float4* xs4 = (const float4*)(g_xs + (size_t)sa.x * ROW);
        const float4* et4 = (const float4*)(g_et + sa.y * ROW);
#pragma unroll
        for (int q = 0; q < 3; q++) {
            float4 xv = xs4[lane * 3 + q];
            float4 ev = et4[lane * 3 + q];
            u64 v0 = fadd2(f2pk(xv.x, xv.y), f2pk(ev.x, ev.y));
            u64 v1 = fadd2(f2pk(xv.z, xv.w), f2pk(ev.z, ev.w));
            sum2[2 * q] = fadd2(sum2[2 * q], v0);
            sum2[2 * q + 1] = fadd2(sum2[2 * q + 1], v1);
            sq2[2 * q] = ffma2(v0, v0, sq2[2 * q]);
            sq2[2 * q + 1] = ffma2(v1, v1, sq2[2 * q + 1]);
            float a0, a1, a2, a3;
            f2up(v0, a0, a1);
            f2up(v1, a2, a3);
            int j = q * 4;
            mn[j] = fminf(mn[j], a0); mx[j] = fmaxf(mx[j], a0);
            mn[j + 1] = fminf(mn[j + 1], a1); mx[j + 1] = fmaxf(mx[j + 1], a1);
            mn[j + 2] = fminf(mn[j + 2], a2); mx[j + 2] = fmaxf(mx[j + 2], a2);
            mn[j + 3] = fminf(mn[j + 3], a3); mx[j + 3] = fmaxf(mx[j + 3], a3);
        }
    }
    float inv = g_invdeg[n];
    bool has = e1 > e0;
    const float4* xdrow = (const float4*)(g_xd + (size_t)n * ROW);
#pragma unroll
    for (int q = 0; q < 3; q++) {
        float4 xv = xdrow[lane * 3 + q];
        float xd4[4] = {xv.x, xv.y, xv.z, xv.w};
#pragma unroll
        for (int h4 = 0; h4 < 4; h4++) {
            int j = q * 4 + h4;
            int f = lane * 12 + j;
            if (f >= TF) continue;
            float sm, sqv;
            {
                float lo, hi;
                f2up(sum2[j >> 1], lo, hi);
                sm = (j & 1) ? hi : lo;
                f2up(sq2[j >> 1], lo, hi);
                sqv = (j & 1) ? hi : lo;
            }
            float xd = xd4[h4];
            float meanw = sm * inv;
            float var = sqv * inv - meanw * meanw;
            float sd = sqrtf(fmaxf(var, 0.f) + 1e-5f);
            float mean = has ? (meanw + xd) : 0.f;
            float mnv = has ? (mn[j] + xd) : 0.f;
            float mxv = has ? (mx[j] + xd) : 0.f;
            int tw = f / F, jj = f - tw * F;
            float* outp = g_aggr + (size_t)n * 1500 + tw * 300 + jj;
            outp[0] = mean;
            outp[75] = mnv;
            outp[150] = mxv;
            outp[225] = sd;
        }
    }
}

// ---------------- S GEMM + scaler combine ----------------
__global__ __launch_bounds__(256, 2) void k_gemmS(const float* __restrict__ W_post, int l) {
    __shared__ __align__(16) float As[256][25];
    __shared__ __align__(16) float Bs[25][48];
    int t = blockIdx.y;
    int n0 = blockIdx.x * 256;
    int tid = threadIdx.x;
    int ty = tid >> 3, tx = tid & 7;
    u64 acc[8][3];
#pragma unroll
    for (int i = 0; i < 8; i++)
#pragma unroll
        for (int g = 0; g < 3; g++) acc[i][g] = 0ULL;
    for (int kc = 0; kc < 300; kc += 25) {
        for (int idx = tid; idx < 256 * 25; idx += 256) {
            int r = idx / 25, kk = idx - r * 25;
            int n = n0 + r;
            As[r][kk] = (n < N_NODES) ? g_aggr[(size_t)n * 1500 + t * 300 + kc + kk] : 0.f;
        }
        for (int idx = tid; idx < 25 * 48; idx += 256) {
            int kk = idx / 48, j = idx - kk * 48;
            int g = j >> 4, f = j & 15;
            Bs[kk][j] = (f < FOUT)
                ? W_post[((size_t)((l * TOWERS + t) * 975 + 75 + g * 300 + kc + kk)) * FOUT + f]
                : 0.f;
        }
        __syncthreads();
#pragma unroll 5
        for (int kk = 0; kk < 25; kk++) {
            u64 b0 = *(const u64*)&Bs[kk][2 * tx];
            u64 b1 = *(const u64*)&Bs[kk][16 + 2 * tx];
            u64 b2 = *(const u64*)&Bs[kk][32 + 2 * tx];
#pragma unroll
            for (int i = 0; i < 8; i++) {
                u64 a2 = f2bcast(As[ty + 32 * i][kk]);
                acc[i][0] = ffma2(a2, b0, acc[i][0]);
                acc[i][1] = ffma2(a2, b1, acc[i][1]);
                acc[i][2] = ffma2(a2, b2, acc[i][2]);
            }
        }
        __syncthreads();
    }
#pragma unroll
    for (int i = 0; i < 8; i++) {
        int n = n0 + ty + 32 * i;
        if (n >= N_NODES) continue;
        float amp = g_amp[n], att = g_att[n];
        float a0l, a0h, a1l, a1h, a2l, a2h;
        f2up(acc[i][0], a0l, a0h);
        f2up(acc[i][1], a1l, a1h);
        f2up(acc[i][2], a2l, a2h);
        float* row = g_S + n * F + t * FOUT;
        row[2 * tx] = a0l + amp * a1l + att * a2l;
        if (2 * tx + 1 < FOUT) row[2 * tx + 1] = a0h + amp * a1h + att * a2h;
    }
}

// ---------------- post+lin GEMM (K=150) + BN reduce ----------------
__global__ __launch_bounds__(256, 2) void k_gemm2(const float* __restrict__ W_lin, int l) {
    __shared__ __align__(16) float As[128][25];
    __shared__ __align__(16) float Bs[25][80];
    __shared__ float red[32][80];
    int n0 = blockIdx.x * 128;
    int tid = threadIdx.x;
    int ty = tid >> 3, tx = tid & 7;
    u64 acc[4][5];
#pragma unroll
    for (int i = 0; i < 4; i++)
#pragma unroll
        for (int j = 0; j < 5; j++) acc[i][j] = 0ULL;
    for (int kc = 0; kc < 150; kc += 25) {
        for (int idx = tid; idx < 128 * 25; idx += 256) {
            int r = idx / 25, kk = idx - r * 25;
            int n = n0 + r;
            int k = kc + kk;
            float v = 0.f;
            if (n < N_NODES) v = (k < F) ? g_x[n * F + k] : g_S[n * F + (k - F)];
            As[r][kk] = v;
        }
        for (int idx = tid; idx < 25 * 80; idx += 256) {
            int kk = idx / 80, j = idx - kk * 80;
            int k = kc + kk;
            float v = 0.f;
            if (j < F) v = (k < F) ? g_Mfold[k * F + j] : W_lin[(l * F + (k - F)) * F + j];
            Bs[kk][j] = v;
        }
        __syncthreads();
#pragma unroll 5
        for (int kk = 0; kk < 25; kk++) {
            u64 b2[5];
#pragma unroll
            for (int j = 0; j < 5; j++)
                b2[j] = *(const u64*)&Bs[kk][2 * (tx * 5 + j)];
#pragma unroll
            for (int i = 0; i < 4; i++) {
                u64 a2 = f2bcast(As[ty + 32 * i][kk]);
#pragma unroll
                for (int j = 0; j < 5; j++) acc[i][j] = ffma2(a2, b2[j], acc[i][j]);
            }
        }
        __syncthreads();
    }
    float s[10], q[10];
#pragma unroll
    for (int j = 0; j < 10; j++) { s[j] = 0.f; q[j] = 0.f; }
#pragma unroll
    for (int i = 0; i < 4; i++) {
        int n = n0 + ty + 32 * i;
        if (n >= N_NODES) continue;
#pragma unroll
        for (int j = 0; j < 5; j++) {
            int jc = 2 * (tx * 5 + j);
            float lo, hi;
            f2up(acc[i][j], lo, hi);
            if (jc < F) {
                float v = lo + g_bfold[jc];
                g_y[n * F + jc] = v;
                s[2 * j] += v; q[2 * j] += v * v;
            }
            if (jc + 1 < F) {
                float v = hi + g_bfold[jc + 1];
                g_y[n * F + jc + 1] = v;
                s[2 * j + 1] += v; q[2 * j + 1] += v * v;
            }
        }
    }
#pragma unroll
    for (int j = 0; j < 10; j++) red[ty][tx * 10 + j] = s[j];
    __syncthreads();
    if (tid < F) {
        float tot = 0.f;
        for (int yy = 0; yy < 32; yy++) tot += red[yy][tid];
        atomicAdd(&g_bnsum[tid], tot);
    }
    __syncthreads();
#pragma unroll
    for (int j = 0; j < 10; j++) red[ty][tx * 10 + j] = q[j];
    __syncthreads();
    if (tid < F) {
        float tot = 0.f;
        for (int yy = 0; yy < 32; yy++) tot += red[yy][tid];
        atomicAdd(&g_bnsq[tid], tot);
    }
}

// ---------------- BN finalize + apply + ReLU (+ pool on last layer) ------
__global__ void k_bnapply(const float* __restrict__ gamma, const float* __restrict__ beta,
                          const int* __restrict__ batch, int l, int do_pool) {
    __shared__ float sc[F], sh[F];
    int tid = threadIdx.x;
    if (tid < F) {
        float mu = g_bnsum[tid] * (1.f / (float)N_NODES);
        float var = g_bnsq[tid] * (1.f / (float)N_NODES) - mu * mu;
        float r = rsqrtf(var + 1e-5f);
        float s = r * gamma[l * F + tid];
        sc[tid] = s;
        sh[tid] = beta[l * F + tid] - mu * s;
    }
    __syncthreads();
    int base = blockIdx.x * 2048;
#pragma unroll
    for (int o = 0; o < 2048; o += 256) {
        int i = base + o + tid;
        if (i < N_NODES * F) {
            int n = i / F, c = i - n * F;
            float v = fmaxf(g_y[i] * sc[c] + sh[c], 0.f);
            g_x[i] = v;
            if (do_pool) atomicAdd(&g_pooled[batch[n] * F + c], v);
        }
    }
}

// ---------------- final MLP ----------------
__global__ void k_mlp(const float* __restrict__ W1, const float* __restrict__ b1,
                      const float* __restrict__ W2, const float* __restrict__ b2,
                      const float* __restrict__ W3, const float* __restrict__ b3,
                      float* __restrict__ out) {
    __shared__ float w1[75 * 50], w2[50 * 25], w3[25];
    int t = threadIdx.x;
    for (int i = t; i < 75 * 50; i += 256) w1[i] = W1[i];
    for (int i = t; i < 50 * 25; i += 256) w2[i] = W2[i];
    if (t < 25) w3[t] = W3[t];
    __syncthreads();
    if (t >= N_GRAPHS) return;
    const float* p = g_pooled + t * F;
    float h1[50];
    for (int j = 0; j < 50; j++) {
        float a = b1[j];
        for (int c = 0; c < F; c++) a += p[c] * w1[c * 50 + j];
        h1[j] = fmaxf(a, 0.f);
    }
    float h2[25];
    for (int j = 0; j < 25; j++) {
        float a = b2[j];
        for (int c = 0; c < 50; c++) a += h1[c] * w2[c * 25 + j];
        h2[j] = fmaxf(a, 0.f);
    }
    float o = b3[0];
    for (int c = 0; c < 25; c++) o += h2[c] * w3[c];
    out[t] = o;
}

// ---------------- launch ----------------
extern "C" void kernel_launch(void* const* d_in, const int* in_sizes, int n_in,
                              void* d_out, int out_size) {
    const int* x_idx = (const int*)d_in[0];
    const int* edge_index = (const int*)d_in[1];
    const int* eattr = (const int*)d_in[2];
    const int* batch = (const int*)d_in[3];
    const float* node_emb = (const float*)d_in[4];
    const float* edge_emb = (const float*)d_in[5];
    const float* W_edge = (const float*)d_in[6];
    const float* b_edge = (const float*)d_in[7];
    const float* W_pre = (const float*)d_in[8];
    const float* b_pre = (const float*)d_in[9];
    const float* W_post = (const float*)d_in[10];
    const float* b_post = (const float*)d_in[11];
    const float* W_lin = (const float*)d_in[12];
    const float* b_lin = (const float*)d_in[13];
    const float* gamma = (const float*)d_in[14];
    const float* beta = (const float*)d_in[15];
    const float* W1 = (const float*)d_in[16];
    const float* b1 = (const float*)d_in[17];
    const float* W2 = (const float*)d_in[18];
    const float* b2 = (const float*)d_in[19];
    const float* W3 = (const float*)d_in[20];
    const float* b3 = (const float*)d_in[21];
    float* out = (float*)d_out;

    dim3 gx(10, (N_NODES + 127) / 128);

    k_gather_count<<<GATHER_BLKS + COUNT_BLKS, 256>>>(x_idx, node_emb, edge_index); // 1
    k_scanA<<<SCAN_BLKS, 256>>>();                                                  // 2
    k_scanB<<<1, 128>>>();                                                          // 3
    k_xds<<<gx, 256>>>(W_pre, 0);                                                   // 4  <- ncu target
    k_scanC<<<SCAN_BLKS, 256>>>();                                                  // 5
    k_scatter<<<COUNT_BLKS, 256>>>(edge_index, eattr);                              // 6
    k_et_fold<<<N_ATTR + 1, 384>>>(edge_emb, W_edge, b_edge, W_pre, b_pre,
                                   W_post, b_post, W_lin, b_lin, 0);                // 7

    for (int l = 0; l < 2; l++) {
        if (l == 1) {
            k_xds<<<gx, 256>>>(W_pre, 1);
            k_et_fold<<<N_ATTR + 1, 384>>>(edge_emb, W_edge, b_edge, W_pre, b_pre,
                                           W_post, b_post, W_lin, b_lin, 1);
        }
        k_aggr<<<(N_NODES * 32 + 255) / 256, 256>>>();
        {
            dim3 grid((N_NODES + 255) / 256, TOWERS);
            k_gemmS<<<grid, 256>>>(W_post, l);
        }
        k_gemm2<<<(N_NODES + 127) / 128, 256>>>(W_lin, l);
        k_bnapply<<<(N_NODES * F + 2047) / 2048, 256>>>(gamma, beta, batch, l, l == 1);
    }

    k_mlp<<<1, 256>>>(W1, b1, W2, b2, W3, b3, out);
}

// round 7
// speedup vs baseline: 1.0907x; 1.0024x over previous
#include <cuda_runtime.h>
#include <cuda_bf16.h>
#include <math.h>

#define N_NODES 20000
#define N_EDGES 320000
#define N_GRAPHS 200
#define TOWERS 5
#define F 75
#define TF 375
#define EDGE_DIM 50
#define N_ATTR 100
#define FOUT 15
#define ROW 384

// ---------------- static scratch (zero-initialized; pads never written) ----
__device__ float g_x[N_NODES * F];
__device__ float g_y[N_NODES * F];
__device__ float g_xd[(size_t)N_NODES * ROW];
__device__ float g_xs[(size_t)N_NODES * ROW];
__device__ float g_aggr[(size_t)N_NODES * 1500];
__device__ float g_S[N_NODES * F];
__device__ float g_et[N_ATTR * ROW];
__device__ float g_Mfold[F * F];
__device__ float g_bfold[F];
__device__ int   g_deg[N_NODES];
__device__ int   g_rowptr[N_NODES + 1];
__device__ int   g_cursor[N_NODES];
__device__ int2  g_col[N_EDGES];           // (src, attr)
__device__ float g_amp[N_NODES], g_att[N_NODES], g_invdeg[N_NODES];
__device__ float g_logsum;
__device__ int   g_part[128];
__device__ int   g_partscan[128];
__device__ float g_bnsum[F], g_bnsq[F];
__device__ float g_pooled[N_GRAPHS * F];

// ---------------- f32x2 helpers ----------------
typedef unsigned long long u64;
__device__ __forceinline__ u64 f2bcast(float a) {
    u64 r;
    asm("mov.b64 %0, {%1, %1};" : "=l"(r) : "f"(a));
    return r;
}
__device__ __forceinline__ u64 f2pk(float lo, float hi) {
    u64 r;
    asm("mov.b64 %0, {%1, %2};" : "=l"(r) : "f"(lo), "f"(hi));
    return r;
}
__device__ __forceinline__ void f2up(u64 v, float& lo, float& hi) {
    asm("mov.b64 {%0, %1}, %2;" : "=f"(lo), "=f"(hi) : "l"(v));
}
__device__ __forceinline__ u64 ffma2(u64 a, u64 b, u64 c) {
    u64 d;
    asm("fma.rn.f32x2 %0, %1, %2, %3;" : "=l"(d) : "l"(a), "l"(b), "l"(c));
    return d;
}
__device__ __forceinline__ u64 fadd2(u64 a, u64 b) {
    u64 d;
    asm("add.rn.f32x2 %0, %1, %2;" : "=l"(d) : "l"(a), "l"(b));
    return d;
}

// ---------------- preprocessing ----------------
#define GATHER_BLKS ((N_NODES * F + 255) / 256)
#define COUNT_BLKS ((N_EDGES + 255) / 256)
#define SCAN_BLKS ((N_NODES + 255) / 256)

__global__ void k_gather_count(const int* __restrict__ x_idx, const float* __restrict__ emb,
                               const int* __restrict__ ei) {
    int b = blockIdx.x;
    if (b < GATHER_BLKS) {
        int i = b * 256 + threadIdx.x;
        if (i < N_NODES * F) {
            int n = i / F, f = i - n * F;
            g_x[i] = emb[x_idx[n] * F + f];
        }
    } else {
        int i = (b - GATHER_BLKS) * 256 + threadIdx.x;
        if (i < N_EDGES) atomicAdd(&g_deg[ei[N_EDGES + i]], 1);
    }
}

__global__ void k_scanA() {
    __shared__ int ss[256];
    __shared__ float ls[256];
    int b = blockIdx.x, tid = threadIdx.x;
    int n = b * 256 + tid;
    int d = (n < N_NODES) ? g_deg[n] : 0;
    ss[tid] = d;
    ls[tid] = (n < N_NODES) ? logf((float)d + 1.f) : 0.f;
    __syncthreads();
    for (int o = 128; o; o >>= 1) {
        if (tid < o) { ss[tid] += ss[tid + o]; ls[tid] += ls[tid + o]; }
        __syncthreads();
    }
    if (tid == 0) { g_part[b] = ss[0]; atomicAdd(&g_logsum, ls[0]); }
}

__global__ void k_scanB() {
    __shared__ int s[128];
    int t = threadIdx.x;
    int own = (t < SCAN_BLKS) ? g_part[t] : 0;
    s[t] = own;
    __syncthreads();
    for (int o = 1; o < 128; o <<= 1) {
        int v = (t >= o) ? s[t - o] : 0;
        __syncthreads();
        s[t] += v;
        __syncthreads();
    }
    if (t < SCAN_BLKS) g_partscan[t] = s[t] - own;
}

__global__ void k_scanC() {
    __shared__ int s[256];
    int b = blockIdx.x, tid = threadIdx.x;
    int n = b * 256 + tid;
    int d = (n < N_NODES) ? g_deg[n] : 0;
    int own = d;
    s[tid] = d;
    __syncthreads();
    for (int o = 1; o < 256; o <<= 1) {
        int v = (tid >= o) ? s[tid - o] : 0;
        __syncthreads();
        s[tid] += v;
        __syncthreads();
    }
    int excl = s[tid] - own + g_partscan[b];
    if (n < N_NODES) {
        g_rowptr[n] = excl;
        g_cursor[n] = excl;
        float avg = g_logsum * (1.f / (float)N_NODES);
        float dc = fmaxf((float)d, 1.f);
        float L = logf(dc + 1.f);
        g_amp[n] = L / avg;
        g_att[n] = avg / L;
        g_invdeg[n] = 1.f / dc;
        if (n == N_NODES - 1) g_rowptr[N_NODES] = excl + d;
    }
    if (n < N_GRAPHS * F) g_pooled[n] = 0.f;
}

__global__ void k_scatter(const int* __restrict__ ei, const int* __restrict__ ea) {
    int i = blockIdx.x * 256 + threadIdx.x;
    if (i < N_EDGES) {
        int dst = ei[N_EDGES + i];
        int pos = atomicAdd(&g_cursor[dst], 1);
        g_col[pos] = make_int2(ei[i], ea[i]);
    }
    if (i < N_NODES) g_deg[i] = 0;     // reset for next invocation
    if (i == 0) g_logsum = 0.f;
}

// ---------------- per-layer: et table + Mfold + bn zero ----------------
__global__ void k_et_fold(const float* __restrict__ edge_emb, const float* __restrict__ W_edge,
                          const float* __restrict__ b_edge, const float* __restrict__ W_pre,
                          const float* __restrict__ b_pre, const float* __restrict__ W_post,
                          const float* __restrict__ b_post, const float* __restrict__ W_lin,
                          const float* __restrict__ b_lin, int l) {
    int a = blockIdx.x, t = threadIdx.x;
    if (a < N_ATTR) {
        __shared__ float e75[F];
        if (t < F) {
            float acc = b_edge[l * F + t];
            for (int d = 0; d < EDGE_DIM; d++)
                acc += edge_emb[a * EDGE_DIM + d] * W_edge[(l * EDGE_DIM + d) * F + t];
            e75[t] = acc;
        }
        __syncthreads();
        if (t < TF) {
            int tw = t / F, f = t - tw * F;
            float acc = b_pre[(l * TOWERS + tw) * F + f];
            const float* Wp = W_pre + ((size_t)((l * TOWERS + tw) * 225 + 150)) * F + f;
            for (int c = 0; c < F; c++) acc += e75[c] * Wp[c * F];
            g_et[a * ROW + t] = acc;
        }
    } else {
        for (int i = t; i < F * F; i += 384) {
            int c = i / F, o = i - c * F;
            float acc = 0.f;
            for (int tf = 0; tf < F; tf++) {
                int tw = tf / FOUT, f = tf - tw * FOUT;
                acc += W_post[((size_t)((l * TOWERS + tw) * 975 + c)) * FOUT + f] *
                       W_lin[(l * F + tf) * F + o];
            }
            g_Mfold[i] = acc;
        }
        if (t < F) {
            float bf = b_lin[l * F + t];
            for (int tf = 0; tf < F; tf++) {
                int tw = tf / FOUT, f = tf - tw * FOUT;
                bf += b_post[(l * TOWERS + tw) * FOUT + f] * W_lin[(l * F + tf) * F + t];
            }
            g_bfold[t] = bf;
            g_bnsum[t] = 0.f;
            g_bnsq[t] = 0.f;
        }
    }
}

// ---------------- xd|xs GEMM: per (part,tower): [N,75]@[75,75] ----------------
// block: 128 nodes, K chunked by 25 (small smem -> 3 blocks/SM).
// 256 thr: ty=tid>>3 (32), tx=tid&7. thread tile 4 nodes x 5 col-pairs.
__global__ __launch_bounds__(256, 3) void k_xds(const float* __restrict__ W_pre, int l) {
    __shared__ __align__(16) float As[128][25];
    __shared__ __align__(16) float Bs[25][80];
    int c = blockIdx.x;
    int n0 = blockIdx.y * 128;
    int part = c / 5, tw = c - part * 5;
    int tid = threadIdx.x;
    int ty = tid >> 3, tx = tid & 7;
    const float* Wbase = W_pre + (size_t)((l * TOWERS + tw) * 225 + part * F) * F;
    u64 acc[4][5];
#pragma unroll
    for (int i = 0; i < 4; i++)
#pragma unroll
        for (int j = 0; j < 5; j++) acc[i][j] = 0ULL;
    for (int kc = 0; kc < F; kc += 25) {
#pragma unroll
        for (int s = 0; s < 13; s++) {
            int idx = tid + s * 256;
            if (idx < 128 * 25) {
                int r = idx / 25, kk = idx - r * 25;
                int n = n0 + r;
                As[r][kk] = (n < N_NODES) ? g_x[n * F + kc + kk] : 0.f;
            }
        }
#pragma unroll
        for (int s = 0; s < 8; s++) {
            int idx = tid + s * 256;
            if (idx < 25 * 80) {
                int kk = idx / 80, j = idx - kk * 80;
                Bs[kk][j] = (j < F) ? Wbase[(kc + kk) * F + j] : 0.f;
            }
        }
        __syncthreads();
#pragma unroll 5
        for (int kk = 0; kk < 25; kk++) {
            u64 b2[5];
#pragma unroll
            for (int j = 0; j < 5; j++)
                b2[j] = *(const u64*)&Bs[kk][2 * (tx * 5 + j)];
#pragma unroll
            for (int i = 0; i < 4; i++) {
                u64 a2 = f2bcast(As[ty + 32 * i][kk]);
#pragma unroll
                for (int j = 0; j < 5; j++) acc[i][j] = ffma2(a2, b2[j], acc[i][j]);
            }
        }
        __syncthreads();
    }
    float* dst = part ? g_xs : g_xd;
#pragma unroll
    for (int i = 0; i < 4; i++) {
        int n = n0 + ty + 32 * i;
        if (n >= N_NODES) continue;
        float* row = dst + (size_t)n * ROW + tw * F;
#pragma unroll
        for (int j = 0; j < 5; j++) {
            int jc = 2 * (tx * 5 + j);
            float lo, hi;
            f2up(acc[i][j], lo, hi);
            if (jc < F) row[jc] = lo;
            if (jc + 1 < F) row[jc + 1] = hi;
        }
    }
}

// ---------------- aggregation: one warp per dst node ----------------
__global__ void k_aggr() {
    int warp = (blockIdx.x * blockDim.x + threadIdx.x) >> 5;
    int lane = threadIdx.x & 31;
    if (warp >= N_NODES) return;
    int n = warp;
    u64 sum2[6], sq2[6];
    float mn[12], mx[12];
#pragma unroll
    for (int q = 0; q < 6; q++) { sum2[q] = 0ULL; sq2[q] = 0ULL; }
#pragma unroll
    for (int j = 0; j < 12; j++) { mn[j] = INFINITY; mx[j] = -INFINITY; }
    int e0 = g_rowptr[n], e1 = g_rowptr[n + 1];
#pragma unroll 2
    for (int e = e0; e < e1; e++) {
        int2 sa = g_col[e];
        const float4* xs4 = (const float4*)(g_xs + (size_t)sa.x * ROW);
        const float4* et4 = (const float4*)(g_et + sa.y * ROW);
#pragma unroll
        for (int q = 0; q < 3; q++) {
            float4 xv = xs4[lane * 3 + q];
            float4 ev = et4[lane * 3 + q];
            u64 v0 = fadd2(f2pk(xv.x, xv.y), f2pk(ev.x, ev.y));
            u64 v1 = fadd2(f2pk(xv.z, xv.w), f2pk(ev.z, ev.w));
            sum2[2 * q] = fadd2(sum2[2 * q], v0);
            sum2[2 * q + 1] = fadd2(sum2[2 * q + 1], v1);
            sq2[2 * q] = ffma2(v0, v0, sq2[2 * q]);
            sq2[2 * q + 1] = ffma2(v1, v1, sq2[2 * q + 1]);
            float a0, a1, a2, a3;
            f2up(v0, a0, a1);
            f2up(v1, a2, a3);
            int j = q * 4;
            mn[j] = fminf(mn[j], a0); mx[j] = fmaxf(mx[j], a0);
            mn[j + 1] = fminf(mn[j + 1], a1); mx[j + 1] = fmaxf(mx[j + 1], a1);
            mn[j + 2] = fminf(mn[j + 2], a2); mx[j + 2] = fmaxf(mx[j + 2], a2);
            mn[j + 3] = fminf(mn[j + 3], a3); mx[j + 3] = fmaxf(mx[j + 3], a3);
        }
    }
    float inv = g_invdeg[n];
    bool has = e1 > e0;
    const float4* xdrow = (const float4*)(g_xd + (size_t)n * ROW);
#pragma unroll
    for (int q = 0; q < 3; q++) {
        float4 xv = xdrow[lane * 3 + q];
        float xd4[4] = {xv.x, xv.y, xv.z, xv.w};
#pragma unroll
        for (int h4 = 0; h4 < 4; h4++) {
            int j = q * 4 + h4;
            int f = lane * 12 + j;
            if (f >= TF) continue;
            float sm, sqv;
            {
                float lo, hi;
                f2up(sum2[j >> 1], lo, hi);
                sm = (j & 1) ? hi : lo;
                f2up(sq2[j >> 1], lo, hi);
                sqv = (j & 1) ? hi : lo;
            }
            float xd = xd4[h4];
            float meanw = sm * inv;
            float var = sqv * inv - meanw * meanw;
            float sd = sqrtf(fmaxf(var, 0.f) + 1e-5f);
            float mean = has ? (meanw + xd) : 0.f;
            float mnv = has ? (mn[j] + xd) : 0.f;
            float mxv = has ? (mx[j] + xd) : 0.f;
            int tw = f / F, jj = f - tw * F;
            float* outp = g_aggr + (size_t)n * 1500 + tw * 300 + jj;
            outp[0] = mean;
            outp[75] = mnv;
            outp[150] = mxv;
            outp[225] = sd;
        }
    }
}

// ---------------- S GEMM + scaler combine, register-staged prefetch ----------
// per tower: [N,300]@[300,48pad]; block 128 nodes; 12 K-chunks of 25.
// 256 thr: ty=tid>>3 (32), tx=tid&7. tile 4 nodes x pairs {2tx,16+2tx,32+2tx}.
__global__ __launch_bounds__(256, 4) void k_gemmS(const float* __restrict__ W_post, int l) {
    __shared__ __align__(16) float As[128][25];
    __shared__ __align__(16) float Bs[25][48];
    int t = blockIdx.y;
    int n0 = blockIdx.x * 128;
    int tid = threadIdx.x;
    int ty = tid >> 3, tx = tid & 7;
    const float* Wb = W_post + (size_t)((l * TOWERS + t) * 975 + 75) * FOUT;
    u64 acc[4][3];
#pragma unroll
    for (int i = 0; i < 4; i++)
#pragma unroll
        for (int g = 0; g < 3; g++) acc[i][g] = 0ULL;
    float areg[13], breg[5];
    // preload chunk 0
#pragma unroll
    for (int s = 0; s < 13; s++) {
        int idx = tid + s * 256;
        if (idx < 128 * 25) {
            int r = idx / 25, kk = idx - r * 25;
            int n = n0 + r;
            areg[s] = (n < N_NODES) ? g_aggr[(size_t)n * 1500 + t * 300 + kk] : 0.f;
        }
    }
#pragma unroll
    for (int s = 0; s < 5; s++) {
        int idx = tid + s * 256;
        if (idx < 25 * 48) {
            int kk = idx / 48, j = idx - kk * 48;
            int g = j >> 4, f = j & 15;
            breg[s] = (f < FOUT) ? Wb[(size_t)(g * 300 + kk) * FOUT + f] : 0.f;
        }
    }
    for (int kc = 0; kc < 300; kc += 25) {
        // commit staged chunk to smem
#pragma unroll
        for (int s = 0; s < 13; s++) {
            int idx = tid + s * 256;
            if (idx < 128 * 25) As[idx / 25][idx - (idx / 25) * 25] = areg[s];
        }
#pragma unroll
        for (int s = 0; s < 5; s++) {
            int idx = tid + s * 256;
            if (idx < 25 * 48) Bs[idx / 48][idx - (idx / 48) * 48] = breg[s];
        }
        __syncthreads();
        // prefetch next chunk while computing
        int kn = kc + 25;
        if (kn < 300) {
#pragma unroll
            for (int s = 0; s < 13; s++) {
                int idx = tid + s * 256;
                if (idx < 128 * 25) {
                    int r = idx / 25, kk = idx - r * 25;
                    int n = n0 + r;
                    areg[s] = (n < N_NODES) ? g_aggr[(size_t)n * 1500 + t * 300 + kn + kk] : 0.f;
                }
            }
#pragma unroll
            for (int s = 0; s < 5; s++) {
                int idx = tid + s * 256;
                if (idx < 25 * 48) {
                    int kk = idx / 48, j = idx - kk * 48;
                    int g = j >> 4, f = j & 15;
                    breg[s] = (f < FOUT) ? Wb[(size_t)(g * 300 + kn + kk) * FOUT + f] : 0.f;
                }
            }
        }
#pragma unroll 5
        for (int kk = 0; kk < 25; kk++) {
            u64 b0 = *(const u64*)&Bs[kk][2 * tx];
            u64 b1 = *(const u64*)&Bs[kk][16 + 2 * tx];
            u64 b2 = *(const u64*)&Bs[kk][32 + 2 * tx];
#pragma unroll
            for (int i = 0; i < 4; i++) {
                u64 a2 = f2bcast(As[ty + 32 * i][kk]);
                acc[i][0] = ffma2(a2, b0, acc[i][0]);
                acc[i][1] = ffma2(a2, b1, acc[i][1]);
                acc[i][2] = ffma2(a2, b2, acc[i][2]);
            }
        }
        __syncthreads();
    }
#pragma unroll
    for (int i = 0; i < 4; i++) {
        int n = n0 + ty + 32 * i;
        if (n >= N_NODES) continue;
        float amp = g_amp[n], att = g_att[n];
        float a0l, a0h, a1l, a1h, a2l, a2h;
        f2up(acc[i][0], a0l, a0h);
        f2up(acc[i][1], a1l, a1h);
        f2up(acc[i][2], a2l, a2h);
        float* row = g_S + n * F + t * FOUT;
        row[2 * tx] = a0l + amp * a1l + att * a2l;
        if (2 * tx + 1 < FOUT) row[2 * tx + 1] = a0h + amp * a1h + att * a2h;
    }
}

// ---------------- post+lin GEMM (K=150) + BN reduce ----------------
__global__ __launch_bounds__(256, 3) void k_gemm2(const float* __restrict__ W_lin, int l) {
    __shared__ __align__(16) float As[128][25];
    __shared__ __align__(16) float Bs[25][80];
    __shared__ float red[32][80];
    int n0 = blockIdx.x * 128;
    int tid = threadIdx.x;
    int ty = tid >> 3, tx = tid & 7;
    u64 acc[4][5];
#pragma unroll
    for (int i = 0; i < 4; i++)
#pragma unroll
        for (int j = 0; j < 5; j++) acc[i][j] = 0ULL;
    for (int kc = 0; kc < 150; kc += 25) {
#pragma unroll
        for (int s = 0; s < 13; s++) {
            int idx = tid + s * 256;
            if (idx < 128 * 25) {
                int r = idx / 25, kk = idx - r * 25;
                int n = n0 + r;
                int k = kc + kk;
                float v = 0.f;
                if (n < N_NODES) v = (k < F) ? g_x[n * F + k] : g_S[n * F + (k - F)];
                As[r][kk] = v;
            }
        }
#pragma unroll
        for (int s = 0; s < 8; s++) {
            int idx = tid + s * 256;
            if (idx < 25 * 80) {
                int kk = idx / 80, j = idx - kk * 80;
                int k = kc + kk;
                float v = 0.f;
                if (j < F) v = (k < F) ? g_Mfold[k * F + j] : W_lin[(l * F + (k - F)) * F + j];
                Bs[kk][j] = v;
            }
        }
        __syncthreads();
#pragma unroll 5
        for (int kk = 0; kk < 25; kk++) {
            u64 b2[5];
#pragma unroll
            for (int j = 0; j < 5; j++)
                b2[j] = *(const u64*)&Bs[kk][2 * (tx * 5 + j)];
#pragma unroll
            for (int i = 0; i < 4; i++) {
                u64 a2 = f2bcast(As[ty + 32 * i][kk]);
#pragma unroll
                for (int j = 0; j < 5; j++) acc[i][j] = ffma2(a2, b2[j], acc[i][j]);
            }
        }
        __syncthreads();
    }
    float s[10], q[10];
#pragma unroll
    for (int j = 0; j < 10; j++) { s[j] = 0.f; q[j] = 0.f; }
#pragma unroll
    for (int i = 0; i < 4; i++) {
        int n = n0 + ty + 32 * i;
        if (n >= N_NODES) continue;
#pragma unroll
        for (int j = 0; j < 5; j++) {
            int jc = 2 * (tx * 5 + j);
            float lo, hi;
            f2up(acc[i][j], lo, hi);
            if (jc < F) {
                float v = lo + g_bfold[jc];
                g_y[n * F + jc] = v;
                s[2 * j] += v; q[2 * j] += v * v;
            }
            if (jc + 1 < F) {
                float v = hi + g_bfold[jc + 1];
                g_y[n * F + jc + 1] = v;
                s[2 * j + 1] += v; q[2 * j + 1] += v * v;
            }
        }
    }
#pragma unroll
    for (int j = 0; j < 10; j++) red[ty][tx * 10 + j] = s[j];
    __syncthreads();
    if (tid < F) {
        float tot = 0.f;
        for (int yy = 0; yy < 32; yy++) tot += red[yy][tid];
        atomicAdd(&g_bnsum[tid], tot);
    }
    __syncthreads();
#pragma unroll
    for (int j = 0; j < 10; j++) red[ty][tx * 10 + j] = q[j];
    __syncthreads();
    if (tid < F) {
        float tot = 0.f;
        for (int yy = 0; yy < 32; yy++) tot += red[yy][tid];
        atomicAdd(&g_bnsq[tid], tot);
    }
}

// ---------------- BN finalize + apply + ReLU (+ pool on last layer) ------
__global__ void k_bnapply(const float* __restrict__ gamma, const float* __restrict__ beta,
                          const int* __restrict__ batch, int l, int do_pool) {
    __shared__ float sc[F], sh[F];
    int tid = threadIdx.x;
    if (tid < F) {
        float mu = g_bnsum[tid] * (1.f / (float)N_NODES);
        float var = g_bnsq[tid] * (1.f / (float)N_NODES) - mu * mu;
        float r = rsqrtf(var + 1e-5f);
        float s = r * gamma[l * F + tid];
        sc[tid] = s;
        sh[tid] = beta[l * F + tid] - mu * s;
    }
    __syncthreads();
    int base = blockIdx.x * 2048;
#pragma unroll
    for (int o = 0; o < 2048; o += 256) {
        int i = base + o + tid;
        if (i < N_NODES * F) {
            int n = i / F, c = i - n * F;
            float v = fmaxf(g_y[i] * sc[c] + sh[c], 0.f);
            g_x[i] = v;
            if (do_pool) atomicAdd(&g_pooled[batch[n] * F + c], v);
        }
    }
}

// ---------------- final MLP ----------------
__global__ void k_mlp(const float* __restrict__ W1, const float* __restrict__ b1,
                      const float* __restrict__ W2, const float* __restrict__ b2,
                      const float* __restrict__ W3, const float* __restrict__ b3,
                      float* __restrict__ out) {
    __shared__ float w1[75 * 50], w2[50 * 25], w3[25];
    int t = threadIdx.x;
    for (int i = t; i < 75 * 50; i += 256) w1[i] = W1[i];
    for (int i = t; i < 50 * 25; i += 256) w2[i] = W2[i];
    if (t < 25) w3[t] = W3[t];
    __syncthreads();
    if (t >= N_GRAPHS) return;
    const float* p = g_pooled + t * F;
    float h1[50];
    for (int j = 0; j < 50; j++) {
        float a = b1[j];
        for (int c = 0; c < F; c++) a += p[c] * w1[c * 50 + j];
        h1[j] = fmaxf(a, 0.f);
    }
    float h2[25];
    for (int j = 0; j < 25; j++) {
        float a = b2[j];
        for (int c = 0; c < 50; c++) a += h1[c] * w2[c * 25 + j];
        h2[j] = fmaxf(a, 0.f);
    }
    float o = b3[0];
    for (int c = 0; c < 25; c++) o += h2[c] * w3[c];
    out[t] = o;
}

// ---------------- launch ----------------
extern "C" void kernel_launch(void* const* d_in, const int* in_sizes, int n_in,
                              void* d_out, int out_size) {
    const int* x_idx = (const int*)d_in[0];
    const int* edge_index = (const int*)d_in[1];
    const int* eattr = (const int*)d_in[2];
    const int* batch = (const int*)d_in[3];
    const float* node_emb = (const float*)d_in[4];
    const float* edge_emb = (const float*)d_in[5];
    const float* W_edge = (const float*)d_in[6];
    const float* b_edge = (const float*)d_in[7];
    const float* W_pre = (const float*)d_in[8];
    const float* b_pre = (const float*)d_in[9];
    const float* W_post = (const float*)d_in[10];
    const float* b_post = (const float*)d_in[11];
    const float* W_lin = (const float*)d_in[12];
    const float* b_lin = (const float*)d_in[13];
    const float* gamma = (const float*)d_in[14];
    const float* beta = (const float*)d_in[15];
    const float* W1 = (const float*)d_in[16];
    const float* b1 = (const float*)d_in[17];
    const float* W2 = (const float*)d_in[18];
    const float* b2 = (const float*)d_in[19];
    const float* W3 = (const float*)d_in[20];
    const float* b3 = (const float*)d_in[21];
    float* out = (float*)d_out;

    dim3 gx(10, (N_NODES + 127) / 128);

    k_gather_count<<<GATHER_BLKS + COUNT_BLKS, 256>>>(x_idx, node_emb, edge_index); // 1
    k_scanA<<<SCAN_BLKS, 256>>>();                                                  // 2
    k_scanB<<<1, 128>>>();                                                          // 3
    k_xds<<<gx, 256>>>(W_pre, 0);                                                   // 4  <- ncu target
    k_scanC<<<SCAN_BLKS, 256>>>();                                                  // 5
    k_scatter<<<COUNT_BLKS, 256>>>(edge_index, eattr);                              // 6
    k_et_fold<<<N_ATTR + 1, 384>>>(edge_emb, W_edge, b_edge, W_pre, b_pre,
                                   W_post, b_post, W_lin, b_lin, 0);                // 7

    for (int l = 0; l < 2; l++) {
        if (l == 1) {
            k_xds<<<gx, 256>>>(W_pre, 1);
            k_et_fold<<<N_ATTR + 1, 384>>>(edge_emb, W_edge, b_edge, W_pre, b_pre,
                                           W_post, b_post, W_lin, b_lin, 1);
        }
        k_aggr<<<(N_NODES * 32 + 255) / 256, 256>>>();
        {
            dim3 grid((N_NODES + 127) / 128, TOWERS);
            k_gemmS<<<grid, 256>>>(W_post, l);
        }
        k_gemm2<<<(N_NODES + 127) / 128, 256>>>(W_lin, l);
        k_bnapply<<<(N_NODES * F + 2047) / 2048, 256>>>(gamma, beta, batch, l, l == 1);
    }

    k_mlp<<<1, 256>>>(W1, b1, W2, b2, W3, b3, out);
}

// round 8
// speedup vs baseline: 1.1766x; 1.0788x over previous
#include <cuda_runtime.h>
#include <cuda_bf16.h>
#include <math.h>

#define N_NODES 20000
#define N_EDGES 320000
#define N_GRAPHS 200
#define TOWERS 5
#define F 75
#define TF 375
#define EDGE_DIM 50
#define N_ATTR 100
#define FOUT 15
#define ROW 384

// ---------------- static scratch (zero-initialized; pads never written) ----
__device__ float g_x[N_NODES * F];
__device__ float g_y[N_NODES * F];
__device__ float g_xd[(size_t)N_NODES * ROW];
__device__ float g_xs[(size_t)N_NODES * ROW];
__device__ float g_aggr[(size_t)N_NODES * 1500];
__device__ float g_S[N_NODES * F];
__device__ float g_et[N_ATTR * ROW];
__device__ float g_Mfold[F * F];
__device__ float g_bfold[F];
__device__ int   g_deg[N_NODES];
__device__ int   g_rowptr[N_NODES + 1];
__device__ int   g_cursor[N_NODES];
__device__ int2  g_col[N_EDGES];           // (src, attr)
__device__ float g_amp[N_NODES], g_att[N_NODES], g_invdeg[N_NODES];
__device__ float g_logsum;
__device__ int   g_part[128];
__device__ int   g_partscan[128];
__device__ float g_bnsum[F], g_bnsq[F];
__device__ float g_pooled[N_GRAPHS * F];

// ---------------- f32x2 helpers ----------------
typedef unsigned long long u64;
__device__ __forceinline__ u64 f2bcast(float a) {
    u64 r;
    asm("mov.b64 %0, {%1, %1};" : "=l"(r) : "f"(a));
    return r;
}
__device__ __forceinline__ u64 f2pk(float lo, float hi) {
    u64 r;
    asm("mov.b64 %0, {%1, %2};" : "=l"(r) : "f"(lo), "f"(hi));
    return r;
}
__device__ __forceinline__ void f2up(u64 v, float& lo, float& hi) {
    asm("mov.b64 {%0, %1}, %2;" : "=f"(lo), "=f"(hi) : "l"(v));
}
__device__ __forceinline__ u64 ffma2(u64 a, u64 b, u64 c) {
    u64 d;
    asm("fma.rn.f32x2 %0, %1, %2, %3;" : "=l"(d) : "l"(a), "l"(b), "l"(c));
    return d;
}
__device__ __forceinline__ u64 fadd2(u64 a, u64 b) {
    u64 d;
    asm("add.rn.f32x2 %0, %1, %2;" : "=l"(d) : "l"(a), "l"(b));
    return d;
}

// ---------------- preprocessing ----------------
#define GATHER_BLKS ((N_NODES * F + 255) / 256)
#define COUNT_BLKS ((N_EDGES + 255) / 256)
#define SCAN_BLKS ((N_NODES + 255) / 256)

__global__ void k_gather_count(const int* __restrict__ x_idx, const float* __restrict__ emb,
                               const int* __restrict__ ei) {
    int b = blockIdx.x;
    if (b < GATHER_BLKS) {
        int i = b * 256 + threadIdx.x;
        if (i < N_NODES * F) {
            int n = i / F, f = i - n * F;
            g_x[i] = emb[x_idx[n] * F + f];
        }
    } else {
        int i = (b - GATHER_BLKS) * 256 + threadIdx.x;
        if (i < N_EDGES) atomicAdd(&g_deg[ei[N_EDGES + i]], 1);
    }
}

__global__ void k_scanA() {
    __shared__ int ss[256];
    __shared__ float ls[256];
    int b = blockIdx.x, tid = threadIdx.x;
    int n = b * 256 + tid;
    int d = (n < N_NODES) ? g_deg[n] : 0;
    ss[tid] = d;
    ls[tid] = (n < N_NODES) ? logf((float)d + 1.f) : 0.f;
    __syncthreads();
    for (int o = 128; o; o >>= 1) {
        if (tid < o) { ss[tid] += ss[tid + o]; ls[tid] += ls[tid + o]; }
        __syncthreads();
    }
    if (tid == 0) { g_part[b] = ss[0]; atomicAdd(&g_logsum, ls[0]); }
}

__global__ void k_scanB() {
    __shared__ int s[128];
    int t = threadIdx.x;
    int own = (t < SCAN_BLKS) ? g_part[t] : 0;
    s[t] = own;
    __syncthreads();
    for (int o = 1; o < 128; o <<= 1) {
        int v = (t >= o) ? s[t - o] : 0;
        __syncthreads();
        s[t] += v;
        __syncthreads();
    }
    if (t < SCAN_BLKS) g_partscan[t] = s[t] - own;
}

__global__ void k_scanC() {
    __shared__ int s[256];
    int b = blockIdx.x, tid = threadIdx.x;
    int n = b * 256 + tid;
    int d = (n < N_NODES) ? g_deg[n] : 0;
    int own = d;
    s[tid] = d;
    __syncthreads();
    for (int o = 1; o < 256; o <<= 1) {
        int v = (tid >= o) ? s[tid - o] : 0;
        __syncthreads();
        s[tid] += v;
        __syncthreads();
    }
    int excl = s[tid] - own + g_partscan[b];
    if (n < N_NODES) {
        g_rowptr[n] = excl;
        g_cursor[n] = excl;
        float avg = g_logsum * (1.f / (float)N_NODES);
        float dc = fmaxf((float)d, 1.f);
        float L = logf(dc + 1.f);
        g_amp[n] = L / avg;
        g_att[n] = avg / L;
        g_invdeg[n] = 1.f / dc;
        if (n == N_NODES - 1) g_rowptr[N_NODES] = excl + d;
    }
    if (n < N_GRAPHS * F) g_pooled[n] = 0.f;
}

__global__ void k_scatter(const int* __restrict__ ei, const int* __restrict__ ea) {
    int i = blockIdx.x * 256 + threadIdx.x;
    if (i < N_EDGES) {
        int dst = ei[N_EDGES + i];
        int pos = atomicAdd(&g_cursor[dst], 1);
        g_col[pos] = make_int2(ei[i], ea[i]);
    }
    if (i < N_NODES) g_deg[i] = 0;     // reset for next invocation
    if (i == 0) g_logsum = 0.f;
}

// ---------------- per-layer: et table + Mfold + bn zero ----------------
__global__ void k_et_fold(const float* __restrict__ edge_emb, const float* __restrict__ W_edge,
                          const float* __restrict__ b_edge, const float* __restrict__ W_pre,
                          const float* __restrict__ b_pre, const float* __restrict__ W_post,
                          const float* __restrict__ b_post, const float* __restrict__ W_lin,
                          const float* __restrict__ b_lin, int l) {
    int a = blockIdx.x, t = threadIdx.x;
    if (a < N_ATTR) {
        __shared__ float e75[F];
        if (t < F) {
            float acc = b_edge[l * F + t];
            for (int d = 0; d < EDGE_DIM; d++)
                acc += edge_emb[a * EDGE_DIM + d] * W_edge[(l * EDGE_DIM + d) * F + t];
            e75[t] = acc;
        }
        __syncthreads();
        if (t < TF) {
            int tw = t / F, f = t - tw * F;
            float acc = b_pre[(l * TOWERS + tw) * F + f];
            const float* Wp = W_pre + ((size_t)((l * TOWERS + tw) * 225 + 150)) * F + f;
            for (int c = 0; c < F; c++) acc += e75[c] * Wp[c * F];
            g_et[a * ROW + t] = acc;
        }
    } else {
        for (int i = t; i < F * F; i += 384) {
            int c = i / F, o = i - c * F;
            float acc = 0.f;
            for (int tf = 0; tf < F; tf++) {
                int tw = tf / FOUT, f = tf - tw * FOUT;
                acc += W_post[((size_t)((l * TOWERS + tw) * 975 + c)) * FOUT + f] *
                       W_lin[(l * F + tf) * F + o];
            }
            g_Mfold[i] = acc;
        }
        if (t < F) {
            float bf = b_lin[l * F + t];
            for (int tf = 0; tf < F; tf++) {
                int tw = tf / FOUT, f = tf - tw * FOUT;
                bf += b_post[(l * TOWERS + tw) * FOUT + f] * W_lin[(l * F + tf) * F + t];
            }
            g_bfold[t] = bf;
            g_bnsum[t] = 0.f;
            g_bnsq[t] = 0.f;
        }
    }
}

// ---------------- xd|xs GEMM: per (part,tower): [N,75]@[75,75] ----------------
// B tile: per-thread 12-float stride, cols j -> slot (j/10)*12 + j%10.
// Thread tx reads floats [tx*12, tx*12+9]: 2x LDS.128 + 1x LDS.64, conflict-free.
__global__ __launch_bounds__(256, 3) void k_xds(const float* __restrict__ W_pre, int l) {
    __shared__ __align__(16) float As[128][25];
    __shared__ __align__(16) float Bs[25][96];
    int c = blockIdx.x;
    int n0 = blockIdx.y * 128;
    int part = c / 5, tw = c - part * 5;
    int tid = threadIdx.x;
    int ty = tid >> 3, tx = tid & 7;
    const float* Wbase = W_pre + (size_t)((l * TOWERS + tw) * 225 + part * F) * F;
    u64 acc[4][5];
#pragma unroll
    for (int i = 0; i < 4; i++)
#pragma unroll
        for (int j = 0; j < 5; j++) acc[i][j] = 0ULL;
    for (int kc = 0; kc < F; kc += 25) {
        for (int idx = tid; idx < 128 * 25; idx += 256) {
            int r = idx / 25, kk = idx - r * 25;
            int n = n0 + r;
            As[r][kk] = (n < N_NODES) ? g_x[n * F + kc + kk] : 0.f;
        }
        for (int idx = tid; idx < 25 * 80; idx += 256) {
            int kk = idx / 80, j = idx - kk * 80;
            int slot = (j / 10) * 12 + (j % 10);
            Bs[kk][slot] = (j < F) ? Wbase[(kc + kk) * F + j] : 0.f;
        }
        __syncthreads();
#pragma unroll 5
        for (int kk = 0; kk < 25; kk++) {
            float4 bA = *(const float4*)&Bs[kk][tx * 12];
            float4 bB = *(const float4*)&Bs[kk][tx * 12 + 4];
            u64 b4 = *(const u64*)&Bs[kk][tx * 12 + 8];
            u64 b2[5];
            b2[0] = f2pk(bA.x, bA.y);
            b2[1] = f2pk(bA.z, bA.w);
            b2[2] = f2pk(bB.x, bB.y);
            b2[3] = f2pk(bB.z, bB.w);
            b2[4] = b4;
#pragma unroll
            for (int i = 0; i < 4; i++) {
                u64 a2 = f2bcast(As[ty + 32 * i][kk]);
#pragma unroll
                for (int j = 0; j < 5; j++) acc[i][j] = ffma2(a2, b2[j], acc[i][j]);
            }
        }
        __syncthreads();
    }
    float* dst = part ? g_xs : g_xd;
#pragma unroll
    for (int i = 0; i < 4; i++) {
        int n = n0 + ty + 32 * i;
        if (n >= N_NODES) continue;
        float* row = dst + (size_t)n * ROW + tw * F;
#pragma unroll
        for (int j = 0; j < 5; j++) {
            int jc = tx * 10 + 2 * j;
            float lo, hi;
            f2up(acc[i][j], lo, hi);
            if (jc < F) row[jc] = lo;
            if (jc + 1 < F) row[jc + 1] = hi;
        }
    }
}

// ---------------- aggregation: one warp per dst node ----------------
__global__ void k_aggr() {
    int warp = (blockIdx.x * blockDim.x + threadIdx.x) >> 5;
    int lane = threadIdx.x & 31;
    if (warp >= N_NODES) return;
    int n = warp;
    u64 sum2[6], sq2[6];
    float mn[12], mx[12];
#pragma unroll
    for (int q = 0; q < 6; q++) { sum2[q] = 0ULL; sq2[q] = 0ULL; }
#pragma unroll
    for (int j = 0; j < 12; j++) { mn[j] = INFINITY; mx[j] = -INFINITY; }
    int e0 = g_rowptr[n], e1 = g_rowptr[n + 1];
#pragma unroll 2
    for (int e = e0; e < e1; e++) {
        int2 sa = g_col[e];
        const float4* xs4 = (const float4*)(g_xs + (size_t)sa.x * ROW);
        const float4* et4 = (const float4*)(g_et + sa.y * ROW);
#pragma unroll
        for (int q = 0; q < 3; q++) {
            float4 xv = xs4[lane * 3 + q];
            float4 ev = et4[lane * 3 + q];
            u64 v0 = fadd2(f2pk(xv.x, xv.y), f2pk(ev.x, ev.y));
            u64 v1 = fadd2(f2pk(xv.z, xv.w), f2pk(ev.z, ev.w));
            sum2[2 * q] = fadd2(sum2[2 * q], v0);
            sum2[2 * q + 1] = fadd2(sum2[2 * q + 1], v1);
            sq2[2 * q] = ffma2(v0, v0, sq2[2 * q]);
            sq2[2 * q + 1] = ffma2(v1, v1, sq2[2 * q + 1]);
            float a0, a1, a2, a3;
            f2up(v0, a0, a1);
            f2up(v1, a2, a3);
            int j = q * 4;
            mn[j] = fminf(mn[j], a0); mx[j] = fmaxf(mx[j], a0);
            mn[j + 1] = fminf(mn[j + 1], a1); mx[j + 1] = fmaxf(mx[j + 1], a1);
            mn[j + 2] = fminf(mn[j + 2], a2); mx[j + 2] = fmaxf(mx[j + 2], a2);
            mn[j + 3] = fminf(mn[j + 3], a3); mx[j + 3] = fmaxf(mx[j + 3], a3);
        }
    }
    float inv = g_invdeg[n];
    bool has = e1 > e0;
    const float4* xdrow = (const float4*)(g_xd + (size_t)n * ROW);
#pragma unroll
    for (int q = 0; q < 3; q++) {
        float4 xv = xdrow[lane * 3 + q];
        float xd4[4] = {xv.x, xv.y, xv.z, xv.w};
#pragma unroll
        for (int h4 = 0; h4 < 4; h4++) {
            int j = q * 4 + h4;
            int f = lane * 12 + j;
            if (f >= TF) continue;
            float sm, sqv;
            {
                float lo, hi;
                f2up(sum2[j >> 1], lo, hi);
                sm = (j & 1) ? hi : lo;
                f2up(sq2[j >> 1], lo, hi);
                sqv = (j & 1) ? hi : lo;
            }
            float xd = xd4[h4];
            float meanw = sm * inv;
            float var = sqv * inv - meanw * meanw;
            float sd = sqrtf(fmaxf(var, 0.f) + 1e-5f);
            float mean = has ? (meanw + xd) : 0.f;
            float mnv = has ? (mn[j] + xd) : 0.f;
            float mxv = has ? (mx[j] + xd) : 0.f;
            int tw = f / F, jj = f - tw * F;
            float* outp = g_aggr + (size_t)n * 1500 + tw * 300 + jj;
            outp[0] = mean;
            outp[75] = mnv;
            outp[150] = mxv;
            outp[225] = sd;
        }
    }
}

// ---------------- S GEMM + scaler combine ----------------
// per tower: [N,300]@[300,48pad]. block 256 nodes. 256 thr: ty=tid>>2 (64), tx=tid&3.
// thread: 4 nodes (ty+64i) x 6 pairs = {g0,g1,g2} x {2tx,2tx+1}; B via 3x LDS.128.
__global__ __launch_bounds__(256, 3) void k_gemmS(const float* __restrict__ W_post, int l) {
    __shared__ __align__(16) float As[256][25];
    __shared__ __align__(16) float Bs[25][48];
    int t = blockIdx.y;
    int n0 = blockIdx.x * 256;
    int tid = threadIdx.x;
    int ty = tid >> 2, tx = tid & 3;
    const float* Wb = W_post + (size_t)((l * TOWERS + t) * 975 + 75) * FOUT;
    u64 acc[4][6];
#pragma unroll
    for (int i = 0; i < 4; i++)
#pragma unroll
        for (int g = 0; g < 6; g++) acc[i][g] = 0ULL;
    for (int kc = 0; kc < 300; kc += 25) {
        for (int idx = tid; idx < 256 * 25; idx += 256) {
            int r = idx / 25, kk = idx - r * 25;
            int n = n0 + r;
            As[r][kk] = (n < N_NODES) ? g_aggr[(size_t)n * 1500 + t * 300 + kc + kk] : 0.f;
        }
        for (int idx = tid; idx < 25 * 48; idx += 256) {
            int kk = idx / 48, j = idx - kk * 48;
            int g = j >> 4, f = j & 15;
            Bs[kk][j] = (f < FOUT)
                ? Wb[(size_t)(g * 300 + kc + kk) * FOUT + f]
                : 0.f;
        }
        __syncthreads();
#pragma unroll 5
        for (int kk = 0; kk < 25; kk++) {
            float4 b0 = *(const float4*)&Bs[kk][4 * tx];
            float4 b1 = *(const float4*)&Bs[kk][16 + 4 * tx];
            float4 b2v = *(const float4*)&Bs[kk][32 + 4 * tx];
            u64 bb[6];
            bb[0] = f2pk(b0.x, b0.y);
            bb[1] = f2pk(b0.z, b0.w);
            bb[2] = f2pk(b1.x, b1.y);
            bb[3] = f2pk(b1.z, b1.w);
            bb[4] = f2pk(b2v.x, b2v.y);
            bb[5] = f2pk(b2v.z, b2v.w);
#pragma unroll
            for (int i = 0; i < 4; i++) {
                u64 a2 = f2bcast(As[ty + 64 * i][kk]);
#pragma unroll
                for (int g = 0; g < 6; g++) acc[i][g] = ffma2(a2, bb[g], acc[i][g]);
            }
        }
        __syncthreads();
    }
#pragma unroll
    for (int i = 0; i < 4; i++) {
        int n = n0 + ty + 64 * i;
        if (n >= N_NODES) continue;
        float amp = g_amp[n], att = g_att[n];
        float g0[4], g1[4], g2[4];
        f2up(acc[i][0], g0[0], g0[1]); f2up(acc[i][1], g0[2], g0[3]);
        f2up(acc[i][2], g1[0], g1[1]); f2up(acc[i][3], g1[2], g1[3]);
        f2up(acc[i][4], g2[0], g2[1]); f2up(acc[i][5], g2[2], g2[3]);
        float* row = g_S + n * F + t * FOUT;
#pragma unroll
        for (int cidx = 0; cidx < 4; cidx++) {
            int f = 4 * tx + cidx;
            if (f < FOUT) row[f] = g0[cidx] + amp * g1[cidx] + att * g2[cidx];
        }
    }
}

// ---------------- post+lin GEMM (K=150) + BN reduce ----------------
__global__ __launch_bounds__(256, 3) void k_gemm2(const float* __restrict__ W_lin, int l) {
    __shared__ __align__(16) float As[128][25];
    __shared__ __align__(16) float Bs[25][96];
    __shared__ float red[32][80];
    int n0 = blockIdx.x * 128;
    int tid = threadIdx.x;
    int ty = tid >> 3, tx = tid & 7;
    u64 acc[4][5];
#pragma unroll
    for (int i = 0; i < 4; i++)
#pragma unroll
        for (int j = 0; j < 5; j++) acc[i][j] = 0ULL;
    for (int kc = 0; kc < 150; kc += 25) {
        for (int idx = tid; idx < 128 * 25; idx += 256) {
            int r = idx / 25, kk = idx - r * 25;
            int n = n0 + r;
            int k = kc + kk;
            float v = 0.f;
            if (n < N_NODES) v = (k < F) ? g_x[n * F + k] : g_S[n * F + (k - F)];
            As[r][kk] = v;
        }
        for (int idx = tid; idx < 25 * 80; idx += 256) {
            int kk = idx / 80, j = idx - kk * 80;
            int k = kc + kk;
            int slot = (j / 10) * 12 + (j % 10);
            float v = 0.f;
            if (j < F) v = (k < F) ? g_Mfold[k * F + j] : W_lin[(l * F + (k - F)) * F + j];
            Bs[kk][slot] = v;
        }
        __syncthreads();
#pragma unroll 5
        for (int kk = 0; kk < 25; kk++) {
            float4 bA = *(const float4*)&Bs[kk][tx * 12];
            float4 bB = *(const float4*)&Bs[kk][tx * 12 + 4];
            u64 b4 = *(const u64*)&Bs[kk][tx * 12 + 8];
            u64 b2[5];
            b2[0] = f2pk(bA.x, bA.y);
            b2[1] = f2pk(bA.z, bA.w);
            b2[2] = f2pk(bB.x, bB.y);
            b2[3] = f2pk(bB.z, bB.w);
            b2[4] = b4;
#pragma unroll
            for (int i = 0; i < 4; i++) {
                u64 a2 = f2bcast(As[ty + 32 * i][kk]);
#pragma unroll
                for (int j = 0; j < 5; j++) acc[i][j] = ffma2(a2, b2[j], acc[i][j]);
            }
        }
        __syncthreads();
    }
    float s[10], q[10];
#pragma unroll
    for (int j = 0; j < 10; j++) { s[j] = 0.f; q[j] = 0.f; }
#pragma unroll
    for (int i = 0; i < 4; i++) {
        int n = n0 + ty + 32 * i;
        if (n >= N_NODES) continue;
#pragma unroll
        for (int j = 0; j < 5; j++) {
            int jc = tx * 10 + 2 * j;
            float lo, hi;
            f2up(acc[i][j], lo, hi);
            if (jc < F) {
                float v = lo + g_bfold[jc];
                g_y[n * F + jc] = v;
                s[2 * j] += v; q[2 * j] += v * v;
            }
            if (jc + 1 < F) {
                float v = hi + g_bfold[jc + 1];
                g_y[n * F + jc + 1] = v;
                s[2 * j + 1] += v; q[2 * j + 1] += v * v;
            }
        }
    }
#pragma unroll
    for (int j = 0; j < 10; j++) red[ty][tx * 10 + j] = s[j];
    __syncthreads();
    if (tid < F) {
        float tot = 0.f;
        for (int yy = 0; yy < 32; yy++) tot += red[yy][tid];
        atomicAdd(&g_bnsum[tid], tot);
    }
    __syncthreads();
#pragma unroll
    for (int j = 0; j < 10; j++) red[ty][tx * 10 + j] = q[j];
    __syncthreads();
    if (tid < F) {
        float tot = 0.f;
        for (int yy = 0; yy < 32; yy++) tot += red[yy][tid];
        atomicAdd(&g_bnsq[tid], tot);
    }
}

// ---------------- BN finalize + apply + ReLU (+ pool on last layer) ------
__global__ void k_bnapply(const float* __restrict__ gamma, const float* __restrict__ beta,
                          const int* __restrict__ batch, int l, int do_pool) {
    __shared__ float sc[F], sh[F];
    int tid = threadIdx.x;
    if (tid < F) {
        float mu = g_bnsum[tid] * (1.f / (float)N_NODES);
        float var = g_bnsq[tid] * (1.f / (float)N_NODES) - mu * mu;
        float r = rsqrtf(var + 1e-5f);
        float s = r * gamma[l * F + tid];
        sc[tid] = s;
        sh[tid] = beta[l * F + tid] - mu * s;
    }
    __syncthreads();
    int base = blockIdx.x * 2048;
#pragma unroll
    for (int o = 0; o < 2048; o += 256) {
        int i = base + o + tid;
        if (i < N_NODES * F) {
            int n = i / F, c = i - n * F;
            float v = fmaxf(g_y[i] * sc[c] + sh[c], 0.f);
            g_x[i] = v;
            if (do_pool) atomicAdd(&g_pooled[batch[n] * F + c], v);
        }
    }
}

// ---------------- final MLP ----------------
__global__ void k_mlp(const float* __restrict__ W1, const float* __restrict__ b1,
                      const float* __restrict__ W2, const float* __restrict__ b2,
                      const float* __restrict__ W3, const float* __restrict__ b3,
                      float* __restrict__ out) {
    __shared__ float w1[75 * 50], w2[50 * 25], w3[25];
    int t = threadIdx.x;
    for (int i = t; i < 75 * 50; i += 256) w1[i] = W1[i];
    for (int i = t; i < 50 * 25; i += 256) w2[i] = W2[i];
    if (t < 25) w3[t] = W3[t];
    __syncthreads();
    if (t >= N_GRAPHS) return;
    const float* p = g_pooled + t * F;
    float h1[50];
    for (int j = 0; j < 50; j++) {
        float a = b1[j];
        for (int c = 0; c < F; c++) a += p[c] * w1[c * 50 + j];
        h1[j] = fmaxf(a, 0.f);
    }
    float h2[25];
    for (int j = 0; j < 25; j++) {
        float a = b2[j];
        for (int c = 0; c < 50; c++) a += h1[c] * w2[c * 25 + j];
        h2[j] = fmaxf(a, 0.f);
    }
    float o = b3[0];
    for (int c = 0; c < 25; c++) o += h2[c] * w3[c];
    out[t] = o;
}

// ---------------- launch ----------------
extern "C" void kernel_launch(void* const* d_in, const int* in_sizes, int n_in,
                              void* d_out, int out_size) {
    const int* x_idx = (const int*)d_in[0];
    const int* edge_index = (const int*)d_in[1];
    const int* eattr = (const int*)d_in[2];
    const int* batch = (const int*)d_in[3];
    const float* node_emb = (const float*)d_in[4];
    const float* edge_emb = (const float*)d_in[5];
    const float* W_edge = (const float*)d_in[6];
    const float* b_edge = (const float*)d_in[7];
    const float* W_pre = (const float*)d_in[8];
    const float* b_pre = (const float*)d_in[9];
    const float* W_post = (const float*)d_in[10];
    const float* b_post = (const float*)d_in[11];
    const float* W_lin = (const float*)d_in[12];
    const float* b_lin = (const float*)d_in[13];
    const float* gamma = (const float*)d_in[14];
    const float* beta = (const float*)d_in[15];
    const float* W1 = (const float*)d_in[16];
    const float* b1 = (const float*)d_in[17];
    const float* W2 = (const float*)d_in[18];
    const float* b2 = (const float*)d_in[19];
    const float* W3 = (const float*)d_in[20];
    const float* b3 = (const float*)d_in[21];
    float* out = (float*)d_out;

    dim3 gx(10, (N_NODES + 127) / 128);

    k_gather_count<<<GATHER_BLKS + COUNT_BLKS, 256>>>(x_idx, node_emb, edge_index); // 1
    k_scanA<<<SCAN_BLKS, 256>>>();                                                  // 2
    k_scanB<<<1, 128>>>();                                                          // 3
    k_xds<<<gx, 256>>>(W_pre, 0);                                                   // 4  <- ncu target
    k_scanC<<<SCAN_BLKS, 256>>>();                                                  // 5
    k_scatter<<<COUNT_BLKS, 256>>>(edge_index, eattr);                              // 6
    k_et_fold<<<N_ATTR + 1, 384>>>(edge_emb, W_edge, b_edge, W_pre, b_pre,
                                   W_post, b_post, W_lin, b_lin, 0);                // 7

    for (int l = 0; l < 2; l++) {
        if (l == 1) {
            k_xds<<<gx, 256>>>(W_pre, 1);
            k_et_fold<<<N_ATTR + 1, 384>>>(edge_emb, W_edge, b_edge, W_pre, b_pre,
                                           W_post, b_post, W_lin, b_lin, 1);
        }
        k_aggr<<<(N_NODES * 32 + 255) / 256, 256>>>();
        {
            dim3 grid((N_NODES + 255) / 256, TOWERS);
            k_gemmS<<<grid, 256>>>(W_post, l);
        }
        k_gemm2<<<(N_NODES + 127) / 128, 256>>>(W_lin, l);
        k_bnapply<<<(N_NODES * F + 2047) / 2048, 256>>>(gamma, beta, batch, l, l == 1);
    }

    k_mlp<<<1, 256>>>(W1, b1, W2, b2, W3, b3, out);
}

// round 11
// speedup vs baseline: 1.2671x; 1.0769x over previous
#include <cuda_runtime.h>
#include <cuda_bf16.h>
#include <math.h>

#define N_NODES 20000
#define N_EDGES 320000
#define N_GRAPHS 200
#define TOWERS 5
#define F 75
#define TF 375
#define EDGE_DIM 50
#define N_ATTR 100
#define FOUT 15
#define ROW 384

// ---------------- static scratch (zero-initialized; pads never written) ----
__device__ float g_x[N_NODES * F];
__device__ float g_y[N_NODES * F];
__device__ float g_xd[(size_t)N_NODES * ROW];
__device__ float g_xs[(size_t)N_NODES * ROW];
__device__ float g_aggr[(size_t)N_NODES * 1500];
__device__ float g_S[N_NODES * F];
__device__ float g_et[N_ATTR * ROW];
__device__ float g_Mfold[F * F];
__device__ float g_bfold[F];
__device__ int   g_deg[N_NODES];
__device__ int   g_rowptr[N_NODES + 1];
__device__ int   g_cursor[N_NODES];
__device__ int2  g_col[N_EDGES];           // (src, attr)
__device__ float g_amp[N_NODES], g_att[N_NODES], g_invdeg[N_NODES];
__device__ float g_logsum;
__device__ int   g_part[128];
__device__ int   g_partscan[128];
__device__ float g_bnsum[F], g_bnsq[F];
__device__ float g_pooled[N_GRAPHS * F];

// ---------------- f32x2 helpers ----------------
typedef unsigned long long u64;
__device__ __forceinline__ u64 f2bcast(float a) {
    u64 r;
    asm("mov.b64 %0, {%1, %1};" : "=l"(r) : "f"(a));
    return r;
}
__device__ __forceinline__ u64 f2pk(float lo, float hi) {
    u64 r;
    asm("mov.b64 %0, {%1, %2};" : "=l"(r) : "f"(lo), "f"(hi));
    return r;
}
__device__ __forceinline__ void f2up(u64 v, float& lo, float& hi) {
    asm("mov.b64 {%0, %1}, %2;" : "=f"(lo), "=f"(hi) : "l"(v));
}
__device__ __forceinline__ u64 ffma2(u64 a, u64 b, u64 c) {
    u64 d;
    asm("fma.rn.f32x2 %0, %1, %2, %3;" : "=l"(d) : "l"(a), "l"(b), "l"(c));
    return d;
}
__device__ __forceinline__ u64 fadd2(u64 a, u64 b) {
    u64 d;
    asm("add.rn.f32x2 %0, %1, %2;" : "=l"(d) : "l"(a), "l"(b));
    return d;
}

// ---------------- tf32 helpers ----------------
__device__ __forceinline__ unsigned tf32_hi(float v) {
    unsigned u;
    asm("cvt.rna.tf32.f32 %0, %1;" : "=r"(u) : "f"(v));
    return u;
}

#define MMA_TF32(c, a, b0, b1) \
    asm volatile("mma.sync.aligned.m16n8k8.row.col.f32.tf32.tf32.f32 " \
        "{%0,%1,%2,%3}, {%4,%5,%6,%7}, {%8,%9}, {%0,%1,%2,%3};" \
        : "+f"((c)[0]), "+f"((c)[1]), "+f"((c)[2]), "+f"((c)[3]) \
        : "r"((a)[0]), "r"((a)[1]), "r"((a)[2]), "r"((a)[3]), "r"(b0), "r"(b1))

// ---------------- preprocessing ----------------
#define GATHER_BLKS ((N_NODES * F + 255) / 256)
#define COUNT_BLKS ((N_EDGES + 255) / 256)
#define SCAN_BLKS ((N_NODES + 255) / 256)

__global__ void k_gather_count(const int* __restrict__ x_idx, const float* __restrict__ emb,
                               const int* __restrict__ ei) {
    int b = blockIdx.x;
    if (b < GATHER_BLKS) {
        int i = b * 256 + threadIdx.x;
        if (i < N_NODES * F) {
            int n = i / F, f = i - n * F;
            g_x[i] = emb[x_idx[n] * F + f];
        }
    } else {
        int i = (b - GATHER_BLKS) * 256 + threadIdx.x;
        if (i < N_EDGES) atomicAdd(&g_deg[ei[N_EDGES + i]], 1);
    }
}

__global__ void k_scanA() {
    __shared__ int ss[256];
    __shared__ float ls[256];
    int b = blockIdx.x, tid = threadIdx.x;
    int n = b * 256 + tid;
    int d = (n < N_NODES) ? g_deg[n] : 0;
    ss[tid] = d;
    ls[tid] = (n < N_NODES) ? logf((float)d + 1.f) : 0.f;
    __syncthreads();
    for (int o = 128; o; o >>= 1) {
        if (tid < o) { ss[tid] += ss[tid + o]; ls[tid] += ls[tid + o]; }
        __syncthreads();
    }
    if (tid == 0) { g_part[b] = ss[0]; atomicAdd(&g_logsum, ls[0]); }
}

__global__ void k_scanB() {
    __shared__ int s[128];
    int t = threadIdx.x;
    int own = (t < SCAN_BLKS) ? g_part[t] : 0;
    s[t] = own;
    __syncthreads();
    for (int o = 1; o < 128; o <<= 1) {
        int v = (t >= o) ? s[t - o] : 0;
        __syncthreads();
        s[t] += v;
        __syncthreads();
    }
    if (t < SCAN_BLKS) g_partscan[t] = s[t] - own;
}

__global__ void k_scanC() {
    __shared__ int s[256];
    int b = blockIdx.x, tid = threadIdx.x;
    int n = b * 256 + tid;
    int d = (n < N_NODES) ? g_deg[n] : 0;
    int own = d;
    s[tid] = d;
    __syncthreads();
    for (int o = 1; o < 256; o <<= 1) {
        int v = (tid >= o) ? s[tid - o] : 0;
        __syncthreads();
        s[tid] += v;
        __syncthreads();
    }
    int excl = s[tid] - own + g_partscan[b];
    if (n < N_NODES) {
        g_rowptr[n] = excl;
        g_cursor[n] = excl;
        float avg = g_logsum * (1.f / (float)N_NODES);
        float dc = fmaxf((float)d, 1.f);
        float L = logf(dc + 1.f);
        g_amp[n] = L / avg;
        g_att[n] = avg / L;
        g_invdeg[n] = 1.f / dc;
        if (n == N_NODES - 1) g_rowptr[N_NODES] = excl + d;
    }
    if (n < N_GRAPHS * F) g_pooled[n] = 0.f;
}

__global__ void k_scatter(const int* __restrict__ ei, const int* __restrict__ ea) {
    int i = blockIdx.x * 256 + threadIdx.x;
    if (i < N_EDGES) {
        int dst = ei[N_EDGES + i];
        int pos = atomicAdd(&g_cursor[dst], 1);
        g_col[pos] = make_int2(ei[i], ea[i]);
    }
    if (i < N_NODES) g_deg[i] = 0;     // reset for next invocation
    if (i == 0) g_logsum = 0.f;
}

// ---------------- per-layer: et table + Mfold + bn zero ----------------
__global__ void k_et_fold(const float* __restrict__ edge_emb, const float* __restrict__ W_edge,
                          const float* __restrict__ b_edge, const float* __restrict__ W_pre,
                          const float* __restrict__ b_pre, const float* __restrict__ W_post,
                          const float* __restrict__ b_post, const float* __restrict__ W_lin,
                          const float* __restrict__ b_lin, int l) {
    int a = blockIdx.x, t = threadIdx.x;
    if (a < N_ATTR) {
        __shared__ float e75[F];
        if (t < F) {
            float acc = b_edge[l * F + t];
            for (int d = 0; d < EDGE_DIM; d++)
                acc += edge_emb[a * EDGE_DIM + d] * W_edge[(l * EDGE_DIM + d) * F + t];
            e75[t] = acc;
        }
        __syncthreads();
        if (t < TF) {
            int tw = t / F, f = t - tw * F;
            float acc = b_pre[(l * TOWERS + tw) * F + f];
            const float* Wp = W_pre + ((size_t)((l * TOWERS + tw) * 225 + 150)) * F + f;
            for (int c = 0; c < F; c++) acc += e75[c] * Wp[c * F];
            g_et[a * ROW + t] = acc;
        }
    } else {
        for (int i = t; i < F * F; i += 384) {
            int c = i / F, o = i - c * F;
            float acc = 0.f;
            for (int tf = 0; tf < F; tf++) {
                int tw = tf / FOUT, f = tf - tw * FOUT;
                acc += W_post[((size_t)((l * TOWERS + tw) * 975 + c)) * FOUT + f] *
                       W_lin[(l * F + tf) * F + o];
            }
            g_Mfold[i] = acc;
        }
        if (t < F) {
            float bf = b_lin[l * F + t];
            for (int tf = 0; tf < F; tf++) {
                int tw = tf / FOUT, f = tf - tw * FOUT;
                bf += b_post[(l * TOWERS + tw) * FOUT + f] * W_lin[(l * F + tf) * F + t];
            }
            g_bfold[t] = bf;
            g_bnsum[t] = 0.f;
            g_bnsq[t] = 0.f;
        }
    }
}

// ---------------- xd|xs GEMM via tf32 mma.sync, hi/lo split ----------------
// per (part,tower) piece: [128 nodes x 80 cols], K=75 pad 80, chunked by 16.
// 8 warps: 4(m) x 2(n); warp tile 32 rows x 40 cols = 2 m16 x 5 n8 tiles.
// D = Ahi*Bhi + Ahi*Blo + Alo*Bhi  (fp32-grade accuracy).
__global__ __launch_bounds__(256, 2) void k_xds(const float* __restrict__ W_pre, int l) {
    __shared__ __align__(16) float Ah[128][20], Al[128][20];
    __shared__ __align__(16) float Bh[16][88], Bl[16][88];
    int piece = blockIdx.x;
    int n0 = blockIdx.y * 128;
    int part = piece / 5, tw = piece - part * 5;
    const float* Wbase = W_pre + (size_t)((l * TOWERS + tw) * 225 + part * F) * F;
    int tid = threadIdx.x, lane = tid & 31, wid = tid >> 5;
    int wm = wid >> 1, wn = wid & 1;
    float c[2][5][4];
#pragma unroll
    for (int t = 0; t < 2; t++)
#pragma unroll
        for (int s5 = 0; s5 < 5; s5++)
#pragma unroll
            for (int e = 0; e < 4; e++) c[t][s5][e] = 0.f;

    for (int kc = 0; kc < 80; kc += 16) {
        // A fill: 128 rows x 16 k
#pragma unroll
        for (int s = 0; s < 8; s++) {
            int idx = tid + s * 256;
            int r = idx >> 4, k = idx & 15;
            int gk = kc + k;
            int n = n0 + r;
            float v = (n < N_NODES && gk < F) ? g_x[n * F + gk] : 0.f;
            unsigned hu = tf32_hi(v);
            float hf = __uint_as_float(hu);
            float rs = v - hf;
            unsigned lu = tf32_hi(rs);
            Ah[r][k] = hf;
            Al[r][k] = __uint_as_float(lu);
        }
        // B fill: 16 k x 80 n
#pragma unroll
        for (int s = 0; s < 5; s++) {
            int idx = tid + s * 256;
            int k = idx / 80, j = idx - k * 80;
            int gk = kc + k;
            float v = (gk < F && j < F) ? Wbase[gk * F + j] : 0.f;
            unsigned hu = tf32_hi(v);
            float hf = __uint_as_float(hu);
            float rs = v - hf;
            unsigned lu = tf32_hi(rs);
            Bh[k][j] = hf;
            Bl[k][j] = __uint_as_float(lu);
        }
        __syncthreads();
#pragma unroll
        for (int k8 = 0; k8 < 16; k8 += 8) {
            unsigned ah[2][4], al[2][4];
            int ar = lane >> 2;
            int ak = k8 + (lane & 3);
#pragma unroll
            for (int t = 0; t < 2; t++) {
                int r = wm * 32 + t * 16 + ar;
                ah[t][0] = __float_as_uint(Ah[r][ak]);
                ah[t][1] = __float_as_uint(Ah[r + 8][ak]);
                ah[t][2] = __float_as_uint(Ah[r][ak + 4]);
                ah[t][3] = __float_as_uint(Ah[r + 8][ak + 4]);
                al[t][0] = __float_as_uint(Al[r][ak]);
                al[t][1] = __float_as_uint(Al[r + 8][ak]);
                al[t][2] = __float_as_uint(Al[r][ak + 4]);
                al[t][3] = __float_as_uint(Al[r + 8][ak + 4]);
            }
#pragma unroll
            for (int s5 = 0; s5 < 5; s5++) {
                int n = wn * 40 + s5 * 8 + (lane >> 2);
                int bk = k8 + (lane & 3);
                unsigned bh0 = __float_as_uint(Bh[bk][n]);
                unsigned bh1 = __float_as_uint(Bh[bk + 4][n]);
                unsigned bl0 = __float_as_uint(Bl[bk][n]);
                unsigned bl1 = __float_as_uint(Bl[bk + 4][n]);
#pragma unroll
                for (int t = 0; t < 2; t++) {
                    MMA_TF32(c[t][s5], ah[t], bh0, bh1);
                    MMA_TF32(c[t][s5], ah[t], bl0, bl1);
                    MMA_TF32(c[t][s5], al[t], bh0, bh1);
                }
            }
        }
        __syncthreads();
    }
    float* dst = part ? g_xs : g_xd;
#pragma unroll
    for (int t = 0; t < 2; t++) {
        int r0 = n0 + wm * 32 + t * 16 + (lane >> 2);
#pragma unroll
        for (int s5 = 0; s5 < 5; s5++) {
            int gc = wn * 40 + s5 * 8 + 2 * (lane & 3);
#pragma unroll
            for (int h = 0; h < 2; h++) {
                int rr = r0 + h * 8;
                if (rr >= N_NODES) continue;
                float* row = dst + (size_t)rr * ROW + tw * F;
                if (gc < F) row[gc] = c[t][s5][h * 2 + 0];
                if (gc + 1 < F) row[gc + 1] = c[t][s5][h * 2 + 1];
            }
        }
    }
}

// ---------------- aggregation: one warp per dst node ----------------
__global__ void k_aggr() {
    int warp = (blockIdx.x * blockDim.x + threadIdx.x) >> 5;
    int lane = threadIdx.x & 31;
    if (warp >= N_NODES) return;
    int n = warp;
    u64 sum2[6], sq2[6];
    float mn[12], mx[12];
#pragma unroll
    for (int q = 0; q < 6; q++) { sum2[q] = 0ULL; sq2[q] = 0ULL; }
#pragma unroll
    for (int j = 0; j < 12; j++) { mn[j] = INFINITY; mx[j] = -INFINITY; }
    int e0 = g_rowptr[n], e1 = g_rowptr[n + 1];
#pragma unroll 2
    for (int e = e0; e < e1; e++) {
        int2 sa = g_col[e];
        const float4* xs4 = (const float4*)(g_xs + (size_t)sa.x * ROW);
        const float4* et4 = (const float4*)(g_et + sa.y * ROW);
#pragma unroll
        for (int q = 0; q < 3; q++) {
            float4 xv = xs4[lane * 3 + q];
            float4 ev = et4[lane * 3 + q];
            u64 v0 = fadd2(f2pk(xv.x, xv.y), f2pk(ev.x, ev.y));
            u64 v1 = fadd2(f2pk(xv.z, xv.w), f2pk(ev.z, ev.w));
            sum2[2 * q] = fadd2(sum2[2 * q], v0);
            sum2[2 * q + 1] = fadd2(sum2[2 * q + 1], v1);
            sq2[2 * q] = ffma2(v0, v0, sq2[2 * q]);
            sq2[2 * q + 1] = ffma2(v1, v1, sq2[2 * q + 1]);
            float a0, a1, a2, a3;
            f2up(v0, a0, a1);
            f2up(v1, a2, a3);
            int j = q * 4;
            mn[j] = fminf(mn[j], a0); mx[j] = fmaxf(mx[j], a0);
            mn[j + 1] = fminf(mn[j + 1], a1); mx[j + 1] = fmaxf(mx[j + 1], a1);
            mn[j + 2] = fminf(mn[j + 2], a2); mx[j + 2] = fmaxf(mx[j + 2], a2);
            mn[j + 3] = fminf(mn[j + 3], a3); mx[j + 3] = fmaxf(mx[j + 3], a3);
        }
    }
    float inv = g_invdeg[n];
    bool has = e1 > e0;
    const float4* xdrow = (const float4*)(g_xd + (size_t)n * ROW);
#pragma unroll
    for (int q = 0; q < 3; q++) {
        float4 xv = xdrow[lane * 3 + q];
        float xd4[4] = {xv.x, xv.y, xv.z, xv.w};
#pragma unroll
        for (int h4 = 0; h4 < 4; h4++) {
            int j = q * 4 + h4;
            int f = lane * 12 + j;
            if (f >= TF) continue;
            float sm, sqv;
            {
                float lo, hi;
                f2up(sum2[j >> 1], lo, hi);
                sm = (j & 1) ? hi : lo;
                f2up(sq2[j >> 1], lo, hi);
                sqv = (j & 1) ? hi : lo;
            }
            float xd = xd4[h4];
            float meanw = sm * inv;
            float var = sqv * inv - meanw * meanw;
            float sd = sqrtf(fmaxf(var, 0.f) + 1e-5f);
            float mean = has ? (meanw + xd) : 0.f;
            float mnv = has ? (mn[j] + xd) : 0.f;
            float mxv = has ? (mx[j] + xd) : 0.f;
            int tw = f / F, jj = f - tw * F;
            float* outp = g_aggr + (size_t)n * 1500 + tw * 300 + jj;
            outp[0] = mean;
            outp[75] = mnv;
            outp[150] = mxv;
            outp[225] = sd;
        }
    }
}

// ---------------- S GEMM + scaler combine ----------------
// per tower: [N,300]@[300,48pad]. block 256 nodes. 256 thr: ty=tid>>2 (64), tx=tid&3.
// thread: 4 nodes (ty+64i) x 6 pairs = {g0,g1,g2} x {2tx,2tx+1}; B via 3x LDS.128.
__global__ __launch_bounds__(256, 3) void k_gemmS(const float* __restrict__ W_post, int l) {
    __shared__ __align__(16) float As[256][25];
    __shared__ __align__(16) float Bs[25][48];
    int t = blockIdx.y;
    int n0 = blockIdx.x * 256;
    int tid = threadIdx.x;
    int ty = tid >> 2, tx = tid & 3;
    const float* Wb = W_post + (size_t)((l * TOWERS + t) * 975 + 75) * FOUT;
    u64 acc[4][6];
#pragma unroll
    for (int i = 0; i < 4; i++)
#pragma unroll
        for (int g = 0; g < 6; g++) acc[i][g] = 0ULL;
    for (int kc = 0; kc < 300; kc += 25) {
        for (int idx = tid; idx < 256 * 25; idx += 256) {
            int r = idx / 25, kk = idx - r * 25;
            int n = n0 + r;
            As[r][kk] = (n < N_NODES) ? g_aggr[(size_t)n * 1500 + t * 300 + kc + kk] : 0.f;
        }
        for (int idx = tid; idx < 25 * 48; idx += 256) {
            int kk = idx / 48, j = idx - kk * 48;
            int g = j >> 4, f = j & 15;
            Bs[kk][j] = (f < FOUT)
                ? Wb[(size_t)(g * 300 + kc + kk) * FOUT + f]
                : 0.f;
        }
        __syncthreads();
#pragma unroll 5
        for (int kk = 0; kk < 25; kk++) {
            float4 b0 = *(const float4*)&Bs[kk][4 * tx];
            float4 b1 = *(const float4*)&Bs[kk][16 + 4 * tx];
            float4 b2v = *(const float4*)&Bs[kk][32 + 4 * tx];
            u64 bb[6];
            bb[0] = f2pk(b0.x, b0.y);
            bb[1] = f2pk(b0.z, b0.w);
            bb[2] = f2pk(b1.x, b1.y);
            bb[3] = f2pk(b1.z, b1.w);
            bb[4] = f2pk(b2v.x, b2v.y);
            bb[5] = f2pk(b2v.z, b2v.w);
#pragma unroll
            for (int i = 0; i < 4; i++) {
                u64 a2 = f2bcast(As[ty + 64 * i][kk]);
#pragma unroll
                for (int g = 0; g < 6; g++) acc[i][g] = ffma2(a2, bb[g], acc[i][g]);
            }
        }
        __syncthreads();
    }
#pragma unroll
    for (int i = 0; i < 4; i++) {
        int n = n0 + ty + 64 * i;
        if (n >= N_NODES) continue;
        float amp = g_amp[n], att = g_att[n];
        float g0[4], g1[4], g2[4];
        f2up(acc[i][0], g0[0], g0[1]); f2up(acc[i][1], g0[2], g0[3]);
        f2up(acc[i][2], g1[0], g1[1]); f2up(acc[i][3], g1[2], g1[3]);
        f2up(acc[i][4], g2[0], g2[1]); f2up(acc[i][5], g2[2], g2[3]);
        float* row = g_S + n * F + t * FOUT;
#pragma unroll
        for (int cidx = 0; cidx < 4; cidx++) {
            int f = 4 * tx + cidx;
            if (f < FOUT) row[f] = g0[cidx] + amp * g1[cidx] + att * g2[cidx];
        }
    }
}

// ---------------- post+lin GEMM (K=150) + BN reduce ----------------
__global__ __launch_bounds__(256, 3) void k_gemm2(const float* __restrict__ W_lin, int l) {
    __shared__ __align__(16) float As[128][25];
    __shared__ __align__(16) float Bs[25][96];
    __shared__ float red[32][80];
    int n0 = blockIdx.x * 128;
    int tid = threadIdx.x;
    int ty = tid >> 3, tx = tid & 7;
    u64 acc[4][5];
#pragma unroll
    for (int i = 0; i < 4; i++)
#pragma unroll
        for (int j = 0; j < 5; j++) acc[i][j] = 0ULL;
    for (int kc = 0; kc < 150; kc += 25) {
        for (int idx = tid; idx < 128 * 25; idx += 256) {
            int r = idx / 25, kk = idx - r * 25;
            int n = n0 + r;
            int k = kc + kk;
            float v = 0.f;
            if (n < N_NODES) v = (k < F) ? g_x[n * F + k] : g_S[n * F + (k - F)];
            As[r][kk] = v;
        }
        for (int idx = tid; idx < 25 * 80; idx += 256) {
            int kk = idx / 80, j = idx - kk * 80;
            int k = kc + kk;
            int slot = (j / 10) * 12 + (j % 10);
            float v = 0.f;
            if (j < F) v = (k < F) ? g_Mfold[k * F + j] : W_lin[(l * F + (k - F)) * F + j];
            Bs[kk][slot] = v;
        }
        __syncthreads();
#pragma unroll 5
        for (int kk = 0; kk < 25; kk++) {
            float4 bA = *(const float4*)&Bs[kk][tx * 12];
            float4 bB = *(const float4*)&Bs[kk][tx * 12 + 4];
            u64 b4 = *(const u64*)&Bs[kk][tx * 12 + 8];
            u64 b2[5];
            b2[0] = f2pk(bA.x, bA.y);
            b2[1] = f2pk(bA.z, bA.w);
            b2[2] = f2pk(bB.x, bB.y);
            b2[3] = f2pk(bB.z, bB.w);
            b2[4] = b4;
#pragma unroll
            for (int i = 0; i < 4; i++) {
                u64 a2 = f2bcast(As[ty + 32 * i][kk]);
#pragma unroll
                for (int j = 0; j < 5; j++) acc[i][j] = ffma2(a2, b2[j], acc[i][j]);
            }
        }
        __syncthreads();
    }
    float s[10], q[10];
#pragma unroll
    for (int j = 0; j < 10; j++) { s[j] = 0.f; q[j] = 0.f; }
#pragma unroll
    for (int i = 0; i < 4; i++) {
        int n = n0 + ty + 32 * i;
        if (n >= N_NODES) continue;
#pragma unroll
        for (int j = 0; j < 5; j++) {
            int jc = tx * 10 + 2 * j;
            float lo, hi;
            f2up(acc[i][j], lo, hi);
            if (jc < F) {
                float v = lo + g_bfold[jc];
                g_y[n * F + jc] = v;
                s[2 * j] += v; q[2 * j] += v * v;
            }
            if (jc + 1 < F) {
                float v = hi + g_bfold[jc + 1];
                g_y[n * F + jc + 1] = v;
                s[2 * j + 1] += v; q[2 * j + 1] += v * v;
            }
        }
    }
#pragma unroll
    for (int j = 0; j < 10; j++) red[ty][tx * 10 + j] = s[j];
    __syncthreads();
    if (tid < F) {
        float tot = 0.f;
        for (int yy = 0; yy < 32; yy++) tot += red[yy][tid];
        atomicAdd(&g_bnsum[tid], tot);
    }
    __syncthreads();
#pragma unroll
    for (int j = 0; j < 10; j++) red[ty][tx * 10 + j] = q[j];
    __syncthreads();
    if (tid < F) {
        float tot = 0.f;
        for (int yy = 0; yy < 32; yy++) tot += red[yy][tid];
        atomicAdd(&g_bnsq[tid], tot);
    }
}

// ---------------- BN finalize + apply + ReLU (+ pool on last layer) ------
__global__ void k_bnapply(const float* __restrict__ gamma, const float* __restrict__ beta,
                          const int* __restrict__ batch, int l, int do_pool) {
    __shared__ float sc[F], sh[F];
    int tid = threadIdx.x;
    if (tid < F) {
        float mu = g_bnsum[tid] * (1.f / (float)N_NODES);
        float var = g_bnsq[tid] * (1.f / (float)N_NODES) - mu * mu;
        float r = rsqrtf(var + 1e-5f);
        float s = r * gamma[l * F + tid];
        sc[tid] = s;
        sh[tid] = beta[l * F + tid] - mu * s;
    }
    __syncthreads();
    int base = blockIdx.x * 2048;
#pragma unroll
    for (int o = 0; o < 2048; o += 256) {
        int i = base + o + tid;
        if (i < N_NODES * F) {
            int n = i / F, c = i - n * F;
            float v = fmaxf(g_y[i] * sc[c] + sh[c], 0.f);
            g_x[i] = v;
            if (do_pool) atomicAdd(&g_pooled[batch[n] * F + c], v);
        }
    }
}

// ---------------- final MLP ----------------
__global__ void k_mlp(const float* __restrict__ W1, const float* __restrict__ b1,
                      const float* __restrict__ W2, const float* __restrict__ b2,
                      const float* __restrict__ W3, const float* __restrict__ b3,
                      float* __restrict__ out) {
    __shared__ float w1[75 * 50], w2[50 * 25], w3[25];
    int t = threadIdx.x;
    for (int i = t; i < 75 * 50; i += 256) w1[i] = W1[i];
    for (int i = t; i < 50 * 25; i += 256) w2[i] = W2[i];
    if (t < 25) w3[t] = W3[t];
    __syncthreads();
    if (t >= N_GRAPHS) return;
    const float* p = g_pooled + t * F;
    float h1[50];
    for (int j = 0; j < 50; j++) {
        float a = b1[j];
        for (int c = 0; c < F; c++) a += p[c] * w1[c * 50 + j];
        h1[j] = fmaxf(a, 0.f);
    }
    float h2[25];
    for (int j = 0; j < 25; j++) {
        float a = b2[j];
        for (int c = 0; c < 50; c++) a += h1[c] * w2[c * 25 + j];
        h2[j] = fmaxf(a, 0.f);
    }
    float o = b3[0];
    for (int c = 0; c < 25; c++) o += h2[c] * w3[c];
    out[t] = o;
}

// ---------------- launch ----------------
extern "C" void kernel_launch(void* const* d_in, const int* in_sizes, int n_in,
                              void* d_out, int out_size) {
    const int* x_idx = (const int*)d_in[0];
    const int* edge_index = (const int*)d_in[1];
    const int* eattr = (const int*)d_in[2];
    const int* batch = (const int*)d_in[3];
    const float* node_emb = (const float*)d_in[4];
    const float* edge_emb = (const float*)d_in[5];
    const float* W_edge = (const float*)d_in[6];
    const float* b_edge = (const float*)d_in[7];
    const float* W_pre = (const float*)d_in[8];
    const float* b_pre = (const float*)d_in[9];
    const float* W_post = (const float*)d_in[10];
    const float* b_post = (const float*)d_in[11];
    const float* W_lin = (const float*)d_in[12];
    const float* b_lin = (const float*)d_in[13];
    const float* gamma = (const float*)d_in[14];
    const float* beta = (const float*)d_in[15];
    const float* W1 = (const float*)d_in[16];
    const float* b1 = (const float*)d_in[17];
    const float* W2 = (const float*)d_in[18];
    const float* b2 = (const float*)d_in[19];
    const float* W3 = (const float*)d_in[20];
    const float* b3 = (const float*)d_in[21];
    float* out = (float*)d_out;

    dim3 gx(10, (N_NODES + 127) / 128);

    k_gather_count<<<GATHER_BLKS + COUNT_BLKS, 256>>>(x_idx, node_emb, edge_index); // 1
    k_scanA<<<SCAN_BLKS, 256>>>();                                                  // 2
    k_scanB<<<1, 128>>>();                                                          // 3
    k_xds<<<gx, 256>>>(W_pre, 0);                                                   // 4  <- ncu target
    k_scanC<<<SCAN_BLKS, 256>>>();                                                  // 5
    k_scatter<<<COUNT_BLKS, 256>>>(edge_index, eattr);                              // 6
    k_et_fold<<<N_ATTR + 1, 384>>>(edge_emb, W_edge, b_edge, W_pre, b_pre,
                                   W_post, b_post, W_lin, b_lin, 0);                // 7

    for (int l = 0; l < 2; l++) {
        if (l == 1) {
            k_xds<<<gx, 256>>>(W_pre, 1);
            k_et_fold<<<N_ATTR + 1, 384>>>(edge_emb, W_edge, b_edge, W_pre, b_pre,
                                           W_post, b_post, W_lin, b_lin, 1);
        }
        k_aggr<<<(N_NODES * 32 + 255) / 256, 256>>>();
        {
            dim3 grid((N_NODES + 255) / 256, TOWERS);
            k_gemmS<<<grid, 256>>>(W_post, l);
        }
        k_gemm2<<<(N_NODES + 127) / 128, 256>>>(W_lin, l);
        k_bnapply<<<(N_NODES * F + 2047) / 2048, 256>>>(gamma, beta, batch, l, l == 1);
    }

    k_mlp<<<1, 256>>>(W1, b1, W2, b2, W3, b3, out);
}

// round 12
// speedup vs baseline: 1.3957x; 1.1014x over previous
#include <cuda_runtime.h>
#include <cuda_bf16.h>
#include <math.h>

#define N_NODES 20000
#define N_EDGES 320000
#define N_GRAPHS 200
#define TOWERS 5
#define F 75
#define TF 375
#define EDGE_DIM 50
#define N_ATTR 100
#define FOUT 15
#define ROW 384

// ---------------- static scratch (zero-initialized; pads never written) ----
__device__ float g_x[N_NODES * F];
__device__ float g_y[N_NODES * F];
__device__ float g_xd[(size_t)N_NODES * ROW];
__device__ float g_xs[(size_t)N_NODES * ROW];
__device__ float g_aggr[(size_t)N_NODES * 1500];
__device__ float g_S[N_NODES * F];
__device__ float g_et[N_ATTR * ROW];
__device__ float g_Mfold[F * F];
__device__ float g_bfold[F];
__device__ int   g_deg[N_NODES];
__device__ int   g_rowptr[N_NODES + 1];
__device__ int   g_cursor[N_NODES];
__device__ int2  g_col[N_EDGES];           // (src, attr)
__device__ float g_amp[N_NODES], g_att[N_NODES], g_invdeg[N_NODES];
__device__ float g_logsum;
__device__ int   g_part[128];
__device__ int   g_partscan[128];
__device__ float g_bnsum[F], g_bnsq[F];
__device__ float g_pooled[N_GRAPHS * F];

// ---------------- f32x2 helpers ----------------
typedef unsigned long long u64;
__device__ __forceinline__ u64 f2bcast(float a) {
    u64 r;
    asm("mov.b64 %0, {%1, %1};" : "=l"(r) : "f"(a));
    return r;
}
__device__ __forceinline__ u64 f2pk(float lo, float hi) {
    u64 r;
    asm("mov.b64 %0, {%1, %2};" : "=l"(r) : "f"(lo), "f"(hi));
    return r;
}
__device__ __forceinline__ void f2up(u64 v, float& lo, float& hi) {
    asm("mov.b64 {%0, %1}, %2;" : "=f"(lo), "=f"(hi) : "l"(v));
}
__device__ __forceinline__ u64 ffma2(u64 a, u64 b, u64 c) {
    u64 d;
    asm("fma.rn.f32x2 %0, %1, %2, %3;" : "=l"(d) : "l"(a), "l"(b), "l"(c));
    return d;
}
__device__ __forceinline__ u64 fadd2(u64 a, u64 b) {
    u64 d;
    asm("add.rn.f32x2 %0, %1, %2;" : "=l"(d) : "l"(a), "l"(b));
    return d;
}

// ---------------- tf32 helpers ----------------
__device__ __forceinline__ unsigned tf32_hi(float v) {
    unsigned u;
    asm("cvt.rna.tf32.f32 %0, %1;" : "=r"(u) : "f"(v));
    return u;
}

#define MMA_TF32(c, a, b0, b1) \
    asm volatile("mma.sync.aligned.m16n8k8.row.col.f32.tf32.tf32.f32 " \
        "{%0,%1,%2,%3}, {%4,%5,%6,%7}, {%8,%9}, {%0,%1,%2,%3};" \
        : "+f"((c)[0]), "+f"((c)[1]), "+f"((c)[2]), "+f"((c)[3]) \
        : "r"((a)[0]), "r"((a)[1]), "r"((a)[2]), "r"((a)[3]), "r"(b0), "r"(b1))

// ---------------- preprocessing ----------------
#define GATHER_BLKS ((N_NODES * F + 255) / 256)
#define COUNT_BLKS ((N_EDGES + 255) / 256)
#define SCAN_BLKS ((N_NODES + 255) / 256)

__global__ void k_gather_count(const int* __restrict__ x_idx, const float* __restrict__ emb,
                               const int* __restrict__ ei) {
    int b = blockIdx.x;
    if (b < GATHER_BLKS) {
        int i = b * 256 + threadIdx.x;
        if (i < N_NODES * F) {
            int n = i / F, f = i - n * F;
            g_x[i] = emb[x_idx[n] * F + f];
        }
    } else {
        int i = (b - GATHER_BLKS) * 256 + threadIdx.x;
        if (i < N_EDGES) atomicAdd(&g_deg[ei[N_EDGES + i]], 1);
    }
}

__global__ void k_scanA() {
    __shared__ int ss[256];
    __shared__ float ls[256];
    int b = blockIdx.x, tid = threadIdx.x;
    int n = b * 256 + tid;
    int d = (n < N_NODES) ? g_deg[n] : 0;
    ss[tid] = d;
    ls[tid] = (n < N_NODES) ? logf((float)d + 1.f) : 0.f;
    __syncthreads();
    for (int o = 128; o; o >>= 1) {
        if (tid < o) { ss[tid] += ss[tid + o]; ls[tid] += ls[tid + o]; }
        __syncthreads();
    }
    if (tid == 0) { g_part[b] = ss[0]; atomicAdd(&g_logsum, ls[0]); }
}

__global__ void k_scanB() {
    __shared__ int s[128];
    int t = threadIdx.x;
    int own = (t < SCAN_BLKS) ? g_part[t] : 0;
    s[t] = own;
    __syncthreads();
    for (int o = 1; o < 128; o <<= 1) {
        int v = (t >= o) ? s[t - o] : 0;
        __syncthreads();
        s[t] += v;
        __syncthreads();
    }
    if (t < SCAN_BLKS) g_partscan[t] = s[t] - own;
}

__global__ void k_scanC() {
    __shared__ int s[256];
    int b = blockIdx.x, tid = threadIdx.x;
    int n = b * 256 + tid;
    int d = (n < N_NODES) ? g_deg[n] : 0;
    int own = d;
    s[tid] = d;
    __syncthreads();
    for (int o = 1; o < 256; o <<= 1) {
        int v = (tid >= o) ? s[tid - o] : 0;
        __syncthreads();
        s[tid] += v;
        __syncthreads();
    }
    int excl = s[tid] - own + g_partscan[b];
    if (n < N_NODES) {
        g_rowptr[n] = excl;
        g_cursor[n] = excl;
        float avg = g_logsum * (1.f / (float)N_NODES);
        float dc = fmaxf((float)d, 1.f);
        float L = logf(dc + 1.f);
        g_amp[n] = L / avg;
        g_att[n] = avg / L;
        g_invdeg[n] = 1.f / dc;
        if (n == N_NODES - 1) g_rowptr[N_NODES] = excl + d;
    }
    if (n < N_GRAPHS * F) g_pooled[n] = 0.f;
}

__global__ void k_scatter(const int* __restrict__ ei, const int* __restrict__ ea) {
    int i = blockIdx.x * 256 + threadIdx.x;
    if (i < N_EDGES) {
        int dst = ei[N_EDGES + i];
        int pos = atomicAdd(&g_cursor[dst], 1);
        g_col[pos] = make_int2(ei[i], ea[i]);
    }
    if (i < N_NODES) g_deg[i] = 0;     // reset for next invocation
    if (i == 0) g_logsum = 0.f;
}

// ---------------- per-layer: et table + Mfold + bn zero ----------------
__global__ void k_et_fold(const float* __restrict__ edge_emb, const float* __restrict__ W_edge,
                          const float* __restrict__ b_edge, const float* __restrict__ W_pre,
                          const float* __restrict__ b_pre, const float* __restrict__ W_post,
                          const float* __restrict__ b_post, const float* __restrict__ W_lin,
                          const float* __restrict__ b_lin, int l) {
    int a = blockIdx.x, t = threadIdx.x;
    if (a < N_ATTR) {
        __shared__ float e75[F];
        if (t < F) {
            float acc = b_edge[l * F + t];
            for (int d = 0; d < EDGE_DIM; d++)
                acc += edge_emb[a * EDGE_DIM + d] * W_edge[(l * EDGE_DIM + d) * F + t];
            e75[t] = acc;
        }
        __syncthreads();
        if (t < TF) {
            int tw = t / F, f = t - tw * F;
            float acc = b_pre[(l * TOWERS + tw) * F + f];
            const float* Wp = W_pre + ((size_t)((l * TOWERS + tw) * 225 + 150)) * F + f;
            for (int c = 0; c < F; c++) acc += e75[c] * Wp[c * F];
            g_et[a * ROW + t] = acc;
        }
    } else {
        for (int i = t; i < F * F; i += 384) {
            int c = i / F, o = i - c * F;
            float acc = 0.f;
            for (int tf = 0; tf < F; tf++) {
                int tw = tf / FOUT, f = tf - tw * FOUT;
                acc += W_post[((size_t)((l * TOWERS + tw) * 975 + c)) * FOUT + f] *
                       W_lin[(l * F + tf) * F + o];
            }
            g_Mfold[i] = acc;
        }
        if (t < F) {
            float bf = b_lin[l * F + t];
            for (int tf = 0; tf < F; tf++) {
                int tw = tf / FOUT, f = tf - tw * FOUT;
                bf += b_post[(l * TOWERS + tw) * FOUT + f] * W_lin[(l * F + tf) * F + t];
            }
            g_bfold[t] = bf;
            g_bnsum[t] = 0.f;
            g_bnsq[t] = 0.f;
        }
    }
}

// ---------------- xd|xs GEMM via tf32 mma.sync, hi/lo split ----------------
// per (part,tower) piece: [128 nodes x 80 cols], K=75 pad 80, chunked by 16.
// 8 warps: 4(m) x 2(n); warp tile 32 rows x 40 cols = 2 m16 x 5 n8 tiles.
// D = Ahi*Bhi + Ahi*Blo + Alo*Bhi  (fp32-grade accuracy).
__global__ __launch_bounds__(256, 2) void k_xds(const float* __restrict__ W_pre, int l) {
    __shared__ __align__(16) float Ah[128][20], Al[128][20];
    __shared__ __align__(16) float Bh[16][88], Bl[16][88];
    int piece = blockIdx.x;
    int n0 = blockIdx.y * 128;
    int part = piece / 5, tw = piece - part * 5;
    const float* Wbase = W_pre + (size_t)((l * TOWERS + tw) * 225 + part * F) * F;
    int tid = threadIdx.x, lane = tid & 31, wid = tid >> 5;
    int wm = wid >> 1, wn = wid & 1;
    float c[2][5][4];
#pragma unroll
    for (int t = 0; t < 2; t++)
#pragma unroll
        for (int s5 = 0; s5 < 5; s5++)
#pragma unroll
            for (int e = 0; e < 4; e++) c[t][s5][e] = 0.f;

    for (int kc = 0; kc < 80; kc += 16) {
#pragma unroll
        for (int s = 0; s < 8; s++) {
            int idx = tid + s * 256;
            int r = idx >> 4, k = idx & 15;
            int gk = kc + k;
            int n = n0 + r;
            float v = (n < N_NODES && gk < F) ? g_x[n * F + gk] : 0.f;
            unsigned hu = tf32_hi(v);
            float hf = __uint_as_float(hu);
            float rs = v - hf;
            unsigned lu = tf32_hi(rs);
            Ah[r][k] = hf;
            Al[r][k] = __uint_as_float(lu);
        }
#pragma unroll
        for (int s = 0; s < 5; s++) {
            int idx = tid + s * 256;
            int k = idx / 80, j = idx - k * 80;
            int gk = kc + k;
            float v = (gk < F && j < F) ? Wbase[gk * F + j] : 0.f;
            unsigned hu = tf32_hi(v);
            float hf = __uint_as_float(hu);
            float rs = v - hf;
            unsigned lu = tf32_hi(rs);
            Bh[k][j] = hf;
            Bl[k][j] = __uint_as_float(lu);
        }
        __syncthreads();
#pragma unroll
        for (int k8 = 0; k8 < 16; k8 += 8) {
            unsigned ah[2][4], al[2][4];
            int ar = lane >> 2;
            int ak = k8 + (lane & 3);
#pragma unroll
            for (int t = 0; t < 2; t++) {
                int r = wm * 32 + t * 16 + ar;
                ah[t][0] = __float_as_uint(Ah[r][ak]);
                ah[t][1] = __float_as_uint(Ah[r + 8][ak]);
                ah[t][2] = __float_as_uint(Ah[r][ak + 4]);
                ah[t][3] = __float_as_uint(Ah[r + 8][ak + 4]);
                al[t][0] = __float_as_uint(Al[r][ak]);
                al[t][1] = __float_as_uint(Al[r + 8][ak]);
                al[t][2] = __float_as_uint(Al[r][ak + 4]);
                al[t][3] = __float_as_uint(Al[r + 8][ak + 4]);
            }
#pragma unroll
            for (int s5 = 0; s5 < 5; s5++) {
                int n = wn * 40 + s5 * 8 + (lane >> 2);
                int bk = k8 + (lane & 3);
                unsigned bh0 = __float_as_uint(Bh[bk][n]);
                unsigned bh1 = __float_as_uint(Bh[bk + 4][n]);
                unsigned bl0 = __float_as_uint(Bl[bk][n]);
                unsigned bl1 = __float_as_uint(Bl[bk + 4][n]);
#pragma unroll
                for (int t = 0; t < 2; t++) {
                    MMA_TF32(c[t][s5], ah[t], bh0, bh1);
                    MMA_TF32(c[t][s5], ah[t], bl0, bl1);
                    MMA_TF32(c[t][s5], al[t], bh0, bh1);
                }
            }
        }
        __syncthreads();
    }
    float* dst = part ? g_xs : g_xd;
#pragma unroll
    for (int t = 0; t < 2; t++) {
        int r0 = n0 + wm * 32 + t * 16 + (lane >> 2);
#pragma unroll
        for (int s5 = 0; s5 < 5; s5++) {
            int gc = wn * 40 + s5 * 8 + 2 * (lane & 3);
#pragma unroll
            for (int h = 0; h < 2; h++) {
                int rr = r0 + h * 8;
                if (rr >= N_NODES) continue;
                float* row = dst + (size_t)rr * ROW + tw * F;
                if (gc < F) row[gc] = c[t][s5][h * 2 + 0];
                if (gc + 1 < F) row[gc + 1] = c[t][s5][h * 2 + 1];
            }
        }
    }
}

// ---------------- aggregation: one warp per dst node ----------------
__global__ void k_aggr() {
    int warp = (blockIdx.x * blockDim.x + threadIdx.x) >> 5;
    int lane = threadIdx.x & 31;
    if (warp >= N_NODES) return;
    int n = warp;
    u64 sum2[6], sq2[6];
    float mn[12], mx[12];
#pragma unroll
    for (int q = 0; q < 6; q++) { sum2[q] = 0ULL; sq2[q] = 0ULL; }
#pragma unroll
    for (int j = 0; j < 12; j++) { mn[j] = INFINITY; mx[j] = -INFINITY; }
    int e0 = g_rowptr[n], e1 = g_rowptr[n + 1];
#pragma unroll 2
    for (int e = e0; e < e1; e++) {
        int2 sa = g_col[e];
        const float4* xs4 = (const float4*)(g_xs + (size_t)sa.x * ROW);
        const float4* et4 = (const float4*)(g_et + sa.y * ROW);
#pragma unroll
        for (int q = 0; q < 3; q++) {
            float4 xv = xs4[lane * 3 + q];
            float4 ev = et4[lane * 3 + q];
            u64 v0 = fadd2(f2pk(xv.x, xv.y), f2pk(ev.x, ev.y));
            u64 v1 = fadd2(f2pk(xv.z, xv.w), f2pk(ev.z, ev.w));
            sum2[2 * q] = fadd2(sum2[2 * q], v0);
            sum2[2 * q + 1] = fadd2(sum2[2 * q + 1], v1);
            sq2[2 * q] = ffma2(v0, v0, sq2[2 * q]);
            sq2[2 * q + 1] = ffma2(v1, v1, sq2[2 * q + 1]);
            float a0, a1, a2, a3;
            f2up(v0, a0, a1);
            f2up(v1, a2, a3);
            int j = q * 4;
            mn[j] = fminf(mn[j], a0); mx[j] = fmaxf(mx[j], a0);
            mn[j + 1] = fminf(mn[j + 1], a1); mx[j + 1] = fmaxf(mx[j + 1], a1);
            mn[j + 2] = fminf(mn[j + 2], a2); mx[j + 2] = fmaxf(mx[j + 2], a2);
            mn[j + 3] = fminf(mn[j + 3], a3); mx[j + 3] = fmaxf(mx[j + 3], a3);
        }
    }
    float inv = g_invdeg[n];
    bool has = e1 > e0;
    const float4* xdrow = (const float4*)(g_xd + (size_t)n * ROW);
#pragma unroll
    for (int q = 0; q < 3; q++) {
        float4 xv = xdrow[lane * 3 + q];
        float xd4[4] = {xv.x, xv.y, xv.z, xv.w};
#pragma unroll
        for (int h4 = 0; h4 < 4; h4++) {
            int j = q * 4 + h4;
            int f = lane * 12 + j;
            if (f >= TF) continue;
            float sm, sqv;
            {
                float lo, hi;
                f2up(sum2[j >> 1], lo, hi);
                sm = (j & 1) ? hi : lo;
                f2up(sq2[j >> 1], lo, hi);
                sqv = (j & 1) ? hi : lo;
            }
            float xd = xd4[h4];
            float meanw = sm * inv;
            float var = sqv * inv - meanw * meanw;
            float sd = sqrtf(fmaxf(var, 0.f) + 1e-5f);
            float mean = has ? (meanw + xd) : 0.f;
            float mnv = has ? (mn[j] + xd) : 0.f;
            float mxv = has ? (mx[j] + xd) : 0.f;
            int tw = f / F, jj = f - tw * F;
            float* outp = g_aggr + (size_t)n * 1500 + tw * 300 + jj;
            outp[0] = mean;
            outp[75] = mnv;
            outp[150] = mxv;
            outp[225] = sd;
        }
    }
}

// ---------------- S GEMM via tf32 mma.sync + scaler combine ----------------
// per tower: A=[128 nodes x 300] (aggr), B=[300 x 48] ([g0|g1|g2] x16 each, f<15).
// 8 warps, each owns 16 rows x 48 cols = 6 n8-tiles; scaler groups are tile pairs
// {0,1}/{2,3}/{4,5} at the same f-position per thread -> combine in registers.
__global__ __launch_bounds__(256, 3) void k_gemmS(const float* __restrict__ W_post, int l) {
    __shared__ __align__(16) float Ah[128][20], Al[128][20];
    __shared__ __align__(16) float Bh[16][56], Bl[16][56];
    int t = blockIdx.y;
    int n0 = blockIdx.x * 128;
    const float* Wb = W_post + (size_t)((l * TOWERS + t) * 975 + 75) * FOUT;
    int tid = threadIdx.x, lane = tid & 31, wid = tid >> 5;
    float c[6][4];
#pragma unroll
    for (int s6 = 0; s6 < 6; s6++)
#pragma unroll
        for (int e = 0; e < 4; e++) c[s6][e] = 0.f;

    for (int kc = 0; kc < 304; kc += 16) {
        // A fill: 128 rows x 16 k from g_aggr
#pragma unroll
        for (int s = 0; s < 8; s++) {
            int idx = tid + s * 256;
            int r = idx >> 4, k = idx & 15;
            int gk = kc + k;
            int n = n0 + r;
            float v = (n < N_NODES && gk < 300) ? g_aggr[(size_t)n * 1500 + t * 300 + gk] : 0.f;
            unsigned hu = tf32_hi(v);
            float hf = __uint_as_float(hu);
            float rs = v - hf;
            unsigned lu = tf32_hi(rs);
            Ah[r][k] = hf;
            Al[r][k] = __uint_as_float(lu);
        }
        // B fill: 16 k x 48 cols (g = j>>4, f = j&15, f<15 valid)
#pragma unroll
        for (int s = 0; s < 3; s++) {
            int idx = tid + s * 256;
            int k = idx / 48, j = idx - k * 48;
            int gk = kc + k;
            int g = j >> 4, f = j & 15;
            float v = (gk < 300 && f < FOUT) ? Wb[(size_t)(g * 300 + gk) * FOUT + f] : 0.f;
            unsigned hu = tf32_hi(v);
            float hf = __uint_as_float(hu);
            float rs = v - hf;
            unsigned lu = tf32_hi(rs);
            Bh[k][j] = hf;
            Bl[k][j] = __uint_as_float(lu);
        }
        __syncthreads();
#pragma unroll
        for (int k8 = 0; k8 < 16; k8 += 8) {
            unsigned ah[4], al[4];
            int r = wid * 16 + (lane >> 2);
            int ak = k8 + (lane & 3);
            ah[0] = __float_as_uint(Ah[r][ak]);
            ah[1] = __float_as_uint(Ah[r + 8][ak]);
            ah[2] = __float_as_uint(Ah[r][ak + 4]);
            ah[3] = __float_as_uint(Ah[r + 8][ak + 4]);
            al[0] = __float_as_uint(Al[r][ak]);
            al[1] = __float_as_uint(Al[r + 8][ak]);
            al[2] = __float_as_uint(Al[r][ak + 4]);
            al[3] = __float_as_uint(Al[r + 8][ak + 4]);
#pragma unroll
            for (int s6 = 0; s6 < 6; s6++) {
                int nn = s6 * 8 + (lane >> 2);
                int bk = k8 + (lane & 3);
                unsigned bh0 = __float_as_uint(Bh[bk][nn]);
                unsigned bh1 = __float_as_uint(Bh[bk + 4][nn]);
                unsigned bl0 = __float_as_uint(Bl[bk][nn]);
                unsigned bl1 = __float_as_uint(Bl[bk + 4][nn]);
                MMA_TF32(c[s6], ah, bh0, bh1);
                MMA_TF32(c[s6], ah, bl0, bl1);
                MMA_TF32(c[s6], al, bh0, bh1);
            }
        }
        __syncthreads();
    }
    // epilogue: S = g0 + amp*g1 + att*g2 per (node, f)
    int r0 = n0 + wid * 16 + (lane >> 2);
#pragma unroll
    for (int h = 0; h < 2; h++) {
        int n = r0 + h * 8;
        if (n >= N_NODES) continue;
        float amp = g_amp[n], att = g_att[n];
        float* row = g_S + n * F + t * FOUT;
#pragma unroll
        for (int p = 0; p < 2; p++) {
#pragma unroll
            for (int e = 0; e < 2; e++) {
                int f = p * 8 + 2 * (lane & 3) + e;
                if (f < FOUT) {
                    float v = c[p][h * 2 + e] + amp * c[p + 2][h * 2 + e] + att * c[p + 4][h * 2 + e];
                    row[f] = v;
                }
            }
        }
    }
}

// ---------------- post+lin GEMM (K=150) + BN reduce ----------------
__global__ __launch_bounds__(256, 3) void k_gemm2(const float* __restrict__ W_lin, int l) {
    __shared__ __align__(16) float As[128][25];
    __shared__ __align__(16) float Bs[25][96];
    __shared__ float red[32][80];
    int n0 = blockIdx.x * 128;
    int tid = threadIdx.x;
    int ty = tid >> 3, tx = tid & 7;
    u64 acc[4][5];
#pragma unroll
    for (int i = 0; i < 4; i++)
#pragma unroll
        for (int j = 0; j < 5; j++) acc[i][j] = 0ULL;
    for (int kc = 0; kc < 150; kc += 25) {
        for (int idx = tid; idx < 128 * 25; idx += 256) {
            int r = idx / 25, kk = idx - r * 25;
            int n = n0 + r;
            int k = kc + kk;
            float v = 0.f;
            if (n < N_NODES) v = (k < F) ? g_x[n * F + k] : g_S[n * F + (k - F)];
            As[r][kk] = v;
        }
        for (int idx = tid; idx < 25 * 80; idx += 256) {
            int kk = idx / 80, j = idx - kk * 80;
            int k = kc + kk;
            int slot = (j / 10) * 12 + (j % 10);
            float v = 0.f;
            if (j < F) v = (k < F) ? g_Mfold[k * F + j] : W_lin[(l * F + (k - F)) * F + j];
            Bs[kk][slot] = v;
        }
        __syncthreads();
#pragma unroll 5
        for (int kk = 0; kk < 25; kk++) {
            float4 bA = *(const float4*)&Bs[kk][tx * 12];
            float4 bB = *(const float4*)&Bs[kk][tx * 12 + 4];
            u64 b4 = *(const u64*)&Bs[kk][tx * 12 + 8];
            u64 b2[5];
            b2[0] = f2pk(bA.x, bA.y);
            b2[1] = f2pk(bA.z, bA.w);
            b2[2] = f2pk(bB.x, bB.y);
            b2[3] = f2pk(bB.z, bB.w);
            b2[4] = b4;
#pragma unroll
            for (int i = 0; i < 4; i++) {
                u64 a2 = f2bcast(As[ty + 32 * i][kk]);
#pragma unroll
                for (int j = 0; j < 5; j++) acc[i][j] = ffma2(a2, b2[j], acc[i][j]);
            }
        }
        __syncthreads();
    }
    float s[10], q[10];
#pragma unroll
    for (int j = 0; j < 10; j++) { s[j] = 0.f; q[j] = 0.f; }
#pragma unroll
    for (int i = 0; i < 4; i++) {
        int n = n0 + ty + 32 * i;
        if (n >= N_NODES) continue;
#pragma unroll
        for (int j = 0; j < 5; j++) {
            int jc = tx * 10 + 2 * j;
            float lo, hi;
            f2up(acc[i][j], lo, hi);
            if (jc < F) {
                float v = lo + g_bfold[jc];
                g_y[n * F + jc] = v;
                s[2 * j] += v; q[2 * j] += v * v;
            }
            if (jc + 1 < F) {
                float v = hi + g_bfold[jc + 1];
                g_y[n * F + jc + 1] = v;
                s[2 * j + 1] += v; q[2 * j + 1] += v * v;
            }
        }
    }
#pragma unroll
    for (int j = 0; j < 10; j++) red[ty][tx * 10 + j] = s[j];
    __syncthreads();
    if (tid < F) {
        float tot = 0.f;
        for (int yy = 0; yy < 32; yy++) tot += red[yy][tid];
        atomicAdd(&g_bnsum[tid], tot);
    }
    __syncthreads();
#pragma unroll
    for (int j = 0; j < 10; j++) red[ty][tx * 10 + j] = q[j];
    __syncthreads();
    if (tid < F) {
        float tot = 0.f;
        for (int yy = 0; yy < 32; yy++) tot += red[yy][tid];
        atomicAdd(&g_bnsq[tid], tot);
    }
}

// ---------------- BN finalize + apply + ReLU (+ pool on last layer) ------
__global__ void k_bnapply(const float* __restrict__ gamma, const float* __restrict__ beta,
                          const int* __restrict__ batch, int l, int do_pool) {
    __shared__ float sc[F], sh[F];
    int tid = threadIdx.x;
    if (tid < F) {
        float mu = g_bnsum[tid] * (1.f / (float)N_NODES);
        float var = g_bnsq[tid] * (1.f / (float)N_NODES) - mu * mu;
        float r = rsqrtf(var + 1e-5f);
        float s = r * gamma[l * F + tid];
        sc[tid] = s;
        sh[tid] = beta[l * F + tid] - mu * s;
    }
    __syncthreads();
    int base = blockIdx.x * 2048;
#pragma unroll
    for (int o = 0; o < 2048; o += 256) {
        int i = base + o + tid;
        if (i < N_NODES * F) {
            int n = i / F, c = i - n * F;
            float v = fmaxf(g_y[i] * sc[c] + sh[c], 0.f);
            g_x[i] = v;
            if (do_pool) atomicAdd(&g_pooled[batch[n] * F + c], v);
        }
    }
}

// ---------------- final MLP ----------------
__global__ void k_mlp(const float* __restrict__ W1, const float* __restrict__ b1,
                      const float* __restrict__ W2, const float* __restrict__ b2,
                      const float* __restrict__ W3, const float* __restrict__ b3,
                      float* __restrict__ out) {
    __shared__ float w1[75 * 50], w2[50 * 25], w3[25];
    int t = threadIdx.x;
    for (int i = t; i < 75 * 50; i += 256) w1[i] = W1[i];
    for (int i = t; i < 50 * 25; i += 256) w2[i] = W2[i];
    if (t < 25) w3[t] = W3[t];
    __syncthreads();
    if (t >= N_GRAPHS) return;
    const float* p = g_pooled + t * F;
    float h1[50];
    for (int j = 0; j < 50; j++) {
        float a = b1[j];
        for (int c = 0; c < F; c++) a += p[c] * w1[c * 50 + j];
        h1[j] = fmaxf(a, 0.f);
    }
    float h2[25];
    for (int j = 0; j < 25; j++) {
        float a = b2[j];
        for (int c = 0; c < 50; c++) a += h1[c] * w2[c * 25 + j];
        h2[j] = fmaxf(a, 0.f);
    }
    float o = b3[0];
    for (int c = 0; c < 25; c++) o += h2[c] * w3[c];
    out[t] = o;
}

// ---------------- launch ----------------
extern "C" void kernel_launch(void* const* d_in, const int* in_sizes, int n_in,
                              void* d_out, int out_size) {
    const int* x_idx = (const int*)d_in[0];
    const int* edge_index = (const int*)d_in[1];
    const int* eattr = (const int*)d_in[2];
    const int* batch = (const int*)d_in[3];
    const float* node_emb = (const float*)d_in[4];
    const float* edge_emb = (const float*)d_in[5];
    const float* W_edge = (const float*)d_in[6];
    const float* b_edge = (const float*)d_in[7];
    const float* W_pre = (const float*)d_in[8];
    const float* b_pre = (const float*)d_in[9];
    const float* W_post = (const float*)d_in[10];
    const float* b_post = (const float*)d_in[11];
    const float* W_lin = (const float*)d_in[12];
    const float* b_lin = (const float*)d_in[13];
    const float* gamma = (const float*)d_in[14];
    const float* beta = (const float*)d_in[15];
    const float* W1 = (const float*)d_in[16];
    const float* b1 = (const float*)d_in[17];
    const float* W2 = (const float*)d_in[18];
    const float* b2 = (const float*)d_in[19];
    const float* W3 = (const float*)d_in[20];
    const float* b3 = (const float*)d_in[21];
    float* out = (float*)d_out;

    dim3 gx(10, (N_NODES + 127) / 128);

    k_gather_count<<<GATHER_BLKS + COUNT_BLKS, 256>>>(x_idx, node_emb, edge_index); // 1
    k_scanA<<<SCAN_BLKS, 256>>>();                                                  // 2
    k_scanB<<<1, 128>>>();                                                          // 3
    k_xds<<<gx, 256>>>(W_pre, 0);                                                   // 4  <- ncu target
    k_scanC<<<SCAN_BLKS, 256>>>();                                                  // 5
    k_scatter<<<COUNT_BLKS, 256>>>(edge_index, eattr);                              // 6
    k_et_fold<<<N_ATTR + 1, 384>>>(edge_emb, W_edge, b_edge, W_pre, b_pre,
                                   W_post, b_post, W_lin, b_lin, 0);                // 7

    for (int l = 0; l < 2; l++) {
        if (l == 1) {
            k_xds<<<gx, 256>>>(W_pre, 1);
            k_et_fold<<<N_ATTR + 1, 384>>>(edge_emb, W_edge, b_edge, W_pre, b_pre,
                                           W_post, b_post, W_lin, b_lin, 1);
        }
        k_aggr<<<(N_NODES * 32 + 255) / 256, 256>>>();
        {
            dim3 grid((N_NODES + 127) / 128, TOWERS);
            k_gemmS<<<grid, 256>>>(W_post, l);
        }
        k_gemm2<<<(N_NODES + 127) / 128, 256>>>(W_lin, l);
        k_bnapply<<<(N_NODES * F + 2047) / 2048, 256>>>(gamma, beta, batch, l, l == 1);
    }

    k_mlp<<<1, 256>>>(W1, b1, W2, b2, W3, b3, out);
}

// round 14
// speedup vs baseline: 1.4713x; 1.0542x over previous
#include <cuda_runtime.h>
#include <cuda_bf16.h>
#include <math.h>

#define N_NODES 20000
#define N_EDGES 320000
#define N_GRAPHS 200
#define TOWERS 5
#define F 75
#define TF 375
#define EDGE_DIM 50
#define N_ATTR 100
#define FOUT 15
#define ROW 384

// ---------------- static scratch (zero-initialized; pads never written) ----
__device__ float g_x[N_NODES * F];
__device__ float g_y[N_NODES * F];
__device__ float g_xd[(size_t)N_NODES * ROW];
__device__ float g_xs[(size_t)N_NODES * ROW];
__device__ float g_aggr[(size_t)N_NODES * 1500];
__device__ float g_S[N_NODES * F];
__device__ float g_et[2][N_ATTR * ROW];
__device__ float g_Mfold[2][F * F];
__device__ float g_bfold[2][F];
__device__ int   g_deg[N_NODES];
__device__ int   g_rowptr[N_NODES + 1];
__device__ int   g_cursor[N_NODES];
__device__ int2  g_col[N_EDGES];           // (src, attr)
__device__ float g_amp[N_NODES], g_att[N_NODES], g_invdeg[N_NODES];
__device__ float g_logsum;
__device__ int   g_part[128];
__device__ int   g_partscan[128];
__device__ float g_bnsum[2][F], g_bnsq[2][F];
__device__ float g_pooled[N_GRAPHS * F];

// ---------------- f32x2 helpers ----------------
typedef unsigned long long u64;
__device__ __forceinline__ u64 f2pk(float lo, float hi) {
    u64 r;
    asm("mov.b64 %0, {%1, %2};" : "=l"(r) : "f"(lo), "f"(hi));
    return r;
}
__device__ __forceinline__ void f2up(u64 v, float& lo, float& hi) {
    asm("mov.b64 {%0, %1}, %2;" : "=f"(lo), "=f"(hi) : "l"(v));
}
__device__ __forceinline__ u64 ffma2(u64 a, u64 b, u64 c) {
    u64 d;
    asm("fma.rn.f32x2 %0, %1, %2, %3;" : "=l"(d) : "l"(a), "l"(b), "l"(c));
    return d;
}
__device__ __forceinline__ u64 fadd2(u64 a, u64 b) {
    u64 d;
    asm("add.rn.f32x2 %0, %1, %2;" : "=l"(d) : "l"(a), "l"(b));
    return d;
}

// ---------------- tf32 helpers ----------------
__device__ __forceinline__ unsigned tf32_hi(float v) {
    unsigned u;
    asm("cvt.rna.tf32.f32 %0, %1;" : "=r"(u) : "f"(v));
    return u;
}

#define MMA_TF32(c, a, b0, b1) \
    asm volatile("mma.sync.aligned.m16n8k8.row.col.f32.tf32.tf32.f32 " \
        "{%0,%1,%2,%3}, {%4,%5,%6,%7}, {%8,%9}, {%0,%1,%2,%3};" \
        : "+f"((c)[0]), "+f"((c)[1]), "+f"((c)[2]), "+f"((c)[3]) \
        : "r"((a)[0]), "r"((a)[1]), "r"((a)[2]), "r"((a)[3]), "r"(b0), "r"(b1))

// ---------------- preprocessing ----------------
#define GATHER_BLKS ((N_NODES * F + 255) / 256)
#define COUNT_BLKS ((N_EDGES + 255) / 256)
#define SCAN_BLKS ((N_NODES + 255) / 256)

__global__ void k_gather_count(const int* __restrict__ x_idx, const float* __restrict__ emb,
                               const int* __restrict__ ei) {
    int b = blockIdx.x;
    if (b < GATHER_BLKS) {
        int i = b * 256 + threadIdx.x;
        if (i < N_NODES * F) {
            int n = i / F, f = i - n * F;
            g_x[i] = emb[x_idx[n] * F + f];
        }
    } else {
        int i = (b - GATHER_BLKS) * 256 + threadIdx.x;
        if (i < N_EDGES) atomicAdd(&g_deg[ei[N_EDGES + i]], 1);
    }
}

__global__ void k_scanA() {
    __shared__ int ss[256];
    __shared__ float ls[256];
    int b = blockIdx.x, tid = threadIdx.x;
    int n = b * 256 + tid;
    int d = (n < N_NODES) ? g_deg[n] : 0;
    ss[tid] = d;
    ls[tid] = (n < N_NODES) ? logf((float)d + 1.f) : 0.f;
    __syncthreads();
    for (int o = 128; o; o >>= 1) {
        if (tid < o) { ss[tid] += ss[tid + o]; ls[tid] += ls[tid + o]; }
        __syncthreads();
    }
    if (tid == 0) { g_part[b] = ss[0]; atomicAdd(&g_logsum, ls[0]); }
}

__global__ void k_scanB() {
    __shared__ int s[128];
    int t = threadIdx.x;
    int own = (t < SCAN_BLKS) ? g_part[t] : 0;
    s[t] = own;
    __syncthreads();
    for (int o = 1; o < 128; o <<= 1) {
        int v = (t >= o) ? s[t - o] : 0;
        __syncthreads();
        s[t] += v;
        __syncthreads();
    }
    if (t < SCAN_BLKS) g_partscan[t] = s[t] - own;
}

__global__ void k_scanC() {
    __shared__ int s[256];
    int b = blockIdx.x, tid = threadIdx.x;
    int n = b * 256 + tid;
    int d = (n < N_NODES) ? g_deg[n] : 0;
    int own = d;
    s[tid] = d;
    __syncthreads();
    for (int o = 1; o < 256; o <<= 1) {
        int v = (tid >= o) ? s[tid - o] : 0;
        __syncthreads();
        s[tid] += v;
        __syncthreads();
    }
    int excl = s[tid] - own + g_partscan[b];
    if (n < N_NODES) {
        g_rowptr[n] = excl;
        g_cursor[n] = excl;
        float avg = g_logsum * (1.f / (float)N_NODES);
        float dc = fmaxf((float)d, 1.f);
        float L = logf(dc + 1.f);
        g_amp[n] = L / avg;
        g_att[n] = avg / L;
        g_invdeg[n] = 1.f / dc;
        if (n == N_NODES - 1) g_rowptr[N_NODES] = excl + d;
    }
    if (n < N_GRAPHS * F) g_pooled[n] = 0.f;
}

__global__ void k_scatter(const int* __restrict__ ei, const int* __restrict__ ea) {
    int i = blockIdx.x * 256 + threadIdx.x;
    if (i < N_EDGES) {
        int dst = ei[N_EDGES + i];
        int pos = atomicAdd(&g_cursor[dst], 1);
        g_col[pos] = make_int2(ei[i], ea[i]);
    }
    if (i < N_NODES) g_deg[i] = 0;     // reset for next invocation
    if (i == 0) g_logsum = 0.f;
}

// ---------------- both layers: et table + Mfold + bn zero ----------------
__global__ void k_et_fold(const float* __restrict__ edge_emb, const float* __restrict__ W_edge,
                          const float* __restrict__ b_edge, const float* __restrict__ W_pre,
                          const float* __restrict__ b_pre, const float* __restrict__ W_post,
                          const float* __restrict__ b_post, const float* __restrict__ W_lin,
                          const float* __restrict__ b_lin) {
    int a = blockIdx.x, t = threadIdx.x;
    int l = blockIdx.y;
    if (a < N_ATTR) {
        __shared__ float e75[F];
        if (t < F) {
            float acc = b_edge[l * F + t];
            for (int d = 0; d < EDGE_DIM; d++)
                acc += edge_emb[a * EDGE_DIM + d] * W_edge[(l * EDGE_DIM + d) * F + t];
            e75[t] = acc;
        }
        __syncthreads();
        if (t < TF) {
            int tw = t / F, f = t - tw * F;
            float acc = b_pre[(l * TOWERS + tw) * F + f];
            const float* Wp = W_pre + ((size_t)((l * TOWERS + tw) * 225 + 150)) * F + f;
            for (int c = 0; c < F; c++) acc += e75[c] * Wp[c * F];
            g_et[l][a * ROW + t] = acc;
        }
    } else {
        for (int i = t; i < F * F; i += 384) {
            int c = i / F, o = i - c * F;
            float acc = 0.f;
            for (int tf = 0; tf < F; tf++) {
                int tw = tf / FOUT, f = tf - tw * FOUT;
                acc += W_post[((size_t)((l * TOWERS + tw) * 975 + c)) * FOUT + f] *
                       W_lin[(l * F + tf) * F + o];
            }
            g_Mfold[l][i] = acc;
        }
        if (t < F) {
            float bf = b_lin[l * F + t];
            for (int tf = 0; tf < F; tf++) {
                int tw = tf / FOUT, f = tf - tw * FOUT;
                bf += b_post[(l * TOWERS + tw) * FOUT + f] * W_lin[(l * F + tf) * F + t];
            }
            g_bfold[l][t] = bf;
            g_bnsum[l][t] = 0.f;
            g_bnsq[l][t] = 0.f;
        }
    }
}

// ---------------- xd|xs GEMM via tf32 mma.sync, hi/lo split ----------------
// per (part,tower) piece: [128 nodes x 80 cols], K=75 pad 80, chunked by 16.
// 8 warps: 4(m) x 2(n); warp tile 32 rows x 40 cols = 2 m16 x 5 n8 tiles.
__global__ __launch_bounds__(256, 2) void k_xds(const float* __restrict__ W_pre, int l) {
    __shared__ __align__(16) float Ah[128][20], Al[128][20];
    __shared__ __align__(16) float Bh[16][88], Bl[16][88];
    int piece = blockIdx.x;
    int n0 = blockIdx.y * 128;
    int part = piece / 5, tw = piece - part * 5;
    const float* Wbase = W_pre + (size_t)((l * TOWERS + tw) * 225 + part * F) * F;
    int tid = threadIdx.x, lane = tid & 31, wid = tid >> 5;
    int wm = wid >> 1, wn = wid & 1;
    float c[2][5][4];
#pragma unroll
    for (int t = 0; t < 2; t++)
#pragma unroll
        for (int s5 = 0; s5 < 5; s5++)
#pragma unroll
            for (int e = 0; e < 4; e++) c[t][s5][e] = 0.f;

    for (int kc = 0; kc < 80; kc += 16) {
#pragma unroll
        for (int s = 0; s < 8; s++) {
            int idx = tid + s * 256;
            int r = idx >> 4, k = idx & 15;
            int gk = kc + k;
            int n = n0 + r;
            float v = (n < N_NODES && gk < F) ? g_x[n * F + gk] : 0.f;
            unsigned hu = tf32_hi(v);
            float hf = __uint_as_float(hu);
            float rs = v - hf;
            unsigned lu = tf32_hi(rs);
            Ah[r][k] = hf;
            Al[r][k] = __uint_as_float(lu);
        }
#pragma unroll
        for (int s = 0; s < 5; s++) {
            int idx = tid + s * 256;
            int k = idx / 80, j = idx - k * 80;
            int gk = kc + k;
            float v = (gk < F && j < F) ? Wbase[gk * F + j] : 0.f;
            unsigned hu = tf32_hi(v);
            float hf = __uint_as_float(hu);
            float rs = v - hf;
            unsigned lu = tf32_hi(rs);
            Bh[k][j] = hf;
            Bl[k][j] = __uint_as_float(lu);
        }
        __syncthreads();
#pragma unroll
        for (int k8 = 0; k8 < 16; k8 += 8) {
            unsigned ah[2][4], al[2][4];
            int ar = lane >> 2;
            int ak = k8 + (lane & 3);
#pragma unroll
            for (int t = 0; t < 2; t++) {
                int r = wm * 32 + t * 16 + ar;
                ah[t][0] = __float_as_uint(Ah[r][ak]);
                ah[t][1] = __float_as_uint(Ah[r + 8][ak]);
                ah[t][2] = __float_as_uint(Ah[r][ak + 4]);
                ah[t][3] = __float_as_uint(Ah[r + 8][ak + 4]);
                al[t][0] = __float_as_uint(Al[r][ak]);
                al[t][1] = __float_as_uint(Al[r + 8][ak]);
                al[t][2] = __float_as_uint(Al[r][ak + 4]);
                al[t][3] = __float_as_uint(Al[r + 8][ak + 4]);
            }
#pragma unroll
            for (int s5 = 0; s5 < 5; s5++) {
                int n = wn * 40 + s5 * 8 + (lane >> 2);
                int bk = k8 + (lane & 3);
                unsigned bh0 = __float_as_uint(Bh[bk][n]);
                unsigned bh1 = __float_as_uint(Bh[bk + 4][n]);
                unsigned bl0 = __float_as_uint(Bl[bk][n]);
                unsigned bl1 = __float_as_uint(Bl[bk + 4][n]);
#pragma unroll
                for (int t = 0; t < 2; t++) {
                    MMA_TF32(c[t][s5], ah[t], bh0, bh1);
                    MMA_TF32(c[t][s5], ah[t], bl0, bl1);
                    MMA_TF32(c[t][s5], al[t], bh0, bh1);
                }
            }
        }
        __syncthreads();
    }
    float* dst = part ? g_xs : g_xd;
#pragma unroll
    for (int t = 0; t < 2; t++) {
        int r0 = n0 + wm * 32 + t * 16 + (lane >> 2);
#pragma unroll
        for (int s5 = 0; s5 < 5; s5++) {
            int gc = wn * 40 + s5 * 8 + 2 * (lane & 3);
#pragma unroll
            for (int h = 0; h < 2; h++) {
                int rr = r0 + h * 8;
                if (rr >= N_NODES) continue;
                float* row = dst + (size_t)rr * ROW + tw * F;
                if (gc < F) row[gc] = c[t][s5][h * 2 + 0];
                if (gc + 1 < F) row[gc + 1] = c[t][s5][h * 2 + 1];
            }
        }
    }
}

// ---------------- aggregation: one warp per dst node ----------------
__global__ void k_aggr(int l) {
    int warp = (blockIdx.x * blockDim.x + threadIdx.x) >> 5;
    int lane = threadIdx.x & 31;
    if (warp >= N_NODES) return;
    int n = warp;
    u64 sum2[6], sq2[6];
    float mn[12], mx[12];
#pragma unroll
    for (int q = 0; q < 6; q++) { sum2[q] = 0ULL; sq2[q] = 0ULL; }
#pragma unroll
    for (int j = 0; j < 12; j++) { mn[j] = INFINITY; mx[j] = -INFINITY; }
    int e0 = g_rowptr[n], e1 = g_rowptr[n + 1];
    const float* etbase = g_et[l];
#pragma unroll 2
    for (int e = e0; e < e1; e++) {
        int2 sa = g_col[e];
        const float4* xs4 = (const float4*)(g_xs + (size_t)sa.x * ROW);
        const float4* et4 = (const float4*)(etbase + sa.y * ROW);
#pragma unroll
        for (int q = 0; q < 3; q++) {
            float4 xv = xs4[lane * 3 + q];
            float4 ev = et4[lane * 3 + q];
            u64 v0 = fadd2(f2pk(xv.x, xv.y), f2pk(ev.x, ev.y));
            u64 v1 = fadd2(f2pk(xv.z, xv.w), f2pk(ev.z, ev.w));
            sum2[2 * q] = fadd2(sum2[2 * q], v0);
            sum2[2 * q + 1] = fadd2(sum2[2 * q + 1], v1);
            sq2[2 * q] = ffma2(v0, v0, sq2[2 * q]);
            sq2[2 * q + 1] = ffma2(v1, v1, sq2[2 * q + 1]);
            float a0, a1, a2, a3;
            f2up(v0, a0, a1);
            f2up(v1, a2, a3);
            int j = q * 4;
            mn[j] = fminf(mn[j], a0); mx[j] = fmaxf(mx[j], a0);
            mn[j + 1] = fminf(mn[j + 1], a1); mx[j + 1] = fmaxf(mx[j + 1], a1);
            mn[j + 2] = fminf(mn[j + 2], a2); mx[j + 2] = fmaxf(mx[j + 2], a2);
            mn[j + 3] = fminf(mn[j + 3], a3); mx[j + 3] = fmaxf(mx[j + 3], a3);
        }
    }
    float inv = g_invdeg[n];
    bool has = e1 > e0;
    const float4* xdrow = (const float4*)(g_xd + (size_t)n * ROW);
#pragma unroll
    for (int q = 0; q < 3; q++) {
        float4 xv = xdrow[lane * 3 + q];
        float xd4[4] = {xv.x, xv.y, xv.z, xv.w};
#pragma unroll
        for (int h4 = 0; h4 < 4; h4++) {
            int j = q * 4 + h4;
            int f = lane * 12 + j;
            if (f >= TF) continue;
            float sm, sqv;
            {
                float lo, hi;
                f2up(sum2[j >> 1], lo, hi);
                sm = (j & 1) ? hi : lo;
                f2up(sq2[j >> 1], lo, hi);
                sqv = (j & 1) ? hi : lo;
            }
            float xd = xd4[h4];
            float meanw = sm * inv;
            float var = sqv * inv - meanw * meanw;
            float sd = sqrtf(fmaxf(var, 0.f) + 1e-5f);
            float mean = has ? (meanw + xd) : 0.f;
            float mnv = has ? (mn[j] + xd) : 0.f;
            float mxv = has ? (mx[j] + xd) : 0.f;
            int tw = f / F, jj = f - tw * F;
            float* outp = g_aggr + (size_t)n * 1500 + tw * 300 + jj;
            outp[0] = mean;
            outp[75] = mnv;
            outp[150] = mxv;
            outp[225] = sd;
        }
    }
}

// ---------------- S GEMM via tf32 mma.sync + scaler combine ----------------
__global__ __launch_bounds__(256, 3) void k_gemmS(const float* __restrict__ W_post, int l) {
    __shared__ __align__(16) float Ah[128][20], Al[128][20];
    __shared__ __align__(16) float Bh[16][56], Bl[16][56];
    int t = blockIdx.y;
    int n0 = blockIdx.x * 128;
    const float* Wb = W_post + (size_t)((l * TOWERS + t) * 975 + 75) * FOUT;
    int tid = threadIdx.x, lane = tid & 31, wid = tid >> 5;
    float c[6][4];
#pragma unroll
    for (int s6 = 0; s6 < 6; s6++)
#pragma unroll
        for (int e = 0; e < 4; e++) c[s6][e] = 0.f;

    for (int kc = 0; kc < 304; kc += 16) {
#pragma unroll
        for (int s = 0; s < 8; s++) {
            int idx = tid + s * 256;
            int r = idx >> 4, k = idx & 15;
            int gk = kc + k;
            int n = n0 + r;
            float v = (n < N_NODES && gk < 300) ? g_aggr[(size_t)n * 1500 + t * 300 + gk] : 0.f;
            unsigned hu = tf32_hi(v);
            float hf = __uint_as_float(hu);
            float rs = v - hf;
            unsigned lu = tf32_hi(rs);
            Ah[r][k] = hf;
            Al[r][k] = __uint_as_float(lu);
        }
#pragma unroll
        for (int s = 0; s < 3; s++) {
            int idx = tid + s * 256;
            int k = idx / 48, j = idx - k * 48;
            int gk = kc + k;
            int g = j >> 4, f = j & 15;
            float v = (gk < 300 && f < FOUT) ? Wb[(size_t)(g * 300 + gk) * FOUT + f] : 0.f;
            unsigned hu = tf32_hi(v);
            float hf = __uint_as_float(hu);
            float rs = v - hf;
            unsigned lu = tf32_hi(rs);
            Bh[k][j] = hf;
            Bl[k][j] = __uint_as_float(lu);
        }
        __syncthreads();
#pragma unroll
        for (int k8 = 0; k8 < 16; k8 += 8) {
            unsigned ah[4], al[4];
            int r = wid * 16 + (lane >> 2);
            int ak = k8 + (lane & 3);
            ah[0] = __float_as_uint(Ah[r][ak]);
            ah[1] = __float_as_uint(Ah[r + 8][ak]);
            ah[2] = __float_as_uint(Ah[r][ak + 4]);
            ah[3] = __float_as_uint(Ah[r + 8][ak + 4]);
            al[0] = __float_as_uint(Al[r][ak]);
            al[1] = __float_as_uint(Al[r + 8][ak]);
            al[2] = __float_as_uint(Al[r][ak + 4]);
            al[3] = __float_as_uint(Al[r + 8][ak + 4]);
#pragma unroll
            for (int s6 = 0; s6 < 6; s6++) {
                int nn = s6 * 8 + (lane >> 2);
                int bk = k8 + (lane & 3);
                unsigned bh0 = __float_as_uint(Bh[bk][nn]);
                unsigned bh1 = __float_as_uint(Bh[bk + 4][nn]);
                unsigned bl0 = __float_as_uint(Bl[bk][nn]);
                unsigned bl1 = __float_as_uint(Bl[bk + 4][nn]);
                MMA_TF32(c[s6], ah, bh0, bh1);
                MMA_TF32(c[s6], ah, bl0, bl1);
                MMA_TF32(c[s6], al, bh0, bh1);
            }
        }
        __syncthreads();
    }
    int r0 = n0 + wid * 16 + (lane >> 2);
#pragma unroll
    for (int h = 0; h < 2; h++) {
        int n = r0 + h * 8;
        if (n >= N_NODES) continue;
        float amp = g_amp[n], att = g_att[n];
        float* row = g_S + n * F + t * FOUT;
#pragma unroll
        for (int p = 0; p < 2; p++) {
#pragma unroll
            for (int e = 0; e < 2; e++) {
                int f = p * 8 + 2 * (lane & 3) + e;
                if (f < FOUT) {
                    float v = c[p][h * 2 + e] + amp * c[p + 2][h * 2 + e] + att * c[p + 4][h * 2 + e];
                    row[f] = v;
                }
            }
        }
    }
}

// ---------------- post+lin GEMM via tf32 mma.sync + BN reduce --------------
// A = [128 nodes x 150pad160] = [x | S], B = [150pad x 75pad80] = [Mfold; W_lin].
// Same warp layout as k_xds: 8 warps 4m x 2n, warp tile 32 x 40.
__global__ __launch_bounds__(256, 2) void k_gemm2(const float* __restrict__ W_lin, int l) {
    __shared__ __align__(16) float Ah[128][20], Al[128][20];
    __shared__ __align__(16) float Bh[16][88], Bl[16][88];
    __shared__ float redS[80], redQ[80];
    int n0 = blockIdx.x * 128;
    int tid = threadIdx.x, lane = tid & 31, wid = tid >> 5;
    int wm = wid >> 1, wn = wid & 1;
    if (tid < 80) { redS[tid] = 0.f; redQ[tid] = 0.f; }
    float c[2][5][4];
#pragma unroll
    for (int t = 0; t < 2; t++)
#pragma unroll
        for (int s5 = 0; s5 < 5; s5++)
#pragma unroll
            for (int e = 0; e < 4; e++) c[t][s5][e] = 0.f;

    const float* Mf = g_Mfold[l];
    const float* Wl = W_lin + (size_t)l * F * F;
    for (int kc = 0; kc < 160; kc += 16) {
#pragma unroll
        for (int s = 0; s < 8; s++) {
            int idx = tid + s * 256;
            int r = idx >> 4, k = idx & 15;
            int gk = kc + k;
            int n = n0 + r;
            float v = 0.f;
            if (n < N_NODES && gk < 150)
                v = (gk < F) ? g_x[n * F + gk] : g_S[n * F + (gk - F)];
            unsigned hu = tf32_hi(v);
            float hf = __uint_as_float(hu);
            float rs = v - hf;
            unsigned lu = tf32_hi(rs);
            Ah[r][k] = hf;
            Al[r][k] = __uint_as_float(lu);
        }
#pragma unroll
        for (int s = 0; s < 5; s++) {
            int idx = tid + s * 256;
            int k = idx / 80, j = idx - k * 80;
            int gk = kc + k;
            float v = 0.f;
            if (gk < 150 && j < F)
                v = (gk < F) ? Mf[gk * F + j] : Wl[(gk - F) * F + j];
            unsigned hu = tf32_hi(v);
            float hf = __uint_as_float(hu);
            float rs = v - hf;
            unsigned lu = tf32_hi(rs);
            Bh[k][j] = hf;
            Bl[k][j] = __uint_as_float(lu);
        }
        __syncthreads();
#pragma unroll
        for (int k8 = 0; k8 < 16; k8 += 8) {
            unsigned ah[2][4], al[2][4];
            int ar = lane >> 2;
            int ak = k8 + (lane & 3);
#pragma unroll
            for (int t = 0; t < 2; t++) {
                int r = wm * 32 + t * 16 + ar;
                ah[t][0] = __float_as_uint(Ah[r][ak]);
                ah[t][1] = __float_as_uint(Ah[r + 8][ak]);
                ah[t][2] = __float_as_uint(Ah[r][ak + 4]);
                ah[t][3] = __float_as_uint(Ah[r + 8][ak + 4]);
                al[t][0] = __float_as_uint(Al[r][ak]);
                al[t][1] = __float_as_uint(Al[r + 8][ak]);
                al[t][2] = __float_as_uint(Al[r][ak + 4]);
                al[t][3] = __float_as_uint(Al[r + 8][ak + 4]);
            }
#pragma unroll
            for (int s5 = 0; s5 < 5; s5++) {
                int n = wn * 40 + s5 * 8 + (lane >> 2);
                int bk = k8 + (lane & 3);
                unsigned bh0 = __float_as_uint(Bh[bk][n]);
                unsigned bh1 = __float_as_uint(Bh[bk + 4][n]);
                unsigned bl0 = __float_as_uint(Bl[bk][n]);
                unsigned bl1 = __float_as_uint(Bl[bk + 4][n]);
#pragma unroll
                for (int t = 0; t < 2; t++) {
                    MMA_TF32(c[t][s5], ah[t], bh0, bh1);
                    MMA_TF32(c[t][s5], ah[t], bl0, bl1);
                    MMA_TF32(c[t][s5], al[t], bh0, bh1);
                }
            }
        }
        __syncthreads();
    }
    // epilogue: add bfold, store y, accumulate BN partials
    float s[10], q[10];
#pragma unroll
    for (int j = 0; j < 10; j++) { s[j] = 0.f; q[j] = 0.f; }
#pragma unroll
    for (int t = 0; t < 2; t++) {
        int r0 = n0 + wm * 32 + t * 16 + (lane >> 2);
#pragma unroll
        for (int s5 = 0; s5 < 5; s5++) {
            int gc = wn * 40 + s5 * 8 + 2 * (lane & 3);
#pragma unroll
            for (int h = 0; h < 2; h++) {
                int rr = r0 + h * 8;
                if (rr >= N_NODES) continue;
                float* row = g_y + rr * F;
#pragma unroll
                for (int e = 0; e < 2; e++) {
                    int col = gc + e;
                    if (col < F) {
                        float v = c[t][s5][h * 2 + e] + g_bfold[l][col];
                        row[col] = v;
                        s[s5 * 2 + e] += v;
                        q[s5 * 2 + e] += v * v;
                    }
                }
            }
        }
    }
#pragma unroll
    for (int j = 0; j < 10; j++) {
        int col = wn * 40 + (j >> 1) * 8 + 2 * (lane & 3) + (j & 1);
        if (col < F) {
            atomicAdd(&redS[col], s[j]);
            atomicAdd(&redQ[col], q[j]);
        }
    }
    __syncthreads();
    if (tid < F) {
        atomicAdd(&g_bnsum[l][tid], redS[tid]);
        atomicAdd(&g_bnsq[l][tid], redQ[tid]);
    }
}

// ---------------- BN finalize + apply + ReLU (+ pool on last layer) ------
__global__ void k_bnapply(const float* __restrict__ gamma, const float* __restrict__ beta,
                          const int* __restrict__ batch, int l, int do_pool) {
    __shared__ float sc[F], sh[F];
    int tid = threadIdx.x;
    if (tid < F) {
        float mu = g_bnsum[l][tid] * (1.f / (float)N_NODES);
        float var = g_bnsq[l][tid] * (1.f / (float)N_NODES) - mu * mu;
        float r = rsqrtf(var + 1e-5f);
        float s = r * gamma[l * F + tid];
        sc[tid] = s;
        sh[tid] = beta[l * F + tid] - mu * s;
    }
    __syncthreads();
    int base = blockIdx.x * 2048;
#pragma unroll
    for (int o = 0; o < 2048; o += 256) {
        int i = base + o + tid;
        if (i < N_NODES * F) {
            int n = i / F, c = i - n * F;
            float v = fmaxf(g_y[i] * sc[c] + sh[c], 0.f);
            g_x[i] = v;
            if (do_pool) atomicAdd(&g_pooled[batch[n] * F + c], v);
        }
    }
}

// ---------------- final MLP ----------------
__global__ void k_mlp(const float* __restrict__ W1, const float* __restrict__ b1,
                      const float* __restrict__ W2, const float* __restrict__ b2,
                      const float* __restrict__ W3, const float* __restrict__ b3,
                      float* __restrict__ out) {
    __shared__ float w1[75 * 50], w2[50 * 25], w3[25];
    int t = threadIdx.x;
    for (int i = t; i < 75 * 50; i += 256) w1[i] = W1[i];
    for (int i = t; i < 50 * 25; i += 256) w2[i] = W2[i];
    if (t < 25) w3[t] = W3[t];
    __syncthreads();
    if (t >= N_GRAPHS) return;
    const float* p = g_pooled + t * F;
    float h1[50];
    for (int j = 0; j < 50; j++) {
        float a = b1[j];
        for (int c = 0; c < F; c++) a += p[c] * w1[c * 50 + j];
        h1[j] = fmaxf(a, 0.f);
    }
    float h2[25];
    for (int j = 0; j < 25; j++) {
        float a = b2[j];
        for (int c = 0; c < 50; c++) a += h1[c] * w2[c * 25 + j];
        h2[j] = fmaxf(a, 0.f);
    }
    float o = b3[0];
    for (int c = 0; c < 25; c++) o += h2[c] * w3[c];
    out[t] = o;
}

// ---------------- launch ----------------
extern "C" void kernel_launch(void* const* d_in, const int* in_sizes, int n_in,
                              void* d_out, int out_size) {
    const int* x_idx = (const int*)d_in[0];
    const int* edge_index = (const int*)d_in[1];
    const int* eattr = (const int*)d_in[2];
    const int* batch = (const int*)d_in[3];
    const float* node_emb = (const float*)d_in[4];
    const float* edge_emb = (const float*)d_in[5];
    const float* W_edge = (const float*)d_in[6];
    const float* b_edge = (const float*)d_in[7];
    const float* W_pre = (const float*)d_in[8];
    const float* b_pre = (const float*)d_in[9];
    const float* W_post = (const float*)d_in[10];
    const float* b_post = (const float*)d_in[11];
    const float* W_lin = (const float*)d_in[12];
    const float* b_lin = (const float*)d_in[13];
    const float* gamma = (const float*)d_in[14];
    const float* beta = (const float*)d_in[15];
    const float* W1 = (const float*)d_in[16];
    const float* b1 = (const float*)d_in[17];
    const float* W2 = (const float*)d_in[18];
    const float* b2 = (const float*)d_in[19];
    const float* W3 = (const float*)d_in[20];
    const float* b3 = (const float*)d_in[21];
    float* out = (float*)d_out;

    dim3 gx(10, (N_NODES + 127) / 128);
    dim3 gef(N_ATTR + 1, 2);

    k_gather_count<<<GATHER_BLKS + COUNT_BLKS, 256>>>(x_idx, node_emb, edge_index); // 1
    k_scanA<<<SCAN_BLKS, 256>>>();                                                  // 2
    k_scanB<<<1, 128>>>();                                                          // 3
    k_xds<<<gx, 256>>>(W_pre, 0);                                                   // 4  <- ncu target
    k_scanC<<<SCAN_BLKS, 256>>>();                                                  // 5
    k_scatter<<<COUNT_BLKS, 256>>>(edge_index, eattr);                              // 6
    k_et_fold<<<gef, 384>>>(edge_emb, W_edge, b_edge, W_pre, b_pre,
                            W_post, b_post, W_lin, b_lin);                          // 7 (both layers)

    for (int l = 0; l < 2; l++) {
        if (l == 1) k_xds<<<gx, 256>>>(W_pre, 1);
        k_aggr<<<(N_NODES * 32 + 255) / 256, 256>>>(l);
        {
            dim3 grid((N_NODES + 127) / 128, TOWERS);
            k_gemmS<<<grid, 256>>>(W_post, l);
        }
        k_gemm2<<<(N_NODES + 127) / 128, 256>>>(W_lin, l);
        k_bnapply<<<(N_NODES * F + 2047) / 2048, 256>>>(gamma, beta, batch, l, l == 1);
    }

    k_mlp<<<1, 256>>>(W1, b1, W2, b2, W3, b3, out);
}

// round 16
// speedup vs baseline: 1.5334x; 1.0422x over previous
#include <cuda_runtime.h>
#include <cuda_bf16.h>
#include <math.h>

#define N_NODES 20000
#define N_EDGES 320000
#define N_GRAPHS 200
#define TOWERS 5
#define F 75
#define TF 375
#define EDGE_DIM 50
#define N_ATTR 100
#define FOUT 15
#define ROW 384

// ---------------- static scratch (zero-initialized; pads never written) ----
__device__ float g_x[N_NODES * F];
__device__ float g_y[N_NODES * F];
__device__ float g_xd[(size_t)N_NODES * ROW];
__device__ float g_xs[(size_t)N_NODES * ROW];
__device__ float g_aggr[(size_t)N_NODES * 1500];
__device__ float g_S[N_NODES * F];
__device__ float g_et[2][N_ATTR * ROW];
__device__ float g_Mfold[2][F * F];
__device__ float g_bfold[2][F];
__device__ int   g_deg[N_NODES];
__device__ int   g_rowptr[N_NODES + 1];
__device__ int   g_cursor[N_NODES];
__device__ int2  g_col[N_EDGES];           // (src, attr)
__device__ float g_amp[N_NODES], g_att[N_NODES], g_invdeg[N_NODES];
__device__ float g_logsum;
__device__ int   g_part[128];
__device__ int   g_partscan[128];
__device__ float g_bnsum[2][F], g_bnsq[2][F];
__device__ float g_pooled[N_GRAPHS * F];

// ---------------- f32x2 helpers ----------------
typedef unsigned long long u64;
__device__ __forceinline__ u64 f2pk(float lo, float hi) {
    u64 r;
    asm("mov.b64 %0, {%1, %2};" : "=l"(r) : "f"(lo), "f"(hi));
    return r;
}
__device__ __forceinline__ void f2up(u64 v, float& lo, float& hi) {
    asm("mov.b64 {%0, %1}, %2;" : "=f"(lo), "=f"(hi) : "l"(v));
}
__device__ __forceinline__ u64 ffma2(u64 a, u64 b, u64 c) {
    u64 d;
    asm("fma.rn.f32x2 %0, %1, %2, %3;" : "=l"(d) : "l"(a), "l"(b), "l"(c));
    return d;
}
__device__ __forceinline__ u64 fadd2(u64 a, u64 b) {
    u64 d;
    asm("add.rn.f32x2 %0, %1, %2;" : "=l"(d) : "l"(a), "l"(b));
    return d;
}

// ---------------- tf32 helpers ----------------
__device__ __forceinline__ unsigned tf32_hi(float v) {
    unsigned u;
    asm("cvt.rna.tf32.f32 %0, %1;" : "=r"(u) : "f"(v));
    return u;
}

#define MMA_TF32(c, a, b0, b1) \
    asm volatile("mma.sync.aligned.m16n8k8.row.col.f32.tf32.tf32.f32 " \
        "{%0,%1,%2,%3}, {%4,%5,%6,%7}, {%8,%9}, {%0,%1,%2,%3};" \
        : "+f"((c)[0]), "+f"((c)[1]), "+f"((c)[2]), "+f"((c)[3]) \
        : "r"((a)[0]), "r"((a)[1]), "r"((a)[2]), "r"((a)[3]), "r"(b0), "r"(b1))

// ---------------- preprocessing ----------------
#define GATHER_BLKS ((N_NODES * F + 255) / 256)
#define COUNT_BLKS ((N_EDGES + 255) / 256)
#define SCAN_BLKS ((N_NODES + 255) / 256)

__global__ void k_gather_count(const int* __restrict__ x_idx, const float* __restrict__ emb,
                               const int* __restrict__ ei) {
    int b = blockIdx.x;
    if (b < GATHER_BLKS) {
        int i = b * 256 + threadIdx.x;
        if (i < N_NODES * F) {
            int n = i / F, f = i - n * F;
            g_x[i] = emb[x_idx[n] * F + f];
        }
    } else {
        int i = (b - GATHER_BLKS) * 256 + threadIdx.x;
        if (i < N_EDGES) atomicAdd(&g_deg[ei[N_EDGES + i]], 1);
    }
}

__global__ void k_scanA() {
    __shared__ int ss[256];
    __shared__ float ls[256];
    int b = blockIdx.x, tid = threadIdx.x;
    int n = b * 256 + tid;
    int d = (n < N_NODES) ? g_deg[n] : 0;
    ss[tid] = d;
    ls[tid] = (n < N_NODES) ? logf((float)d + 1.f) : 0.f;
    __syncthreads();
    for (int o = 128; o; o >>= 1) {
        if (tid < o) { ss[tid] += ss[tid + o]; ls[tid] += ls[tid + o]; }
        __syncthreads();
    }
    if (tid == 0) { g_part[b] = ss[0]; atomicAdd(&g_logsum, ls[0]); }
}

__global__ void k_scanB() {
    __shared__ int s[128];
    int t = threadIdx.x;
    int own = (t < SCAN_BLKS) ? g_part[t] : 0;
    s[t] = own;
    __syncthreads();
    for (int o = 1; o < 128; o <<= 1) {
        int v = (t >= o) ? s[t - o] : 0;
        __syncthreads();
        s[t] += v;
        __syncthreads();
    }
    if (t < SCAN_BLKS) g_partscan[t] = s[t] - own;
}

__global__ void k_scanC() {
    __shared__ int s[256];
    int b = blockIdx.x, tid = threadIdx.x;
    int n = b * 256 + tid;
    int d = (n < N_NODES) ? g_deg[n] : 0;
    int own = d;
    s[tid] = d;
    __syncthreads();
    for (int o = 1; o < 256; o <<= 1) {
        int v = (tid >= o) ? s[tid - o] : 0;
        __syncthreads();
        s[tid] += v;
        __syncthreads();
    }
    int excl = s[tid] - own + g_partscan[b];
    if (n < N_NODES) {
        g_rowptr[n] = excl;
        g_cursor[n] = excl;
        float avg = g_logsum * (1.f / (float)N_NODES);
        float dc = fmaxf((float)d, 1.f);
        float L = logf(dc + 1.f);
        g_amp[n] = L / avg;
        g_att[n] = avg / L;
        g_invdeg[n] = 1.f / dc;
        if (n == N_NODES - 1) g_rowptr[N_NODES] = excl + d;
    }
    if (n < N_GRAPHS * F) g_pooled[n] = 0.f;
}

__global__ void k_scatter(const int* __restrict__ ei, const int* __restrict__ ea) {
    int i = blockIdx.x * 256 + threadIdx.x;
    if (i < N_EDGES) {
        int dst = ei[N_EDGES + i];
        int pos = atomicAdd(&g_cursor[dst], 1);
        g_col[pos] = make_int2(ei[i], ea[i]);
    }
    if (i < N_NODES) g_deg[i] = 0;     // reset for next invocation
    if (i == 0) g_logsum = 0.f;
}

// ---------------- both layers: et table + Mfold + bn zero ----------------
__global__ void k_et_fold(const float* __restrict__ edge_emb, const float* __restrict__ W_edge,
                          const float* __restrict__ b_edge, const float* __restrict__ W_pre,
                          const float* __restrict__ b_pre, const float* __restrict__ W_post,
                          const float* __restrict__ b_post, const float* __restrict__ W_lin,
                          const float* __restrict__ b_lin) {
    int a = blockIdx.x, t = threadIdx.x;
    int l = blockIdx.y;
    if (a < N_ATTR) {
        __shared__ float e75[F];
        if (t < F) {
            float acc = b_edge[l * F + t];
            for (int d = 0; d < EDGE_DIM; d++)
                acc += edge_emb[a * EDGE_DIM + d] * W_edge[(l * EDGE_DIM + d) * F + t];
            e75[t] = acc;
        }
        __syncthreads();
        if (t < TF) {
            int tw = t / F, f = t - tw * F;
            float acc = b_pre[(l * TOWERS + tw) * F + f];
            const float* Wp = W_pre + ((size_t)((l * TOWERS + tw) * 225 + 150)) * F + f;
            for (int c = 0; c < F; c++) acc += e75[c] * Wp[c * F];
            g_et[l][a * ROW + t] = acc;
        }
    } else {
        for (int i = t; i < F * F; i += 384) {
            int c = i / F, o = i - c * F;
            float acc = 0.f;
            for (int tf = 0; tf < F; tf++) {
                int tw = tf / FOUT, f = tf - tw * FOUT;
                acc += W_post[((size_t)((l * TOWERS + tw) * 975 + c)) * FOUT + f] *
                       W_lin[(l * F + tf) * F + o];
            }
            g_Mfold[l][i] = acc;
        }
        if (t < F) {
            float bf = b_lin[l * F + t];
            for (int tf = 0; tf < F; tf++) {
                int tw = tf / FOUT, f = tf - tw * FOUT;
                bf += b_post[(l * TOWERS + tw) * FOUT + f] * W_lin[(l * F + tf) * F + t];
            }
            g_bfold[l][t] = bf;
            g_bnsum[l][t] = 0.f;
            g_bnsq[l][t] = 0.f;
        }
    }
}

// ---------------- xd|xs GEMM via tf32 mma.sync, hi/lo split (full precision) --
__global__ __launch_bounds__(256, 2) void k_xds(const float* __restrict__ W_pre, int l) {
    __shared__ __align__(16) float Ah[128][20], Al[128][20];
    __shared__ __align__(16) float Bh[16][88], Bl[16][88];
    int piece = blockIdx.x;
    int n0 = blockIdx.y * 128;
    int part = piece / 5, tw = piece - part * 5;
    const float* Wbase = W_pre + (size_t)((l * TOWERS + tw) * 225 + part * F) * F;
    int tid = threadIdx.x, lane = tid & 31, wid = tid >> 5;
    int wm = wid >> 1, wn = wid & 1;
    float c[2][5][4];
#pragma unroll
    for (int t = 0; t < 2; t++)
#pragma unroll
        for (int s5 = 0; s5 < 5; s5++)
#pragma unroll
            for (int e = 0; e < 4; e++) c[t][s5][e] = 0.f;

    for (int kc = 0; kc < 80; kc += 16) {
#pragma unroll
        for (int s = 0; s < 8; s++) {
            int idx = tid + s * 256;
            int r = idx >> 4, k = idx & 15;
            int gk = kc + k;
            int n = n0 + r;
            float v = (n < N_NODES && gk < F) ? g_x[n * F + gk] : 0.f;
            unsigned hu = tf32_hi(v);
            float hf = __uint_as_float(hu);
            float rs = v - hf;
            unsigned lu = tf32_hi(rs);
            Ah[r][k] = hf;
            Al[r][k] = __uint_as_float(lu);
        }
#pragma unroll
        for (int s = 0; s < 5; s++) {
            int idx = tid + s * 256;
            int k = idx / 80, j = idx - k * 80;
            int gk = kc + k;
            float v = (gk < F && j < F) ? Wbase[gk * F + j] : 0.f;
            unsigned hu = tf32_hi(v);
            float hf = __uint_as_float(hu);
            float rs = v - hf;
            unsigned lu = tf32_hi(rs);
            Bh[k][j] = hf;
            Bl[k][j] = __uint_as_float(lu);
        }
        __syncthreads();
#pragma unroll
        for (int k8 = 0; k8 < 16; k8 += 8) {
            unsigned ah[2][4], al[2][4];
            int ar = lane >> 2;
            int ak = k8 + (lane & 3);
#pragma unroll
            for (int t = 0; t < 2; t++) {
                int r = wm * 32 + t * 16 + ar;
                ah[t][0] = __float_as_uint(Ah[r][ak]);
                ah[t][1] = __float_as_uint(Ah[r + 8][ak]);
                ah[t][2] = __float_as_uint(Ah[r][ak + 4]);
                ah[t][3] = __float_as_uint(Ah[r + 8][ak + 4]);
                al[t][0] = __float_as_uint(Al[r][ak]);
                al[t][1] = __float_as_uint(Al[r + 8][ak]);
                al[t][2] = __float_as_uint(Al[r][ak + 4]);
                al[t][3] = __float_as_uint(Al[r + 8][ak + 4]);
            }
#pragma unroll
            for (int s5 = 0; s5 < 5; s5++) {
                int n = wn * 40 + s5 * 8 + (lane >> 2);
                int bk = k8 + (lane & 3);
                unsigned bh0 = __float_as_uint(Bh[bk][n]);
                unsigned bh1 = __float_as_uint(Bh[bk + 4][n]);
                unsigned bl0 = __float_as_uint(Bl[bk][n]);
                unsigned bl1 = __float_as_uint(Bl[bk + 4][n]);
#pragma unroll
                for (int t = 0; t < 2; t++) {
                    MMA_TF32(c[t][s5], ah[t], bh0, bh1);
                    MMA_TF32(c[t][s5], ah[t], bl0, bl1);
                    MMA_TF32(c[t][s5], al[t], bh0, bh1);
                }
            }
        }
        __syncthreads();
    }
    float* dst = part ? g_xs : g_xd;
#pragma unroll
    for (int t = 0; t < 2; t++) {
        int r0 = n0 + wm * 32 + t * 16 + (lane >> 2);
#pragma unroll
        for (int s5 = 0; s5 < 5; s5++) {
            int gc = wn * 40 + s5 * 8 + 2 * (lane & 3);
#pragma unroll
            for (int h = 0; h < 2; h++) {
                int rr = r0 + h * 8;
                if (rr >= N_NODES) continue;
                float* row = dst + (size_t)rr * ROW + tw * F;
                if (gc < F) row[gc] = c[t][s5][h * 2 + 0];
                if (gc + 1 < F) row[gc + 1] = c[t][s5][h * 2 + 1];
            }
        }
    }
}

// ---------------- aggregation: one warp per dst node, 2-edge pipelined -----
__device__ __forceinline__ void aggr_acc(const float4* xv, const float4* ev,
                                         u64* sum2, u64* sq2, float* mn, float* mx) {
#pragma unroll
    for (int q = 0; q < 3; q++) {
        u64 v0 = fadd2(f2pk(xv[q].x, xv[q].y), f2pk(ev[q].x, ev[q].y));
        u64 v1 = fadd2(f2pk(xv[q].z, xv[q].w), f2pk(ev[q].z, ev[q].w));
        sum2[2 * q] = fadd2(sum2[2 * q], v0);
        sum2[2 * q + 1] = fadd2(sum2[2 * q + 1], v1);
        sq2[2 * q] = ffma2(v0, v0, sq2[2 * q]);
        sq2[2 * q + 1] = ffma2(v1, v1, sq2[2 * q + 1]);
        float a0, a1, a2, a3;
        f2up(v0, a0, a1);
        f2up(v1, a2, a3);
        int j = q * 4;
        mn[j] = fminf(mn[j], a0); mx[j] = fmaxf(mx[j], a0);
        mn[j + 1] = fminf(mn[j + 1], a1); mx[j + 1] = fmaxf(mx[j + 1], a1);
        mn[j + 2] = fminf(mn[j + 2], a2); mx[j + 2] = fmaxf(mx[j + 2], a2);
        mn[j + 3] = fminf(mn[j + 3], a3); mx[j + 3] = fmaxf(mx[j + 3], a3);
    }
}

__global__ void k_aggr(int l) {
    int warp = (blockIdx.x * blockDim.x + threadIdx.x) >> 5;
    int lane = threadIdx.x & 31;
    if (warp >= N_NODES) return;
    int n = warp;
    u64 sum2[6], sq2[6];
    float mn[12], mx[12];
#pragma unroll
    for (int q = 0; q < 6; q++) { sum2[q] = 0ULL; sq2[q] = 0ULL; }
#pragma unroll
    for (int j = 0; j < 12; j++) { mn[j] = INFINITY; mx[j] = -INFINITY; }
    int e0 = g_rowptr[n], e1 = g_rowptr[n + 1];
    const float* etbase = g_et[l];
    int e = e0;
    for (; e + 2 <= e1; e += 2) {
        int2 a0 = g_col[e];
        int2 a1 = g_col[e + 1];
        const float4* x0 = (const float4*)(g_xs + (size_t)a0.x * ROW) + lane * 3;
        const float4* t0 = (const float4*)(etbase + a0.y * ROW) + lane * 3;
        const float4* x1 = (const float4*)(g_xs + (size_t)a1.x * ROW) + lane * 3;
        const float4* t1 = (const float4*)(etbase + a1.y * ROW) + lane * 3;
        float4 vx0[3], vt0[3], vx1[3], vt1[3];
#pragma unroll
        for (int q = 0; q < 3; q++) { vx0[q] = x0[q]; vt0[q] = t0[q]; }
#pragma unroll
        for (int q = 0; q < 3; q++) { vx1[q] = x1[q]; vt1[q] = t1[q]; }
        aggr_acc(vx0, vt0, sum2, sq2, mn, mx);
        aggr_acc(vx1, vt1, sum2, sq2, mn, mx);
    }
    if (e < e1) {
        int2 a0 = g_col[e];
        const float4* x0 = (const float4*)(g_xs + (size_t)a0.x * ROW) + lane * 3;
        const float4* t0 = (const float4*)(etbase + a0.y * ROW) + lane * 3;
        float4 vx0[3], vt0[3];
#pragma unroll
        for (int q = 0; q < 3; q++) { vx0[q] = x0[q]; vt0[q] = t0[q]; }
        aggr_acc(vx0, vt0, sum2, sq2, mn, mx);
    }
    float inv = g_invdeg[n];
    bool has = e1 > e0;
    const float4* xdrow = (const float4*)(g_xd + (size_t)n * ROW);
#pragma unroll
    for (int q = 0; q < 3; q++) {
        float4 xv = xdrow[lane * 3 + q];
        float xd4[4] = {xv.x, xv.y, xv.z, xv.w};
#pragma unroll
        for (int h4 = 0; h4 < 4; h4++) {
            int j = q * 4 + h4;
            int f = lane * 12 + j;
            if (f >= TF) continue;
            float sm, sqv;
            {
                float lo, hi;
                f2up(sum2[j >> 1], lo, hi);
                sm = (j & 1) ? hi : lo;
                f2up(sq2[j >> 1], lo, hi);
                sqv = (j & 1) ? hi : lo;
            }
            float xd = xd4[h4];
            float meanw = sm * inv;
            float var = sqv * inv - meanw * meanw;
            float sd = sqrtf(fmaxf(var, 0.f) + 1e-5f);
            float mean = has ? (meanw + xd) : 0.f;
            float mnv = has ? (mn[j] + xd) : 0.f;
            float mxv = has ? (mx[j] + xd) : 0.f;
            int tw = f / F, jj = f - tw * F;
            float* outp = g_aggr + (size_t)n * 1500 + tw * 300 + jj;
            outp[0] = mean;
            outp[75] = mnv;
            outp[150] = mxv;
            outp[225] = sd;
        }
    }
}

// ---------------- S GEMM via tf32 mma.sync (full hi/lo) + scaler combine ----
__global__ __launch_bounds__(256, 3) void k_gemmS(const float* __restrict__ W_post, int l) {
    __shared__ __align__(16) float Ah[128][20], Al[128][20];
    __shared__ __align__(16) float Bh[16][56], Bl[16][56];
    int t = blockIdx.y;
    int n0 = blockIdx.x * 128;
    const float* Wb = W_post + (size_t)((l * TOWERS + t) * 975 + 75) * FOUT;
    int tid = threadIdx.x, lane = tid & 31, wid = tid >> 5;
    float c[6][4];
#pragma unroll
    for (int s6 = 0; s6 < 6; s6++)
#pragma unroll
        for (int e = 0; e < 4; e++) c[s6][e] = 0.f;

    for (int kc = 0; kc < 304; kc += 16) {
#pragma unroll
        for (int s = 0; s < 8; s++) {
            int idx = tid + s * 256;
            int r = idx >> 4, k = idx & 15;
            int gk = kc + k;
            int n = n0 + r;
            float v = (n < N_NODES && gk < 300) ? g_aggr[(size_t)n * 1500 + t * 300 + gk] : 0.f;
            unsigned hu = tf32_hi(v);
            float hf = __uint_as_float(hu);
            float rs = v - hf;
            Ah[r][k] = hf;
            Al[r][k] = __uint_as_float(tf32_hi(rs));
        }
#pragma unroll
        for (int s = 0; s < 3; s++) {
            int idx = tid + s * 256;
            int k = idx / 48, j = idx - k * 48;
            int gk = kc + k;
            int g = j >> 4, f = j & 15;
            float v = (gk < 300 && f < FOUT) ? Wb[(size_t)(g * 300 + gk) * FOUT + f] : 0.f;
            unsigned hu = tf32_hi(v);
            float hf = __uint_as_float(hu);
            float rs = v - hf;
            Bh[k][j] = hf;
            Bl[k][j] = __uint_as_float(tf32_hi(rs));
        }
        __syncthreads();
#pragma unroll
        for (int k8 = 0; k8 < 16; k8 += 8) {
            unsigned ah[4], al[4];
            int r = wid * 16 + (lane >> 2);
            int ak = k8 + (lane & 3);
            ah[0] = __float_as_uint(Ah[r][ak]);
            ah[1] = __float_as_uint(Ah[r + 8][ak]);
            ah[2] = __float_as_uint(Ah[r][ak + 4]);
            ah[3] = __float_as_uint(Ah[r + 8][ak + 4]);
            al[0] = __float_as_uint(Al[r][ak]);
            al[1] = __float_as_uint(Al[r + 8][ak]);
            al[2] = __float_as_uint(Al[r][ak + 4]);
            al[3] = __float_as_uint(Al[r + 8][ak + 4]);
#pragma unroll
            for (int s6 = 0; s6 < 6; s6++) {
                int nn = s6 * 8 + (lane >> 2);
                int bk = k8 + (lane & 3);
                unsigned bh0 = __float_as_uint(Bh[bk][nn]);
                unsigned bh1 = __float_as_uint(Bh[bk + 4][nn]);
                unsigned bl0 = __float_as_uint(Bl[bk][nn]);
                unsigned bl1 = __float_as_uint(Bl[bk + 4][nn]);
                MMA_TF32(c[s6], ah, bh0, bh1);
                MMA_TF32(c[s6], ah, bl0, bl1);
                MMA_TF32(c[s6], al, bh0, bh1);
            }
        }
        __syncthreads();
    }
    int r0 = n0 + wid * 16 + (lane >> 2);
#pragma unroll
    for (int h = 0; h < 2; h++) {
        int n = r0 + h * 8;
        if (n >= N_NODES) continue;
        float amp = g_amp[n], att = g_att[n];
        float* row = g_S + n * F + t * FOUT;
#pragma unroll
        for (int p = 0; p < 2; p++) {
#pragma unroll
            for (int e = 0; e < 2; e++) {
                int f = p * 8 + 2 * (lane & 3) + e;
                if (f < FOUT) {
                    float v = c[p][h * 2 + e] + amp * c[p + 2][h * 2 + e] + att * c[p + 4][h * 2 + e];
                    row[f] = v;
                }
            }
        }
    }
}

// ---------------- post+lin GEMM via tf32 mma.sync (full hi/lo) + BN reduce ---
__global__ __launch_bounds__(256, 2) void k_gemm2(const float* __restrict__ W_lin, int l) {
    __shared__ __align__(16) float Ah[128][20], Al[128][20];
    __shared__ __align__(16) float Bh[16][88], Bl[16][88];
    __shared__ float redS[80], redQ[80];
    int n0 = blockIdx.x * 128;
    int tid = threadIdx.x, lane = tid & 31, wid = tid >> 5;
    int wm = wid >> 1, wn = wid & 1;
    if (tid < 80) { redS[tid] = 0.f; redQ[tid] = 0.f; }
    float c[2][5][4];
#pragma unroll
    for (int t = 0; t < 2; t++)
#pragma unroll
        for (int s5 = 0; s5 < 5; s5++)
#pragma unroll
            for (int e = 0; e < 4; e++) c[t][s5][e] = 0.f;

    const float* Mf = g_Mfold[l];
    const float* Wl = W_lin + (size_t)l * F * F;
    for (int kc = 0; kc < 160; kc += 16) {
#pragma unroll
        for (int s = 0; s < 8; s++) {
            int idx = tid + s * 256;
            int r = idx >> 4, k = idx & 15;
            int gk = kc + k;
            int n = n0 + r;
            float v = 0.f;
            if (n < N_NODES && gk < 150)
                v = (gk < F) ? g_x[n * F + gk] : g_S[n * F + (gk - F)];
            unsigned hu = tf32_hi(v);
            float hf = __uint_as_float(hu);
            float rs = v - hf;
            Ah[r][k] = hf;
            Al[r][k] = __uint_as_float(tf32_hi(rs));
        }
#pragma unroll
        for (int s = 0; s < 5; s++) {
            int idx = tid + s * 256;
            int k = idx / 80, j = idx - k * 80;
            int gk = kc + k;
            float v = 0.f;
            if (gk < 150 && j < F)
                v = (gk < F) ? Mf[gk * F + j] : Wl[(gk - F) * F + j];
            unsigned hu = tf32_hi(v);
            float hf = __uint_as_float(hu);
            float rs = v - hf;
            Bh[k][j] = hf;
            Bl[k][j] = __uint_as_float(tf32_hi(rs));
        }
        __syncthreads();
#pragma unroll
        for (int k8 = 0; k8 < 16; k8 += 8) {
            unsigned ah[2][4], al[2][4];
            int ar = lane >> 2;
            int ak = k8 + (lane & 3);
#pragma unroll
            for (int t = 0; t < 2; t++) {
                int r = wm * 32 + t * 16 + ar;
                ah[t][0] = __float_as_uint(Ah[r][ak]);
                ah[t][1] = __float_as_uint(Ah[r + 8][ak]);
                ah[t][2] = __float_as_uint(Ah[r][ak + 4]);
                ah[t][3] = __float_as_uint(Ah[r + 8][ak + 4]);
                al[t][0] = __float_as_uint(Al[r][ak]);
                al[t][1] = __float_as_uint(Al[r + 8][ak]);
                al[t][2] = __float_as_uint(Al[r][ak + 4]);
                al[t][3] = __float_as_uint(Al[r + 8][ak + 4]);
            }
#pragma unroll
            for (int s5 = 0; s5 < 5; s5++) {
                int n = wn * 40 + s5 * 8 + (lane >> 2);
                int bk = k8 + (lane & 3);
                unsigned bh0 = __float_as_uint(Bh[bk][n]);
                unsigned bh1 = __float_as_uint(Bh[bk + 4][n]);
                unsigned bl0 = __float_as_uint(Bl[bk][n]);
                unsigned bl1 = __float_as_uint(Bl[bk + 4][n]);
#pragma unroll
                for (int t = 0; t < 2; t++) {
                    MMA_TF32(c[t][s5], ah[t], bh0, bh1);
                    MMA_TF32(c[t][s5], ah[t], bl0, bl1);
                    MMA_TF32(c[t][s5], al[t], bh0, bh1);
                }
            }
        }
        __syncthreads();
    }
    // epilogue: add bfold, store y, accumulate BN partials
    float s[10], q[10];
#pragma unroll
    for (int j = 0; j < 10; j++) { s[j] = 0.f; q[j] = 0.f; }
#pragma unroll
    for (int t = 0; t < 2; t++) {
        int r0 = n0 + wm * 32 + t * 16 + (lane >> 2);
#pragma unroll
        for (int s5 = 0; s5 < 5; s5++) {
            int gc = wn * 40 + s5 * 8 + 2 * (lane & 3);
#pragma unroll
            for (int h = 0; h < 2; h++) {
                int rr = r0 + h * 8;
                if (rr >= N_NODES) continue;
                float* row = g_y + rr * F;
#pragma unroll
                for (int e = 0; e < 2; e++) {
                    int col = gc + e;
                    if (col < F) {
                        float v = c[t][s5][h * 2 + e] + g_bfold[l][col];
                        row[col] = v;
                        s[s5 * 2 + e] += v;
                        q[s5 * 2 + e] += v * v;
                    }
                }
            }
        }
    }
#pragma unroll
    for (int j = 0; j < 10; j++) {
        int col = wn * 40 + (j >> 1) * 8 + 2 * (lane & 3) + (j & 1);
        if (col < F) {
            atomicAdd(&redS[col], s[j]);
            atomicAdd(&redQ[col], q[j]);
        }
    }
    __syncthreads();
    if (tid < F) {
        atomicAdd(&g_bnsum[l][tid], redS[tid]);
        atomicAdd(&g_bnsq[l][tid], redQ[tid]);
    }
}

// ---------------- BN finalize + apply + ReLU (+ pool on last layer) ------
__global__ void k_bnapply(const float* __restrict__ gamma, const float* __restrict__ beta,
                          const int* __restrict__ batch, int l, int do_pool) {
    __shared__ float sc[F], sh[F];
    int tid = threadIdx.x;
    if (tid < F) {
        float mu = g_bnsum[l][tid] * (1.f / (float)N_NODES);
        float var = g_bnsq[l][tid] * (1.f / (float)N_NODES) - mu * mu;
        float r = rsqrtf(var + 1e-5f);
        float s = r * gamma[l * F + tid];
        sc[tid] = s;
        sh[tid] = beta[l * F + tid] - mu * s;
    }
    __syncthreads();
    int base = blockIdx.x * 2048;
#pragma unroll
    for (int o = 0; o < 2048; o += 256) {
        int i = base + o + tid;
        if (i < N_NODES * F) {
            int n = i / F, c = i - n * F;
            float v = fmaxf(g_y[i] * sc[c] + sh[c], 0.f);
            g_x[i] = v;
            if (do_pool) atomicAdd(&g_pooled[batch[n] * F + c], v);
        }
    }
}

// ---------------- final MLP ----------------
__global__ void k_mlp(const float* __restrict__ W1, const float* __restrict__ b1,
                      const float* __restrict__ W2, const float* __restrict__ b2,
                      const float* __restrict__ W3, const float* __restrict__ b3,
                      float* __restrict__ out) {
    __shared__ float w1[75 * 50], w2[50 * 25], w3[25];
    int t = threadIdx.x;
    for (int i = t; i < 75 * 50; i += 256) w1[i] = W1[i];
    for (int i = t; i < 50 * 25; i += 256) w2[i] = W2[i];
    if (t < 25) w3[t] = W3[t];
    __syncthreads();
    if (t >= N_GRAPHS) return;
    const float* p = g_pooled + t * F;
    float h1[50];
    for (int j = 0; j < 50; j++) {
        float a = b1[j];
        for (int c = 0; c < F; c++) a += p[c] * w1[c * 50 + j];
        h1[j] = fmaxf(a, 0.f);
    }
    float h2[25];
    for (int j = 0; j < 25; j++) {
        float a = b2[j];
        for (int c = 0; c < 50; c++) a += h1[c] * w2[c * 25 + j];
        h2[j] = fmaxf(a, 0.f);
    }
    float o = b3[0];
    for (int c = 0; c < 25; c++) o += h2[c] * w3[c];
    out[t] = o;
}

// ---------------- launch ----------------
extern "C" void kernel_launch(void* const* d_in, const int* in_sizes, int n_in,
                              void* d_out, int out_size) {
    const int* x_idx = (const int*)d_in[0];
    const int* edge_index = (const int*)d_in[1];
    const int* eattr = (const int*)d_in[2];
    const int* batch = (const int*)d_in[3];
    const float* node_emb = (const float*)d_in[4];
    const float* edge_emb = (const float*)d_in[5];
    const float* W_edge = (const float*)d_in[6];
    const float* b_edge = (const float*)d_in[7];
    const float* W_pre = (const float*)d_in[8];
    const float* b_pre = (const float*)d_in[9];
    const float* W_post = (const float*)d_in[10];
    const float* b_post = (const float*)d_in[11];
    const float* W_lin = (const float*)d_in[12];
    const float* b_lin = (const float*)d_in[13];
    const float* gamma = (const float*)d_in[14];
    const float* beta = (const float*)d_in[15];
    const float* W1 = (const float*)d_in[16];
    const float* b1 = (const float*)d_in[17];
    const float* W2 = (const float*)d_in[18];
    const float* b2 = (const float*)d_in[19];
    const float* W3 = (const float*)d_in[20];
    const float* b3 = (const float*)d_in[21];
    float* out = (float*)d_out;

    dim3 gx(10, (N_NODES + 127) / 128);
    dim3 gef(N_ATTR + 1, 2);

    k_gather_count<<<GATHER_BLKS + COUNT_BLKS, 256>>>(x_idx, node_emb, edge_index); // 1
    k_scanA<<<SCAN_BLKS, 256>>>();                                                  // 2
    k_scanB<<<1, 128>>>();                                                          // 3
    k_xds<<<gx, 256>>>(W_pre, 0);                                                   // 4  <- ncu target
    k_scanC<<<SCAN_BLKS, 256>>>();                                                  // 5
    k_scatter<<<COUNT_BLKS, 256>>>(edge_index, eattr);                              // 6
    k_et_fold<<<gef, 384>>>(edge_emb, W_edge, b_edge, W_pre, b_pre,
                            W_post, b_post, W_lin, b_lin);                          // 7 (both layers)

    for (int l = 0; l < 2; l++) {
        if (l == 1) k_xds<<<gx, 256>>>(W_pre, 1);
        k_aggr<<<(N_NODES * 32 + 255) / 256, 256>>>(l);
        {
            dim3 grid((N_NODES + 127) / 128, TOWERS);
            k_gemmS<<<grid, 256>>>(W_post, l);
        }
        k_gemm2<<<(N_NODES + 127) / 128, 256>>>(W_lin, l);
        k_bnapply<<<(N_NODES * F + 2047) / 2048, 256>>>(gamma, beta, batch, l, l == 1);
    }

    k_mlp<<<1, 256>>>(W1, b1, W2, b2, W3, b3, out);
}